// round 3
// baseline (speedup 1.0000x reference)
#include <cuda_runtime.h>
#include <cuda_bf16.h>
#include <stdint.h>

#define Bd  8
#define Ld  2016
#define Hd  4
#define DKd 32
#define Dd  256
#define FCd 64
#define NLd 3
#define BLd (Bd*Ld)          // 16128 tokens

__device__ __constant__ float kSCALE = 0.0625f;   // 1/sqrt(256)
#define EPSLN 1e-5f

// ---------------------------------------------------------------------------
// Device scratch (no allocation allowed). hi/lo split bf16 pairs everywhere.
// ---------------------------------------------------------------------------
__device__ __align__(128) float          g_h    [BLd*Dd];
__device__ __align__(128) __nv_bfloat16  g_hhi  [BLd*Dd];
__device__ __align__(128) __nv_bfloat16  g_hlo  [BLd*Dd];
__device__ __align__(128) __nv_bfloat16  g_qhi  [BLd*Hd*DKd];
__device__ __align__(128) __nv_bfloat16  g_qlo  [BLd*Hd*DKd];
__device__ __align__(128) __nv_bfloat16  g_khi  [BLd*Hd*DKd];
__device__ __align__(128) __nv_bfloat16  g_klo  [BLd*Hd*DKd];
__device__ __align__(128) __nv_bfloat16  g_vhi  [BLd*Hd*DKd];
__device__ __align__(128) __nv_bfloat16  g_vlo  [BLd*Hd*DKd];
__device__ __align__(128) __nv_bfloat16  g_ohi  [BLd*Hd*DKd];
__device__ __align__(128) __nv_bfloat16  g_olo  [BLd*Hd*DKd];
__device__ __align__(128) float          g_tmp  [BLd*Dd];
__device__ __align__(128) __nv_bfloat16  g_fhi  [BLd*FCd];
__device__ __align__(128) __nv_bfloat16  g_flo  [BLd*FCd];
// bf16 split weights
__device__ __align__(128) __nv_bfloat16  g_qwh [NLd*Dd*128];
__device__ __align__(128) __nv_bfloat16  g_qwl [NLd*Dd*128];
__device__ __align__(128) __nv_bfloat16  g_kwh [NLd*Dd*128];
__device__ __align__(128) __nv_bfloat16  g_kwl [NLd*Dd*128];
__device__ __align__(128) __nv_bfloat16  g_vwh [NLd*Dd*128];
__device__ __align__(128) __nv_bfloat16  g_vwl [NLd*Dd*128];
__device__ __align__(128) __nv_bfloat16  g_owh [NLd*128*Dd];
__device__ __align__(128) __nv_bfloat16  g_owl [NLd*128*Dd];
__device__ __align__(128) __nv_bfloat16  g_f1wh[NLd*Dd*FCd];
__device__ __align__(128) __nv_bfloat16  g_f1wl[NLd*Dd*FCd];
__device__ __align__(128) __nv_bfloat16  g_f2wh[NLd*FCd*Dd];
__device__ __align__(128) __nv_bfloat16  g_f2wl[NLd*FCd*Dd];
__device__ __align__(128) __nv_bfloat16  g_o1wh[Dd*Dd];
__device__ __align__(128) __nv_bfloat16  g_o1wl[Dd*Dd];

// ---------------------------------------------------------------------------
// helpers
// ---------------------------------------------------------------------------
__device__ __forceinline__ void mma16816(float* d, const uint32_t* a,
                                         uint32_t b0, uint32_t b1) {
    asm volatile(
        "mma.sync.aligned.m16n8k16.row.col.f32.bf16.bf16.f32 "
        "{%0,%1,%2,%3}, {%4,%5,%6,%7}, {%8,%9}, {%0,%1,%2,%3};"
        : "+f"(d[0]), "+f"(d[1]), "+f"(d[2]), "+f"(d[3])
        : "r"(a[0]), "r"(a[1]), "r"(a[2]), "r"(a[3]), "r"(b0), "r"(b1));
}

__device__ __forceinline__ uint32_t pk2(float x, float y) {
    __nv_bfloat162 t = __floats2bfloat162_rn(x, y);
    return *reinterpret_cast<uint32_t*>(&t);
}

__device__ __forceinline__ void fsplit(float v, __nv_bfloat16& hi, __nv_bfloat16& lo) {
    hi = __float2bfloat16(v);
    lo = __float2bfloat16(v - __bfloat162float(hi));
}

__device__ __forceinline__ void pksplit(float x, float y, uint32_t& hi, uint32_t& lo) {
    __nv_bfloat16 xh = __float2bfloat16(x), yh = __float2bfloat16(y);
    __nv_bfloat162 th; th.x = xh; th.y = yh;
    hi = *reinterpret_cast<uint32_t*>(&th);
    lo = pk2(x - __bfloat162float(xh), y - __bfloat162float(yh));
}

// ---------------------------------------------------------------------------
// Weight conversion fp32 -> bf16 hi/lo
// ---------------------------------------------------------------------------
__global__ void convert_w(const float* __restrict__ qw, const float* __restrict__ kw,
                          const float* __restrict__ vw, const float* __restrict__ ow,
                          const float* __restrict__ f1w, const float* __restrict__ f2w,
                          const float* __restrict__ o1w) {
    int i = blockIdx.x * 256 + threadIdx.x;
    const int n1 = NLd*Dd*128;   // 98304 (also ow)
    const int n3 = NLd*Dd*FCd;   // 49152 (also f2w)
    const int n5 = Dd*Dd;        // 65536
    if (i < n1) {
        fsplit(qw[i], g_qwh[i], g_qwl[i]);
        fsplit(kw[i], g_kwh[i], g_kwl[i]);
        fsplit(vw[i], g_vwh[i], g_vwl[i]);
        fsplit(ow[i], g_owh[i], g_owl[i]);
    }
    if (i < n3) {
        fsplit(f1w[i], g_f1wh[i], g_f1wl[i]);
        fsplit(f2w[i], g_f2wh[i], g_f2wl[i]);
    }
    if (i < n5) fsplit(o1w[i], g_o1wh[i], g_o1wl[i]);
}

// ---------------------------------------------------------------------------
// Embed: h = x @ in_w + in_b (fp32 + split)
// ---------------------------------------------------------------------------
__global__ void embed_kernel(const float* __restrict__ x,
                             const float* __restrict__ in_w,
                             const float* __restrict__ in_b) {
    int t = blockIdx.x, d = threadIdx.x;
    float x0 = x[t*2], x1 = x[t*2+1];
    float v = fmaf(x0, in_w[d], fmaf(x1, in_w[Dd + d], in_b[d]));
    size_t ix = (size_t)t*Dd + d;
    g_h[ix] = v;
    fsplit(v, g_hhi[ix], g_hlo[ix]);
}

// ---------------------------------------------------------------------------
// Split-precision GEMM: out(M,N) = (Ahi+Alo)(M,K) @ (Whi+Wlo)(K,N) + bias
// 3-term: Ah*Wh + Al*Wh + Ah*Wl  (fp32 accum). CTA tile 128x64, 256 threads.
// ---------------------------------------------------------------------------
template<int K, bool OUT_B16, bool OUT_F32, bool RELU>
__global__ __launch_bounds__(256) void gemm_bias(
        const __nv_bfloat16* __restrict__ Ahi,
        const __nv_bfloat16* __restrict__ Alo,
        const __nv_bfloat16* __restrict__ Whi,
        const __nv_bfloat16* __restrict__ Wlo,
        const float* __restrict__ bias,
        float* __restrict__ outF,
        __nv_bfloat16* __restrict__ outBh,
        __nv_bfloat16* __restrict__ outBl,
        int N) {
    extern __shared__ __nv_bfloat16 sm[];
    constexpr int SA = K + 8;
    constexpr int SW = K + 2;
    __nv_bfloat16* sAh = sm;
    __nv_bfloat16* sAl = sm + 128 * SA;
    __nv_bfloat16* sWh = sm + 256 * SA;
    __nv_bfloat16* sWl = sWh + 64 * SW;

    const int tid = threadIdx.x, lane = tid & 31, warp = tid >> 5;
    const int row0 = blockIdx.x * 128, col0 = blockIdx.y * 64;

    constexpr int AV = K / 8;
    #pragma unroll 4
    for (int i = tid; i < 128 * AV; i += 256) {
        int r = i / AV, c = (i % AV) * 8;
        size_t g = (size_t)(row0 + r)*K + c;
        *reinterpret_cast<uint4*>(&sAh[r*SA + c]) = *reinterpret_cast<const uint4*>(&Ahi[g]);
        *reinterpret_cast<uint4*>(&sAl[r*SA + c]) = *reinterpret_cast<const uint4*>(&Alo[g]);
    }
    for (int i = tid; i < 64 * K; i += 256) {
        int k = i >> 6, n = i & 63;
        size_t g = (size_t)k*N + col0 + n;
        sWh[n*SW + k] = Whi[g];
        sWl[n*SW + k] = Wlo[g];
    }
    __syncthreads();

    float acc[8][4];
    #pragma unroll
    for (int i = 0; i < 8; i++)
        #pragma unroll
        for (int j = 0; j < 4; j++) acc[i][j] = 0.f;

    const int ar = warp*16 + (lane >> 2);
    const int ac = (lane & 3) * 2;
    #pragma unroll
    for (int kk = 0; kk < K/16; kk++) {
        uint32_t ah[4], al[4];
        {
            const __nv_bfloat16* pa = &sAh[ar*SA + kk*16 + ac];
            ah[0] = *(const uint32_t*)pa;
            ah[1] = *(const uint32_t*)(pa + 8*SA);
            ah[2] = *(const uint32_t*)(pa + 8);
            ah[3] = *(const uint32_t*)(pa + 8*SA + 8);
            const __nv_bfloat16* pl = &sAl[ar*SA + kk*16 + ac];
            al[0] = *(const uint32_t*)pl;
            al[1] = *(const uint32_t*)(pl + 8*SA);
            al[2] = *(const uint32_t*)(pl + 8);
            al[3] = *(const uint32_t*)(pl + 8*SA + 8);
        }
        #pragma unroll
        for (int nt = 0; nt < 8; nt++) {
            int nrow = nt*8 + (lane>>2);
            const __nv_bfloat16* pbh = &sWh[nrow*SW + kk*16 + ac];
            uint32_t bh0 = *(const uint32_t*)pbh;
            uint32_t bh1 = *(const uint32_t*)(pbh + 8);
            const __nv_bfloat16* pbl = &sWl[nrow*SW + kk*16 + ac];
            uint32_t bl0 = *(const uint32_t*)pbl;
            uint32_t bl1 = *(const uint32_t*)(pbl + 8);
            mma16816(acc[nt], ah, bh0, bh1);
            mma16816(acc[nt], al, bh0, bh1);
            mma16816(acc[nt], ah, bl0, bl1);
        }
    }

    const int orow = row0 + warp*16 + (lane >> 2);
    #pragma unroll
    for (int nt = 0; nt < 8; nt++) {
        int c = col0 + nt*8 + (lane & 3)*2;
        float b0v = bias[c], b1v = bias[c+1];
        #pragma unroll
        for (int half = 0; half < 2; half++) {
            int r = orow + half*8;
            float v0 = acc[nt][half*2+0] + b0v;
            float v1 = acc[nt][half*2+1] + b1v;
            if (RELU) { v0 = fmaxf(v0, 0.f); v1 = fmaxf(v1, 0.f); }
            size_t o = (size_t)r*N + c;
            if (OUT_F32) { outF[o] = v0; outF[o+1] = v1; }
            if (OUT_B16) {
                __nv_bfloat16 h0, l0, h1, l1;
                fsplit(v0, h0, l0);
                fsplit(v1, h1, l1);
                outBh[o] = h0; outBh[o+1] = h1;
                outBl[o] = l0; outBl[o+1] = l1;
            }
        }
    }
}

// ---------------------------------------------------------------------------
// Attention: per (b,h,16-query tile): S=QK^T*scale in smem, exact fp32
// softmax, write P to gmem, O = P@V. All in split precision (3-term MMA).
// ---------------------------------------------------------------------------
#define SST 2056   // score row stride

__global__ __launch_bounds__(256) void attn_kernel(
        const __nv_bfloat16* __restrict__ Qh, const __nv_bfloat16* __restrict__ Ql,
        const __nv_bfloat16* __restrict__ Kh, const __nv_bfloat16* __restrict__ Kl,
        const __nv_bfloat16* __restrict__ Vh, const __nv_bfloat16* __restrict__ Vl,
        float* __restrict__ Pout,              // layer base: (B*H, L, L)
        __nv_bfloat16* __restrict__ Oh, __nv_bfloat16* __restrict__ Ol) {
    extern __shared__ char smraw[];
    float*         S    = (float*)smraw;                   // [16][SST]
    __nv_bfloat16* Qsh  = (__nv_bfloat16*)(S + 16*SST);    // [16][40]
    __nv_bfloat16* Qsl  = Qsh + 16*40;                     // [16][40]
    __nv_bfloat16* KVh  = Qsl + 16*40;                     // [256][40] / [32][264]
    __nv_bfloat16* KVl  = KVh + 256*40;
    float*         Ored = (float*)(KVl + 256*40);          // [8][512]

    const int tid = threadIdx.x, lane = tid & 31, warp = tid >> 5;
    const int bh = blockIdx.y;
    const int b  = bh >> 2, h = bh & 3;
    const int q0 = blockIdx.x * 16;
    const int tb = b * Ld;

    // Q tile (hi + lo)
    for (int i = tid; i < 16*32; i += 256) {
        int r = i >> 5, d = i & 31;
        size_t g = ((size_t)(tb + q0 + r)*Hd + h)*DKd + d;
        Qsh[r*40 + d] = Qh[g];
        Qsl[r*40 + d] = Ql[g];
    }
    __syncthreads();

    uint32_t aqh[2][4], aql[2][4];
    {
        const int r = (lane >> 2), c = (lane & 3)*2;
        #pragma unroll
        for (int kk = 0; kk < 2; kk++) {
            const __nv_bfloat16* p = &Qsh[r*40 + kk*16 + c];
            aqh[kk][0] = *(const uint32_t*)p;
            aqh[kk][1] = *(const uint32_t*)(p + 8*40);
            aqh[kk][2] = *(const uint32_t*)(p + 8);
            aqh[kk][3] = *(const uint32_t*)(p + 8*40 + 8);
            const __nv_bfloat16* pl = &Qsl[r*40 + kk*16 + c];
            aql[kk][0] = *(const uint32_t*)pl;
            aql[kk][1] = *(const uint32_t*)(pl + 8*40);
            aql[kk][2] = *(const uint32_t*)(pl + 8);
            aql[kk][3] = *(const uint32_t*)(pl + 8*40 + 8);
        }
    }

    // ---- QK^T over 8 chunks of 256 keys ----
    for (int c = 0; c < 8; c++) {
        const int s0 = c * 256;
        for (int i = tid; i < 4096; i += 256) {
            int r = i >> 4, d2 = (i & 15) * 2;
            uint32_t vh = 0, vl = 0;
            int s = s0 + r;
            if (s < Ld) {
                size_t g = ((size_t)(tb + s)*Hd + h)*DKd + d2;
                vh = *(const uint32_t*)&Kh[g];
                vl = *(const uint32_t*)&Kl[g];
            }
            *(uint32_t*)&KVh[r*40 + d2] = vh;
            *(uint32_t*)&KVl[r*40 + d2] = vl;
        }
        __syncthreads();

        float acc[4][4];
        #pragma unroll
        for (int i = 0; i < 4; i++)
            #pragma unroll
            for (int j = 0; j < 4; j++) acc[i][j] = 0.f;

        #pragma unroll
        for (int kk = 0; kk < 2; kk++) {
            #pragma unroll
            for (int nt = 0; nt < 4; nt++) {
                int nrow = warp*32 + nt*8 + (lane>>2);
                const __nv_bfloat16* pbh = &KVh[nrow*40 + kk*16 + (lane&3)*2];
                uint32_t bh0 = *(const uint32_t*)pbh;
                uint32_t bh1 = *(const uint32_t*)(pbh + 8);
                const __nv_bfloat16* pbl = &KVl[nrow*40 + kk*16 + (lane&3)*2];
                uint32_t bl0 = *(const uint32_t*)pbl;
                uint32_t bl1 = *(const uint32_t*)(pbl + 8);
                mma16816(acc[nt], aqh[kk], bh0, bh1);
                mma16816(acc[nt], aql[kk], bh0, bh1);
                mma16816(acc[nt], aqh[kk], bl0, bl1);
            }
        }
        #pragma unroll
        for (int nt = 0; nt < 4; nt++) {
            int col = s0 + warp*32 + nt*8 + (lane & 3)*2;
            int r = lane >> 2;
            #pragma unroll
            for (int half = 0; half < 2; half++) {
                float v0 = (col < Ld) ? acc[nt][half*2+0]*kSCALE : 0.f;
                float v1 = (col < Ld) ? acc[nt][half*2+1]*kSCALE : 0.f;
                S[(r + half*8)*SST + col]     = v0;
                S[(r + half*8)*SST + col + 1] = v1;
            }
        }
        __syncthreads();
    }

    // ---- softmax (warp w owns rows 2w, 2w+1), write P fp32 to gmem ----
    #pragma unroll
    for (int rr = 0; rr < 2; rr++) {
        int r = warp*2 + rr;
        float* srow = &S[r*SST];
        float m = -1e30f;
        for (int j = lane; j < Ld; j += 32) m = fmaxf(m, srow[j]);
        #pragma unroll
        for (int o = 16; o; o >>= 1) m = fmaxf(m, __shfl_xor_sync(~0u, m, o));
        float s = 0.f;
        for (int j = lane; j < Ld; j += 32) {
            float e = __expf(srow[j] - m);
            srow[j] = e;
            s += e;
        }
        #pragma unroll
        for (int o = 16; o; o >>= 1) s += __shfl_xor_sync(~0u, s, o);
        float iv = 1.f / s;
        float* grow = &Pout[((size_t)bh*Ld + q0 + r)*Ld];
        for (int j = lane; j < Ld; j += 32) {
            float p = srow[j] * iv;
            srow[j] = p;
            grow[j] = p;
        }
    }
    __syncthreads();

    // ---- O = P @ V : warp w handles k-slice [32w,32w+32) of each chunk ----
    float oacc[4][4];
    #pragma unroll
    for (int i = 0; i < 4; i++)
        #pragma unroll
        for (int j = 0; j < 4; j++) oacc[i][j] = 0.f;

    for (int c = 0; c < 8; c++) {
        const int s0 = c * 256;
        __syncthreads();
        for (int i = tid; i < 8192; i += 256) {  // V transposed: [d][s]
            int s = i >> 5, d = i & 31;
            int sg = s0 + s;
            __nv_bfloat16 vh = __float2bfloat16(0.f), vl = vh;
            if (sg < Ld) {
                size_t g = ((size_t)(tb + sg)*Hd + h)*DKd + d;
                vh = Vh[g]; vl = Vl[g];
            }
            KVh[d*264 + s] = vh;
            KVl[d*264 + s] = vl;
        }
        __syncthreads();

        const int ksl = warp * 32;
        #pragma unroll
        for (int kk = 0; kk < 2; kk++) {
            int kb = s0 + ksl + kk*16 + (lane & 3)*2;
            int r  = lane >> 2;
            uint32_t ah[4], al[4];
            pksplit(S[r*SST + kb],       S[r*SST + kb + 1],   ah[0], al[0]);
            pksplit(S[(r+8)*SST + kb],   S[(r+8)*SST + kb+1], ah[1], al[1]);
            pksplit(S[r*SST + kb + 8],   S[r*SST + kb + 9],   ah[2], al[2]);
            pksplit(S[(r+8)*SST + kb+8], S[(r+8)*SST + kb+9], ah[3], al[3]);
            #pragma unroll
            for (int nt = 0; nt < 4; nt++) {
                int drow = nt*8 + (lane>>2);
                const __nv_bfloat16* pbh = &KVh[drow*264 + ksl + kk*16 + (lane&3)*2];
                uint32_t bh0 = *(const uint32_t*)pbh;
                uint32_t bh1 = *(const uint32_t*)(pbh + 8);
                const __nv_bfloat16* pbl = &KVl[drow*264 + ksl + kk*16 + (lane&3)*2];
                uint32_t bl0 = *(const uint32_t*)pbl;
                uint32_t bl1 = *(const uint32_t*)(pbl + 8);
                mma16816(oacc[nt], ah, bh0, bh1);
                mma16816(oacc[nt], al, bh0, bh1);
                mma16816(oacc[nt], ah, bl0, bl1);
            }
        }
    }
    __syncthreads();

    #pragma unroll
    for (int nt = 0; nt < 4; nt++) {
        int cc = nt*8 + (lane & 3)*2;
        int r  = lane >> 2;
        Ored[warp*512 + r*32 + cc]       = oacc[nt][0];
        Ored[warp*512 + r*32 + cc + 1]   = oacc[nt][1];
        Ored[warp*512 + (r+8)*32 + cc]   = oacc[nt][2];
        Ored[warp*512 + (r+8)*32 + cc+1] = oacc[nt][3];
    }
    __syncthreads();
    for (int i = tid; i < 512; i += 256) {
        float s = 0.f;
        #pragma unroll
        for (int w = 0; w < 8; w++) s += Ored[w*512 + i];
        int r = i >> 5, d = i & 31;
        size_t g = ((size_t)(tb + q0 + r)*Hd + h)*DKd + d;
        __nv_bfloat16 hh, ll;
        fsplit(s, hh, ll);
        Oh[g] = hh; Ol[g] = ll;
    }
}

// ---------------------------------------------------------------------------
// Fused residual + LayerNorm : h = LN(h + add) ; writes fp32 + split bf16
// ---------------------------------------------------------------------------
__global__ __launch_bounds__(256) void ln_kernel(const float* __restrict__ add,
                                                 const float* __restrict__ gam,
                                                 const float* __restrict__ bet) {
    int warp = threadIdx.x >> 5, lane = threadIdx.x & 31;
    int token = blockIdx.x * 8 + warp;
    const float* hp = &g_h[(size_t)token*Dd];
    const float* ap = &add[(size_t)token*Dd];
    float x[8], s = 0.f;
    #pragma unroll
    for (int j = 0; j < 8; j++) { x[j] = hp[lane*8 + j] + ap[lane*8 + j]; s += x[j]; }
    #pragma unroll
    for (int o = 16; o; o >>= 1) s += __shfl_xor_sync(~0u, s, o);
    float mean = s * (1.f/256.f);
    float v = 0.f;
    #pragma unroll
    for (int j = 0; j < 8; j++) { float d = x[j] - mean; v += d*d; }
    #pragma unroll
    for (int o = 16; o; o >>= 1) v += __shfl_xor_sync(~0u, v, o);
    float rstd = rsqrtf(v * (1.f/256.f) + EPSLN);
    float* op = &g_h[(size_t)token*Dd];
    #pragma unroll
    for (int j = 0; j < 8; j++) {
        int cix = lane*8 + j;
        float y = (x[j] - mean)*rstd*gam[cix] + bet[cix];
        op[cix] = y;
        size_t ix = (size_t)token*Dd + cix;
        __nv_bfloat16 hh, ll;
        fsplit(y, hh, ll);
        g_hhi[ix] = hh;
        g_hlo[ix] = ll;
    }
}

// ---------------------------------------------------------------------------
// Final head tail: out = relu_h(g_tmp fp32) @ o2w + o2b   (warp per token)
// ---------------------------------------------------------------------------
__global__ __launch_bounds__(256) void head2_kernel(const float* __restrict__ o2w,
                                                    const float* __restrict__ o2b,
                                                    float* __restrict__ out) {
    int warp = threadIdx.x >> 5, lane = threadIdx.x & 31;
    int token = blockIdx.x * 8 + warp;
    const float* hp = &g_tmp[(size_t)token*Dd];
    float a0 = 0.f, a1 = 0.f;
    #pragma unroll
    for (int j = 0; j < 8; j++) {
        int k = lane + j*32;
        float hv = hp[k];
        a0 = fmaf(hv, o2w[k*2],   a0);
        a1 = fmaf(hv, o2w[k*2+1], a1);
    }
    #pragma unroll
    for (int o = 16; o; o >>= 1) {
        a0 += __shfl_xor_sync(~0u, a0, o);
        a1 += __shfl_xor_sync(~0u, a1, o);
    }
    if (lane == 0) {
        out[(size_t)token*2]     = a0 + o2b[0];
        out[(size_t)token*2 + 1] = a1 + o2b[1];
    }
}

// ---------------------------------------------------------------------------
// Host orchestration
// ---------------------------------------------------------------------------
static inline void* symaddr(const void* s) {
    void* p = nullptr;
    cudaGetSymbolAddress(&p, s);
    return p;
}

extern "C" void kernel_launch(void* const* d_in, const int* in_sizes, int n_in,
                              void* d_out, int out_size) {
    const float* x    = (const float*)d_in[0];
    const float* in_w = (const float*)d_in[1];
    const float* in_b = (const float*)d_in[2];
    const float* qw   = (const float*)d_in[3];
    const float* qb   = (const float*)d_in[4];
    const float* kw   = (const float*)d_in[5];
    const float* kb   = (const float*)d_in[6];
    const float* vw   = (const float*)d_in[7];
    const float* vb   = (const float*)d_in[8];
    const float* ow   = (const float*)d_in[9];
    const float* ob   = (const float*)d_in[10];
    const float* f1w  = (const float*)d_in[11];
    const float* f1b  = (const float*)d_in[12];
    const float* f2w  = (const float*)d_in[13];
    const float* f2b  = (const float*)d_in[14];
    const float* n1g  = (const float*)d_in[15];
    const float* n1b  = (const float*)d_in[16];
    const float* n2g  = (const float*)d_in[17];
    const float* n2b  = (const float*)d_in[18];
    const float* o1w  = (const float*)d_in[19];
    const float* o1b  = (const float*)d_in[20];
    const float* o2w  = (const float*)d_in[21];
    const float* o2b  = (const float*)d_in[22];

    float* outp     = (float*)d_out;
    float* attn_out = outp + (size_t)Bd*Ld*2;

    __nv_bfloat16* p_hh  = (__nv_bfloat16*)symaddr(g_hhi);
    __nv_bfloat16* p_hl  = (__nv_bfloat16*)symaddr(g_hlo);
    __nv_bfloat16* p_qh  = (__nv_bfloat16*)symaddr(g_qhi);
    __nv_bfloat16* p_ql  = (__nv_bfloat16*)symaddr(g_qlo);
    __nv_bfloat16* p_kh  = (__nv_bfloat16*)symaddr(g_khi);
    __nv_bfloat16* p_kl  = (__nv_bfloat16*)symaddr(g_klo);
    __nv_bfloat16* p_vh  = (__nv_bfloat16*)symaddr(g_vhi);
    __nv_bfloat16* p_vl  = (__nv_bfloat16*)symaddr(g_vlo);
    __nv_bfloat16* p_oh  = (__nv_bfloat16*)symaddr(g_ohi);
    __nv_bfloat16* p_ol  = (__nv_bfloat16*)symaddr(g_olo);
    __nv_bfloat16* p_fh  = (__nv_bfloat16*)symaddr(g_fhi);
    __nv_bfloat16* p_fl  = (__nv_bfloat16*)symaddr(g_flo);
    float*         p_tmp = (float*)symaddr(g_tmp);
    __nv_bfloat16* p_qwh = (__nv_bfloat16*)symaddr(g_qwh);
    __nv_bfloat16* p_qwl = (__nv_bfloat16*)symaddr(g_qwl);
    __nv_bfloat16* p_kwh = (__nv_bfloat16*)symaddr(g_kwh);
    __nv_bfloat16* p_kwl = (__nv_bfloat16*)symaddr(g_kwl);
    __nv_bfloat16* p_vwh = (__nv_bfloat16*)symaddr(g_vwh);
    __nv_bfloat16* p_vwl = (__nv_bfloat16*)symaddr(g_vwl);
    __nv_bfloat16* p_owh = (__nv_bfloat16*)symaddr(g_owh);
    __nv_bfloat16* p_owl = (__nv_bfloat16*)symaddr(g_owl);
    __nv_bfloat16* p_f1h = (__nv_bfloat16*)symaddr(g_f1wh);
    __nv_bfloat16* p_f1l = (__nv_bfloat16*)symaddr(g_f1wl);
    __nv_bfloat16* p_f2h = (__nv_bfloat16*)symaddr(g_f2wh);
    __nv_bfloat16* p_f2l = (__nv_bfloat16*)symaddr(g_f2wl);
    __nv_bfloat16* p_o1h = (__nv_bfloat16*)symaddr(g_o1wh);
    __nv_bfloat16* p_o1l = (__nv_bfloat16*)symaddr(g_o1wl);

    const int SM_G256 = (2*128*(256+8) + 2*64*(256+2)) * 2;   // 201216
    const int SM_G128 = (2*128*(128+8) + 2*64*(128+2)) * 2;   // 102912
    const int SM_G64  = (2*128*(64+8)  + 2*64*(64+2))  * 2;   // 53760
    const int SM_ATTN = 16*SST*4 + 2*16*40*2 + 2*256*40*2 + 8*512*4;  // 191488

    cudaFuncSetAttribute(gemm_bias<256,true ,false,false>, cudaFuncAttributeMaxDynamicSharedMemorySize, SM_G256);
    cudaFuncSetAttribute(gemm_bias<256,true ,false,true >, cudaFuncAttributeMaxDynamicSharedMemorySize, SM_G256);
    cudaFuncSetAttribute(gemm_bias<256,false,true ,true >, cudaFuncAttributeMaxDynamicSharedMemorySize, SM_G256);
    cudaFuncSetAttribute(gemm_bias<128,false,true ,false>, cudaFuncAttributeMaxDynamicSharedMemorySize, SM_G128);
    cudaFuncSetAttribute(gemm_bias<64 ,false,true ,false>, cudaFuncAttributeMaxDynamicSharedMemorySize, SM_G64);
    cudaFuncSetAttribute(attn_kernel, cudaFuncAttributeMaxDynamicSharedMemorySize, SM_ATTN);

    convert_w<<<384, 256>>>(qw, kw, vw, ow, f1w, f2w, o1w);
    embed_kernel<<<BLd, Dd>>>(x, in_w, in_b);

    const dim3 gQKV (BLd/128, 2);   // N=128
    const dim3 gProj(BLd/128, 4);   // N=256
    const dim3 gF1  (BLd/128, 1);   // N=64
    const dim3 gAttn(Ld/16, Bd*Hd);

    for (int i = 0; i < NLd; i++) {
        gemm_bias<256,true,false,false><<<gQKV, 256, SM_G256>>>(
            p_hh, p_hl, p_qwh + (size_t)i*Dd*128, p_qwl + (size_t)i*Dd*128,
            qb + i*128, nullptr, p_qh, p_ql, 128);
        gemm_bias<256,true,false,false><<<gQKV, 256, SM_G256>>>(
            p_hh, p_hl, p_kwh + (size_t)i*Dd*128, p_kwl + (size_t)i*Dd*128,
            kb + i*128, nullptr, p_kh, p_kl, 128);
        gemm_bias<256,true,false,false><<<gQKV, 256, SM_G256>>>(
            p_hh, p_hl, p_vwh + (size_t)i*Dd*128, p_vwl + (size_t)i*Dd*128,
            vb + i*128, nullptr, p_vh, p_vl, 128);

        attn_kernel<<<gAttn, 256, SM_ATTN>>>(
            p_qh, p_ql, p_kh, p_kl, p_vh, p_vl,
            attn_out + (size_t)i*Bd*Hd*Ld*Ld, p_oh, p_ol);

        gemm_bias<128,false,true,false><<<gProj, 256, SM_G128>>>(
            p_oh, p_ol, p_owh + (size_t)i*128*Dd, p_owl + (size_t)i*128*Dd,
            ob + i*Dd, p_tmp, nullptr, nullptr, Dd);
        ln_kernel<<<BLd/8, 256>>>(p_tmp, n1g + i*Dd, n1b + i*Dd);

        gemm_bias<256,true,false,true><<<gF1, 256, SM_G256>>>(
            p_hh, p_hl, p_f1h + (size_t)i*Dd*FCd, p_f1l + (size_t)i*Dd*FCd,
            f1b + i*FCd, nullptr, p_fh, p_fl, FCd);
        gemm_bias<64,false,true,false><<<gProj, 256, SM_G64>>>(
            p_fh, p_fl, p_f2h + (size_t)i*FCd*Dd, p_f2l + (size_t)i*FCd*Dd,
            f2b + i*Dd, p_tmp, nullptr, nullptr, Dd);
        ln_kernel<<<BLd/8, 256>>>(p_tmp, n2g + i*Dd, n2b + i*Dd);
    }

    gemm_bias<256,false,true,true><<<gProj, 256, SM_G256>>>(
        p_hh, p_hl, p_o1h, p_o1l, o1b, p_tmp, nullptr, nullptr, Dd);
    head2_kernel<<<BLd/8, 256>>>(o2w, o2b, outp);
}

// round 4
// speedup vs baseline: 3.3374x; 3.3374x over previous
#include <cuda_runtime.h>
#include <cuda_bf16.h>
#include <stdint.h>

#define Bd  8
#define Ld  2016
#define Hd  4
#define DKd 32
#define Dd  256
#define FCd 64
#define NLd 3
#define BLd (Bd*Ld)          // 16128 tokens

#define SCALEF 0.0625f       // 1/sqrt(256)
#define EPSLN 1e-5f

// ---------------------------------------------------------------------------
// Device scratch (no allocation allowed). hi/lo split bf16 pairs everywhere.
// ---------------------------------------------------------------------------
__device__ __align__(128) float          g_h    [BLd*Dd];
__device__ __align__(128) __nv_bfloat16  g_hhi  [BLd*Dd];
__device__ __align__(128) __nv_bfloat16  g_hlo  [BLd*Dd];
__device__ __align__(128) __nv_bfloat16  g_qkvh [3*BLd*128];
__device__ __align__(128) __nv_bfloat16  g_qkvl [3*BLd*128];
__device__ __align__(128) __nv_bfloat16  g_ohi  [BLd*128];
__device__ __align__(128) __nv_bfloat16  g_olo  [BLd*128];
__device__ __align__(128) float          g_tmp  [BLd*Dd];
__device__ __align__(128) __nv_bfloat16  g_fhi  [BLd*FCd];
__device__ __align__(128) __nv_bfloat16  g_flo  [BLd*FCd];
// split weights
__device__ __align__(128) __nv_bfloat16  g_qkvwh[NLd*3*Dd*128];
__device__ __align__(128) __nv_bfloat16  g_qkvwl[NLd*3*Dd*128];
__device__ __align__(128) float          g_qkvb [NLd*3*128];
__device__ __align__(128) __nv_bfloat16  g_owh  [NLd*128*Dd];
__device__ __align__(128) __nv_bfloat16  g_owl  [NLd*128*Dd];
__device__ __align__(128) __nv_bfloat16  g_f1wh [NLd*Dd*FCd];
__device__ __align__(128) __nv_bfloat16  g_f1wl [NLd*Dd*FCd];
__device__ __align__(128) __nv_bfloat16  g_f2wh [NLd*FCd*Dd];
__device__ __align__(128) __nv_bfloat16  g_f2wl [NLd*FCd*Dd];
__device__ __align__(128) __nv_bfloat16  g_o1wh [Dd*Dd];
__device__ __align__(128) __nv_bfloat16  g_o1wl [Dd*Dd];

// ---------------------------------------------------------------------------
// helpers
// ---------------------------------------------------------------------------
__device__ __forceinline__ void mma16816(float* d, const uint32_t* a,
                                         uint32_t b0, uint32_t b1) {
    asm volatile(
        "mma.sync.aligned.m16n8k16.row.col.f32.bf16.bf16.f32 "
        "{%0,%1,%2,%3}, {%4,%5,%6,%7}, {%8,%9}, {%0,%1,%2,%3};"
        : "+f"(d[0]), "+f"(d[1]), "+f"(d[2]), "+f"(d[3])
        : "r"(a[0]), "r"(a[1]), "r"(a[2]), "r"(a[3]), "r"(b0), "r"(b1));
}

__device__ __forceinline__ uint32_t pk2(float x, float y) {
    __nv_bfloat162 t = __floats2bfloat162_rn(x, y);
    return *reinterpret_cast<uint32_t*>(&t);
}

__device__ __forceinline__ void fsplit(float v, __nv_bfloat16& hi, __nv_bfloat16& lo) {
    hi = __float2bfloat16(v);
    lo = __float2bfloat16(v - __bfloat162float(hi));
}

__device__ __forceinline__ void pksplit(float x, float y, uint32_t& hi, uint32_t& lo) {
    __nv_bfloat16 xh = __float2bfloat16(x), yh = __float2bfloat16(y);
    __nv_bfloat162 th; th.x = xh; th.y = yh;
    hi = *reinterpret_cast<uint32_t*>(&th);
    lo = pk2(x - __bfloat162float(xh), y - __bfloat162float(yh));
}

// ---------------------------------------------------------------------------
// Weight conversion fp32 -> bf16 hi/lo (+ QKV packing)
// ---------------------------------------------------------------------------
__global__ void convert_w(const float* __restrict__ qw, const float* __restrict__ kw,
                          const float* __restrict__ vw, const float* __restrict__ ow,
                          const float* __restrict__ f1w, const float* __restrict__ f2w,
                          const float* __restrict__ o1w,
                          const float* __restrict__ qb, const float* __restrict__ kb,
                          const float* __restrict__ vb) {
    int i = blockIdx.x * 256 + threadIdx.x;
    const int n1 = NLd*Dd*128;   // 98304 (also ow)
    const int n3 = NLd*Dd*FCd;   // 49152 (also f2w)
    const int n5 = Dd*Dd;        // 65536
    if (i < n1) {
        int l = i / (Dd*128), rem = i % (Dd*128);
        size_t b = (size_t)(l*3)*Dd*128 + rem;
        fsplit(qw[i], g_qkvwh[b],            g_qkvwl[b]);
        fsplit(kw[i], g_qkvwh[b + Dd*128],   g_qkvwl[b + Dd*128]);
        fsplit(vw[i], g_qkvwh[b + 2*Dd*128], g_qkvwl[b + 2*Dd*128]);
        fsplit(ow[i], g_owh[i], g_owl[i]);
    }
    if (i < n3) {
        fsplit(f1w[i], g_f1wh[i], g_f1wl[i]);
        fsplit(f2w[i], g_f2wh[i], g_f2wl[i]);
    }
    if (i < n5) fsplit(o1w[i], g_o1wh[i], g_o1wl[i]);
    if (i < NLd*128) {
        int l = i >> 7, n = i & 127;
        g_qkvb[(l*3+0)*128 + n] = qb[i];
        g_qkvb[(l*3+1)*128 + n] = kb[i];
        g_qkvb[(l*3+2)*128 + n] = vb[i];
    }
}

// ---------------------------------------------------------------------------
// Embed: h = x @ in_w + in_b (fp32 + split)
// ---------------------------------------------------------------------------
__global__ void embed_kernel(const float* __restrict__ x,
                             const float* __restrict__ in_w,
                             const float* __restrict__ in_b) {
    int t = blockIdx.x, d = threadIdx.x;
    float x0 = x[t*2], x1 = x[t*2+1];
    float v = fmaf(x0, in_w[d], fmaf(x1, in_w[Dd + d], in_b[d]));
    size_t ix = (size_t)t*Dd + d;
    g_h[ix] = v;
    fsplit(v, g_hhi[ix], g_hlo[ix]);
}

// ---------------------------------------------------------------------------
// GEMM core (shared by generic + qkv): tile 128x64, 512 threads (16 warps:
// 8 M-slices x 2 N-slices). 3-term split MMA. SW/SA = K+8 (conflict-free
// fragment LDS).
// ---------------------------------------------------------------------------
template<int K, bool OUT_B16, bool OUT_F32, bool RELU>
__device__ __forceinline__ void gemm_body(
        const __nv_bfloat16* __restrict__ Ahi,
        const __nv_bfloat16* __restrict__ Alo,
        const __nv_bfloat16* __restrict__ Whi,
        const __nv_bfloat16* __restrict__ Wlo,
        const float* __restrict__ bias,
        float* __restrict__ outF,
        __nv_bfloat16* __restrict__ outBh,
        __nv_bfloat16* __restrict__ outBl,
        int N, int row0, int col0) {
    extern __shared__ __nv_bfloat16 sm[];
    constexpr int SA = K + 8;
    __nv_bfloat16* sAh = sm;
    __nv_bfloat16* sAl = sm + 128 * SA;
    __nv_bfloat16* sWh = sm + 256 * SA;
    __nv_bfloat16* sWl = sWh + 64 * SA;

    const int tid = threadIdx.x, lane = tid & 31, warp = tid >> 5;

    constexpr int AV = K / 8;
    #pragma unroll 2
    for (int i = tid; i < 128 * AV; i += 512) {
        int r = i / AV, c = (i % AV) * 8;
        size_t g = (size_t)(row0 + r)*K + c;
        *reinterpret_cast<uint4*>(&sAh[r*SA + c]) = *reinterpret_cast<const uint4*>(&Ahi[g]);
        *reinterpret_cast<uint4*>(&sAl[r*SA + c]) = *reinterpret_cast<const uint4*>(&Alo[g]);
    }
    #pragma unroll 2
    for (int i = tid; i < 64 * K / 4; i += 512) {
        int k = i >> 4, n4 = (i & 15) * 4;
        size_t g = (size_t)k*N + col0 + n4;
        uint2 wh = *reinterpret_cast<const uint2*>(&Whi[g]);
        uint2 wl = *reinterpret_cast<const uint2*>(&Wlo[g]);
        __nv_bfloat16 th[4]; *reinterpret_cast<uint2*>(th) = wh;
        __nv_bfloat16 tl[4]; *reinterpret_cast<uint2*>(tl) = wl;
        #pragma unroll
        for (int j = 0; j < 4; j++) {
            sWh[(n4+j)*SA + k] = th[j];
            sWl[(n4+j)*SA + k] = tl[j];
        }
    }
    __syncthreads();

    float acc[4][4];
    #pragma unroll
    for (int i = 0; i < 4; i++)
        #pragma unroll
        for (int j = 0; j < 4; j++) acc[i][j] = 0.f;

    const int mwarp = warp >> 1, nwarp = warp & 1;
    const int ar = mwarp*16 + (lane >> 2);
    const int ac = (lane & 3) * 2;
    #pragma unroll
    for (int kk = 0; kk < K/16; kk++) {
        uint32_t ah[4], al[4];
        {
            const __nv_bfloat16* pa = &sAh[ar*SA + kk*16 + ac];
            ah[0] = *(const uint32_t*)pa;
            ah[1] = *(const uint32_t*)(pa + 8*SA);
            ah[2] = *(const uint32_t*)(pa + 8);
            ah[3] = *(const uint32_t*)(pa + 8*SA + 8);
            const __nv_bfloat16* pl = &sAl[ar*SA + kk*16 + ac];
            al[0] = *(const uint32_t*)pl;
            al[1] = *(const uint32_t*)(pl + 8*SA);
            al[2] = *(const uint32_t*)(pl + 8);
            al[3] = *(const uint32_t*)(pl + 8*SA + 8);
        }
        #pragma unroll
        for (int nt = 0; nt < 4; nt++) {
            int nrow = nwarp*32 + nt*8 + (lane>>2);
            const __nv_bfloat16* pbh = &sWh[nrow*SA + kk*16 + ac];
            uint32_t bh0 = *(const uint32_t*)pbh;
            uint32_t bh1 = *(const uint32_t*)(pbh + 8);
            const __nv_bfloat16* pbl = &sWl[nrow*SA + kk*16 + ac];
            uint32_t bl0 = *(const uint32_t*)pbl;
            uint32_t bl1 = *(const uint32_t*)(pbl + 8);
            mma16816(acc[nt], ah, bh0, bh1);
            mma16816(acc[nt], al, bh0, bh1);
            mma16816(acc[nt], ah, bl0, bl1);
        }
    }

    const int orow = row0 + mwarp*16 + (lane >> 2);
    #pragma unroll
    for (int nt = 0; nt < 4; nt++) {
        int c = col0 + nwarp*32 + nt*8 + (lane & 3)*2;
        float b0v = bias[c], b1v = bias[c+1];
        #pragma unroll
        for (int half = 0; half < 2; half++) {
            int r = orow + half*8;
            float v0 = acc[nt][half*2+0] + b0v;
            float v1 = acc[nt][half*2+1] + b1v;
            if (RELU) { v0 = fmaxf(v0, 0.f); v1 = fmaxf(v1, 0.f); }
            size_t o = (size_t)r*N + c;
            if (OUT_F32) { outF[o] = v0; outF[o+1] = v1; }
            if (OUT_B16) {
                __nv_bfloat16 h0, l0, h1, l1;
                fsplit(v0, h0, l0);
                fsplit(v1, h1, l1);
                outBh[o] = h0; outBh[o+1] = h1;
                outBl[o] = l0; outBl[o+1] = l1;
            }
        }
    }
}

template<int K, bool OUT_B16, bool OUT_F32, bool RELU>
__global__ __launch_bounds__(512) void gemm_bias(
        const __nv_bfloat16* __restrict__ Ahi, const __nv_bfloat16* __restrict__ Alo,
        const __nv_bfloat16* __restrict__ Whi, const __nv_bfloat16* __restrict__ Wlo,
        const float* __restrict__ bias,
        float* __restrict__ outF,
        __nv_bfloat16* __restrict__ outBh, __nv_bfloat16* __restrict__ outBl,
        int N) {
    gemm_body<K, OUT_B16, OUT_F32, RELU>(Ahi, Alo, Whi, Wlo, bias, outF, outBh, outBl,
                                         N, blockIdx.x*128, blockIdx.y*64);
}

// Fused QKV: grid (126, 6); blockIdx.y selects (q/k/v, col-half)
__global__ __launch_bounds__(512) void gemm_qkv(int layer) {
    int sel = blockIdx.y >> 1;
    int col0 = (blockIdx.y & 1) * 64;
    const __nv_bfloat16* Whi = g_qkvwh + ((size_t)(layer*3 + sel))*Dd*128;
    const __nv_bfloat16* Wlo = g_qkvwl + ((size_t)(layer*3 + sel))*Dd*128;
    const float* bias = g_qkvb + (layer*3 + sel)*128;
    __nv_bfloat16* oh = g_qkvh + (size_t)sel*BLd*128;
    __nv_bfloat16* ol = g_qkvl + (size_t)sel*BLd*128;
    gemm_body<256, true, false, false>(g_hhi, g_hlo, Whi, Wlo, bias, nullptr, oh, ol,
                                       128, blockIdx.x*128, col0);
}

// ---------------------------------------------------------------------------
// Attention: two-pass flash-style. 128-query tile per CTA, 8 warps (16 rows
// each). Pass A: online (max, sum). Pass B: recompute S, P=exp(s-m)/sum ->
// gmem (fp32) + PV via register A-fragments. 3-term split MMA everywhere.
// smem 57KB -> 2 CTAs/SM.
// ---------------------------------------------------------------------------
#define NCH 16          // chunks of 128 keys (2048 padded)

__global__ __launch_bounds__(256, 2) void attn_kernel(
        const __nv_bfloat16* __restrict__ qkvh,
        const __nv_bfloat16* __restrict__ qkvl,
        float* __restrict__ Pout,              // layer base: (B*H, L, L)
        __nv_bfloat16* __restrict__ Oh, __nv_bfloat16* __restrict__ Ol) {
    extern __shared__ __nv_bfloat16 sm[];
    __nv_bfloat16* sQh = sm;              // [128][40]
    __nv_bfloat16* sQl = sm + 5120;
    __nv_bfloat16* sKh = sm + 10240;      // [128][40]
    __nv_bfloat16* sKl = sm + 15360;
    __nv_bfloat16* sVh = sm + 20480;      // [32][136] transposed
    __nv_bfloat16* sVl = sm + 24832;

    const int tid = threadIdx.x, lane = tid & 31, warp = tid >> 5;
    const int bh = blockIdx.y;
    const int b  = bh >> 2, h = bh & 3;
    const int q0 = blockIdx.x * 128;
    const size_t base = ((size_t)b*Ld*Hd + h)*DKd;   // token t -> base + t*128
    const __nv_bfloat16* Qh = qkvh;
    const __nv_bfloat16* Ql = qkvl;
    const __nv_bfloat16* Kh = qkvh + (size_t)BLd*128;
    const __nv_bfloat16* Kl = qkvl + (size_t)BLd*128;
    const __nv_bfloat16* Vh = qkvh + (size_t)2*BLd*128;
    const __nv_bfloat16* Vl = qkvl + (size_t)2*BLd*128;

    // ---- load Q tile (zero-padded) ----
    for (int i = tid; i < 128*16; i += 256) {
        int r = i >> 4, d2 = (i & 15) * 2;
        int row = q0 + r;
        uint32_t vh = 0, vl = 0;
        if (row < Ld) {
            size_t g = base + (size_t)row*128 + d2;
            vh = *(const uint32_t*)&Qh[g];
            vl = *(const uint32_t*)&Ql[g];
        }
        *(uint32_t*)&sQh[r*40 + d2] = vh;
        *(uint32_t*)&sQl[r*40 + d2] = vl;
    }
    __syncthreads();

    // per-warp Q fragments (rows mrow..mrow+15)
    const int mrow = warp * 16;
    const int fr = lane >> 2, fc = (lane & 3) * 2;
    uint32_t aqh[2][4], aql[2][4];
    #pragma unroll
    for (int kk = 0; kk < 2; kk++) {
        const __nv_bfloat16* p = &sQh[(mrow + fr)*40 + kk*16 + fc];
        aqh[kk][0] = *(const uint32_t*)p;
        aqh[kk][1] = *(const uint32_t*)(p + 8*40);
        aqh[kk][2] = *(const uint32_t*)(p + 8);
        aqh[kk][3] = *(const uint32_t*)(p + 8*40 + 8);
        const __nv_bfloat16* pl = &sQl[(mrow + fr)*40 + kk*16 + fc];
        aql[kk][0] = *(const uint32_t*)pl;
        aql[kk][1] = *(const uint32_t*)(pl + 8*40);
        aql[kk][2] = *(const uint32_t*)(pl + 8);
        aql[kk][3] = *(const uint32_t*)(pl + 8*40 + 8);
    }

    float m0 = -1e30f, m1 = -1e30f, s0 = 0.f, s1 = 0.f;

    // ================= PASS A: stats =================
    for (int ch = 0; ch < NCH; ch++) {
        const int k0 = ch * 128;
        __syncthreads();
        for (int i = tid; i < 2048; i += 256) {
            int r = i >> 4, d2 = (i & 15) * 2;
            int s = k0 + r;
            uint32_t vh = 0, vl = 0;
            if (s < Ld) {
                size_t g = base + (size_t)s*128 + d2;
                vh = *(const uint32_t*)&Kh[g];
                vl = *(const uint32_t*)&Kl[g];
            }
            *(uint32_t*)&sKh[r*40 + d2] = vh;
            *(uint32_t*)&sKl[r*40 + d2] = vl;
        }
        __syncthreads();

        #pragma unroll
        for (int gq = 0; gq < 4; gq++) {           // 4 groups x 4 n-tiles
            float acc[4][4];
            #pragma unroll
            for (int i = 0; i < 4; i++)
                #pragma unroll
                for (int j = 0; j < 4; j++) acc[i][j] = 0.f;
            #pragma unroll
            for (int nt = 0; nt < 4; nt++) {
                int nrow = gq*32 + nt*8 + fr;
                #pragma unroll
                for (int kk = 0; kk < 2; kk++) {
                    const __nv_bfloat16* pbh = &sKh[nrow*40 + kk*16 + fc];
                    uint32_t bh0 = *(const uint32_t*)pbh;
                    uint32_t bh1 = *(const uint32_t*)(pbh + 8);
                    const __nv_bfloat16* pbl = &sKl[nrow*40 + kk*16 + fc];
                    uint32_t bl0 = *(const uint32_t*)pbl;
                    uint32_t bl1 = *(const uint32_t*)(pbl + 8);
                    mma16816(acc[nt], aqh[kk], bh0, bh1);
                    mma16816(acc[nt], aql[kk], bh0, bh1);
                    mma16816(acc[nt], aqh[kk], bl0, bl1);
                }
            }
            // online softmax update (per-thread partial cols)
            float v[4][4];
            float nm0 = m0, nm1 = m1;
            #pragma unroll
            for (int nt = 0; nt < 4; nt++) {
                int col = k0 + gq*32 + nt*8 + fc;
                bool ok = (col < Ld);
                v[nt][0] = ok ? acc[nt][0]*SCALEF : -1e30f;
                v[nt][1] = ok ? acc[nt][1]*SCALEF : -1e30f;
                v[nt][2] = ok ? acc[nt][2]*SCALEF : -1e30f;
                v[nt][3] = ok ? acc[nt][3]*SCALEF : -1e30f;
                nm0 = fmaxf(nm0, fmaxf(v[nt][0], v[nt][1]));
                nm1 = fmaxf(nm1, fmaxf(v[nt][2], v[nt][3]));
            }
            float a0 = s0 * __expf(m0 - nm0);
            float a1 = s1 * __expf(m1 - nm1);
            #pragma unroll
            for (int nt = 0; nt < 4; nt++) {
                a0 += __expf(v[nt][0] - nm0) + __expf(v[nt][1] - nm0);
                a1 += __expf(v[nt][2] - nm1) + __expf(v[nt][3] - nm1);
            }
            s0 = a0; s1 = a1; m0 = nm0; m1 = nm1;
        }
    }

    // quad reduce (m, s)
    #pragma unroll
    for (int off = 1; off <= 2; off <<= 1) {
        float mo = __shfl_xor_sync(~0u, m0, off);
        float so = __shfl_xor_sync(~0u, s0, off);
        float nm = fmaxf(m0, mo);
        s0 = s0*__expf(m0 - nm) + so*__expf(mo - nm);
        m0 = nm;
        mo = __shfl_xor_sync(~0u, m1, off);
        so = __shfl_xor_sync(~0u, s1, off);
        nm = fmaxf(m1, mo);
        s1 = s1*__expf(m1 - nm) + so*__expf(mo - nm);
        m1 = nm;
    }
    const float inv0 = 1.f / s0, inv1 = 1.f / s1;

    // ================= PASS B: P out + PV =================
    float oacc[4][4];
    #pragma unroll
    for (int i = 0; i < 4; i++)
        #pragma unroll
        for (int j = 0; j < 4; j++) oacc[i][j] = 0.f;

    const int grow0 = q0 + mrow + fr;        // global query rows
    float* prow0 = &Pout[((size_t)bh*Ld + grow0)*Ld];
    float* prow1 = prow0 + 8*(size_t)Ld;
    const bool wr0 = (grow0 < Ld), wr1 = (grow0 + 8 < Ld);

    for (int ch = 0; ch < NCH; ch++) {
        const int k0 = ch * 128;
        __syncthreads();
        for (int i = tid; i < 2048; i += 256) {
            int r = i >> 4, d2 = (i & 15) * 2;
            int s = k0 + r;
            uint32_t vh = 0, vl = 0;
            if (s < Ld) {
                size_t g = base + (size_t)s*128 + d2;
                vh = *(const uint32_t*)&Kh[g];
                vl = *(const uint32_t*)&Kl[g];
            }
            *(uint32_t*)&sKh[r*40 + d2] = vh;
            *(uint32_t*)&sKl[r*40 + d2] = vl;
        }
        for (int i = tid; i < 2048; i += 256) {   // V -> transposed [d][s]
            int s = i >> 4, d2 = (i & 15) * 2;
            int sg = k0 + s;
            uint32_t vh = 0, vl = 0;
            if (sg < Ld) {
                size_t g = base + (size_t)sg*128 + d2;
                vh = *(const uint32_t*)&Vh[g];
                vl = *(const uint32_t*)&Vl[g];
            }
            __nv_bfloat162 h2 = *reinterpret_cast<__nv_bfloat162*>(&vh);
            __nv_bfloat162 l2 = *reinterpret_cast<__nv_bfloat162*>(&vl);
            sVh[ d2   *136 + s] = h2.x;
            sVh[(d2+1)*136 + s] = h2.y;
            sVl[ d2   *136 + s] = l2.x;
            sVl[(d2+1)*136 + s] = l2.y;
        }
        __syncthreads();

        #pragma unroll
        for (int g = 0; g < 8; g++) {             // 16-key groups
            float acc[2][4];
            #pragma unroll
            for (int i = 0; i < 2; i++)
                #pragma unroll
                for (int j = 0; j < 4; j++) acc[i][j] = 0.f;
            #pragma unroll
            for (int nt = 0; nt < 2; nt++) {
                int nrow = g*16 + nt*8 + fr;
                #pragma unroll
                for (int kk = 0; kk < 2; kk++) {
                    const __nv_bfloat16* pbh = &sKh[nrow*40 + kk*16 + fc];
                    uint32_t bh0 = *(const uint32_t*)pbh;
                    uint32_t bh1 = *(const uint32_t*)(pbh + 8);
                    const __nv_bfloat16* pbl = &sKl[nrow*40 + kk*16 + fc];
                    uint32_t bl0 = *(const uint32_t*)pbl;
                    uint32_t bl1 = *(const uint32_t*)(pbl + 8);
                    mma16816(acc[nt], aqh[kk], bh0, bh1);
                    mma16816(acc[nt], aql[kk], bh0, bh1);
                    mma16816(acc[nt], aqh[kk], bl0, bl1);
                }
            }
            int colb = k0 + g*16 + fc;
            bool ok0 = (colb < Ld), ok1 = (colb + 8 < Ld);
            float p00 = ok0 ? __expf(acc[0][0]*SCALEF - m0)*inv0 : 0.f;
            float p01 = ok0 ? __expf(acc[0][1]*SCALEF - m0)*inv0 : 0.f;
            float p02 = ok0 ? __expf(acc[0][2]*SCALEF - m1)*inv1 : 0.f;
            float p03 = ok0 ? __expf(acc[0][3]*SCALEF - m1)*inv1 : 0.f;
            float p10 = ok1 ? __expf(acc[1][0]*SCALEF - m0)*inv0 : 0.f;
            float p11 = ok1 ? __expf(acc[1][1]*SCALEF - m0)*inv0 : 0.f;
            float p12 = ok1 ? __expf(acc[1][2]*SCALEF - m1)*inv1 : 0.f;
            float p13 = ok1 ? __expf(acc[1][3]*SCALEF - m1)*inv1 : 0.f;

            if (wr0) {
                if (ok0) *(float2*)&prow0[colb]     = make_float2(p00, p01);
                if (ok1) *(float2*)&prow0[colb + 8] = make_float2(p10, p11);
            }
            if (wr1) {
                if (ok0) *(float2*)&prow1[colb]     = make_float2(p02, p03);
                if (ok1) *(float2*)&prow1[colb + 8] = make_float2(p12, p13);
            }

            uint32_t ah[4], al[4];
            pksplit(p00, p01, ah[0], al[0]);
            pksplit(p02, p03, ah[1], al[1]);
            pksplit(p10, p11, ah[2], al[2]);
            pksplit(p12, p13, ah[3], al[3]);

            #pragma unroll
            for (int dt = 0; dt < 4; dt++) {
                int nd = dt*8 + fr;
                const __nv_bfloat16* pbh = &sVh[nd*136 + g*16 + fc];
                uint32_t bh0 = *(const uint32_t*)pbh;
                uint32_t bh1 = *(const uint32_t*)(pbh + 8);
                const __nv_bfloat16* pbl = &sVl[nd*136 + g*16 + fc];
                uint32_t bl0 = *(const uint32_t*)pbl;
                uint32_t bl1 = *(const uint32_t*)(pbl + 8);
                mma16816(oacc[dt], ah, bh0, bh1);
                mma16816(oacc[dt], al, bh0, bh1);
                mma16816(oacc[dt], ah, bl0, bl1);
            }
        }
    }

    // ---- write O (hi/lo) ----
    #pragma unroll
    for (int dt = 0; dt < 4; dt++) {
        int d = dt*8 + fc;
        if (wr0) {
            size_t g = base + (size_t)grow0*128 + d;
            __nv_bfloat16 hh, ll;
            fsplit(oacc[dt][0], hh, ll); Oh[g]   = hh; Ol[g]   = ll;
            fsplit(oacc[dt][1], hh, ll); Oh[g+1] = hh; Ol[g+1] = ll;
        }
        if (wr1) {
            size_t g = base + (size_t)(grow0+8)*128 + d;
            __nv_bfloat16 hh, ll;
            fsplit(oacc[dt][2], hh, ll); Oh[g]   = hh; Ol[g]   = ll;
            fsplit(oacc[dt][3], hh, ll); Oh[g+1] = hh; Ol[g+1] = ll;
        }
    }
}

// ---------------------------------------------------------------------------
// Fused residual + LayerNorm : h = LN(h + add) ; writes fp32 + split bf16
// ---------------------------------------------------------------------------
__global__ __launch_bounds__(256) void ln_kernel(const float* __restrict__ add,
                                                 const float* __restrict__ gam,
                                                 const float* __restrict__ bet) {
    int warp = threadIdx.x >> 5, lane = threadIdx.x & 31;
    int token = blockIdx.x * 8 + warp;
    const float* hp = &g_h[(size_t)token*Dd];
    const float* ap = &add[(size_t)token*Dd];
    float x[8], s = 0.f;
    #pragma unroll
    for (int j = 0; j < 8; j++) { x[j] = hp[lane*8 + j] + ap[lane*8 + j]; s += x[j]; }
    #pragma unroll
    for (int o = 16; o; o >>= 1) s += __shfl_xor_sync(~0u, s, o);
    float mean = s * (1.f/256.f);
    float v = 0.f;
    #pragma unroll
    for (int j = 0; j < 8; j++) { float d = x[j] - mean; v += d*d; }
    #pragma unroll
    for (int o = 16; o; o >>= 1) v += __shfl_xor_sync(~0u, v, o);
    float rstd = rsqrtf(v * (1.f/256.f) + EPSLN);
    float* op = &g_h[(size_t)token*Dd];
    #pragma unroll
    for (int j = 0; j < 8; j++) {
        int cix = lane*8 + j;
        float y = (x[j] - mean)*rstd*gam[cix] + bet[cix];
        op[cix] = y;
        size_t ix = (size_t)token*Dd + cix;
        __nv_bfloat16 hh, ll;
        fsplit(y, hh, ll);
        g_hhi[ix] = hh;
        g_hlo[ix] = ll;
    }
}

// ---------------------------------------------------------------------------
// Final head tail: out = relu_h(g_tmp fp32) @ o2w + o2b   (warp per token)
// ---------------------------------------------------------------------------
__global__ __launch_bounds__(256) void head2_kernel(const float* __restrict__ o2w,
                                                    const float* __restrict__ o2b,
                                                    float* __restrict__ out) {
    int warp = threadIdx.x >> 5, lane = threadIdx.x & 31;
    int token = blockIdx.x * 8 + warp;
    const float* hp = &g_tmp[(size_t)token*Dd];
    float a0 = 0.f, a1 = 0.f;
    #pragma unroll
    for (int j = 0; j < 8; j++) {
        int k = lane + j*32;
        float hv = hp[k];
        a0 = fmaf(hv, o2w[k*2],   a0);
        a1 = fmaf(hv, o2w[k*2+1], a1);
    }
    #pragma unroll
    for (int o = 16; o; o >>= 1) {
        a0 += __shfl_xor_sync(~0u, a0, o);
        a1 += __shfl_xor_sync(~0u, a1, o);
    }
    if (lane == 0) {
        out[(size_t)token*2]     = a0 + o2b[0];
        out[(size_t)token*2 + 1] = a1 + o2b[1];
    }
}

// ---------------------------------------------------------------------------
// Host orchestration
// ---------------------------------------------------------------------------
static inline void* symaddr(const void* s) {
    void* p = nullptr;
    cudaGetSymbolAddress(&p, s);
    return p;
}

extern "C" void kernel_launch(void* const* d_in, const int* in_sizes, int n_in,
                              void* d_out, int out_size) {
    const float* x    = (const float*)d_in[0];
    const float* in_w = (const float*)d_in[1];
    const float* in_b = (const float*)d_in[2];
    const float* qw   = (const float*)d_in[3];
    const float* qb   = (const float*)d_in[4];
    const float* kw   = (const float*)d_in[5];
    const float* kb   = (const float*)d_in[6];
    const float* vw   = (const float*)d_in[7];
    const float* vb   = (const float*)d_in[8];
    const float* ow   = (const float*)d_in[9];
    const float* ob   = (const float*)d_in[10];
    const float* f1w  = (const float*)d_in[11];
    const float* f1b  = (const float*)d_in[12];
    const float* f2w  = (const float*)d_in[13];
    const float* f2b  = (const float*)d_in[14];
    const float* n1g  = (const float*)d_in[15];
    const float* n1b  = (const float*)d_in[16];
    const float* n2g  = (const float*)d_in[17];
    const float* n2b  = (const float*)d_in[18];
    const float* o1w  = (const float*)d_in[19];
    const float* o1b  = (const float*)d_in[20];
    const float* o2w  = (const float*)d_in[21];
    const float* o2b  = (const float*)d_in[22];

    float* outp     = (float*)d_out;
    float* attn_out = outp + (size_t)Bd*Ld*2;

    __nv_bfloat16* p_hh   = (__nv_bfloat16*)symaddr(g_hhi);
    __nv_bfloat16* p_hl   = (__nv_bfloat16*)symaddr(g_hlo);
    __nv_bfloat16* p_qkvh = (__nv_bfloat16*)symaddr(g_qkvh);
    __nv_bfloat16* p_qkvl = (__nv_bfloat16*)symaddr(g_qkvl);
    __nv_bfloat16* p_oh   = (__nv_bfloat16*)symaddr(g_ohi);
    __nv_bfloat16* p_ol   = (__nv_bfloat16*)symaddr(g_olo);
    __nv_bfloat16* p_fh   = (__nv_bfloat16*)symaddr(g_fhi);
    __nv_bfloat16* p_fl   = (__nv_bfloat16*)symaddr(g_flo);
    float*         p_tmp  = (float*)symaddr(g_tmp);
    __nv_bfloat16* p_owh  = (__nv_bfloat16*)symaddr(g_owh);
    __nv_bfloat16* p_owl  = (__nv_bfloat16*)symaddr(g_owl);
    __nv_bfloat16* p_f1h  = (__nv_bfloat16*)symaddr(g_f1wh);
    __nv_bfloat16* p_f1l  = (__nv_bfloat16*)symaddr(g_f1wl);
    __nv_bfloat16* p_f2h  = (__nv_bfloat16*)symaddr(g_f2wh);
    __nv_bfloat16* p_f2l  = (__nv_bfloat16*)symaddr(g_f2wl);
    __nv_bfloat16* p_o1h  = (__nv_bfloat16*)symaddr(g_o1wh);
    __nv_bfloat16* p_o1l  = (__nv_bfloat16*)symaddr(g_o1wl);

    const int SM_G256 = 384*(256+8)*2;   // 202752
    const int SM_G128 = 384*(128+8)*2;   // 104448
    const int SM_G64  = 384*(64+8)*2;    // 55296
    const int SM_ATTN = (2*128*40 + 2*128*40 + 2*32*136) * 2;  // 58368

    cudaFuncSetAttribute(gemm_qkv, cudaFuncAttributeMaxDynamicSharedMemorySize, SM_G256);
    cudaFuncSetAttribute(gemm_bias<256,true ,false,true >, cudaFuncAttributeMaxDynamicSharedMemorySize, SM_G256);
    cudaFuncSetAttribute(gemm_bias<256,false,true ,true >, cudaFuncAttributeMaxDynamicSharedMemorySize, SM_G256);
    cudaFuncSetAttribute(gemm_bias<128,false,true ,false>, cudaFuncAttributeMaxDynamicSharedMemorySize, SM_G128);
    cudaFuncSetAttribute(gemm_bias<64 ,false,true ,false>, cudaFuncAttributeMaxDynamicSharedMemorySize, SM_G64);
    cudaFuncSetAttribute(attn_kernel, cudaFuncAttributeMaxDynamicSharedMemorySize, SM_ATTN);

    convert_w<<<384, 256>>>(qw, kw, vw, ow, f1w, f2w, o1w, qb, kb, vb);
    embed_kernel<<<BLd, Dd>>>(x, in_w, in_b);

    const dim3 gQKV (BLd/128, 6);
    const dim3 gProj(BLd/128, 4);   // N=256
    const dim3 gF1  (BLd/128, 1);   // N=64
    const dim3 gAttn((Ld + 127)/128, Bd*Hd);

    for (int i = 0; i < NLd; i++) {
        gemm_qkv<<<gQKV, 512, SM_G256>>>(i);

        attn_kernel<<<gAttn, 256, SM_ATTN>>>(
            p_qkvh, p_qkvl,
            attn_out + (size_t)i*Bd*Hd*Ld*Ld, p_oh, p_ol);

        gemm_bias<128,false,true,false><<<gProj, 512, SM_G128>>>(
            p_oh, p_ol, p_owh + (size_t)i*128*Dd, p_owl + (size_t)i*128*Dd,
            ob + i*Dd, p_tmp, nullptr, nullptr, Dd);
        ln_kernel<<<BLd/8, 256>>>(p_tmp, n1g + i*Dd, n1b + i*Dd);

        gemm_bias<256,true,false,true><<<gF1, 512, SM_G256>>>(
            p_hh, p_hl, p_f1h + (size_t)i*Dd*FCd, p_f1l + (size_t)i*Dd*FCd,
            f1b + i*FCd, nullptr, p_fh, p_fl, FCd);
        gemm_bias<64,false,true,false><<<gProj, 512, SM_G64>>>(
            p_fh, p_fl, p_f2h + (size_t)i*FCd*Dd, p_f2l + (size_t)i*FCd*Dd,
            f2b + i*Dd, p_tmp, nullptr, nullptr, Dd);
        ln_kernel<<<BLd/8, 256>>>(p_tmp, n2g + i*Dd, n2b + i*Dd);
    }

    gemm_bias<256,false,true,true><<<gProj, 512, SM_G256>>>(
        p_hh, p_hl, p_o1h, p_o1l, o1b, p_tmp, nullptr, nullptr, Dd);
    head2_kernel<<<BLd/8, 256>>>(o2w, o2b, outp);
}

// round 5
// speedup vs baseline: 3.9829x; 1.1934x over previous
#include <cuda_runtime.h>
#include <cuda_bf16.h>
#include <stdint.h>

#define Bd  8
#define Ld  2016
#define Hd  4
#define DKd 32
#define Dd  256
#define FCd 64
#define NLd 3
#define BLd (Bd*Ld)          // 16128 tokens

#define SC2f 0.09016844005556f   // (1/sqrt(256)) * log2(e)
#define EPSLN 1e-5f

// ---------------------------------------------------------------------------
// Device scratch (no allocation allowed). hi/lo split bf16 pairs everywhere.
// ---------------------------------------------------------------------------
__device__ __align__(128) float          g_h    [BLd*Dd];
__device__ __align__(128) __nv_bfloat16  g_hhi  [BLd*Dd];
__device__ __align__(128) __nv_bfloat16  g_hlo  [BLd*Dd];
__device__ __align__(128) __nv_bfloat16  g_qkvh [3*BLd*128];
__device__ __align__(128) __nv_bfloat16  g_qkvl [3*BLd*128];
__device__ __align__(128) __nv_bfloat16  g_ohi  [BLd*128];
__device__ __align__(128) __nv_bfloat16  g_olo  [BLd*128];
__device__ __align__(128) float          g_tmp  [BLd*Dd];
__device__ __align__(128) __nv_bfloat16  g_fhi  [BLd*FCd];
__device__ __align__(128) __nv_bfloat16  g_flo  [BLd*FCd];
// split weights
__device__ __align__(128) __nv_bfloat16  g_qkvwh[NLd*3*Dd*128];
__device__ __align__(128) __nv_bfloat16  g_qkvwl[NLd*3*Dd*128];
__device__ __align__(128) float          g_qkvb [NLd*3*128];
__device__ __align__(128) __nv_bfloat16  g_owh  [NLd*128*Dd];
__device__ __align__(128) __nv_bfloat16  g_owl  [NLd*128*Dd];
__device__ __align__(128) __nv_bfloat16  g_f1wh [NLd*Dd*FCd];
__device__ __align__(128) __nv_bfloat16  g_f1wl [NLd*Dd*FCd];
__device__ __align__(128) __nv_bfloat16  g_f2wh [NLd*FCd*Dd];
__device__ __align__(128) __nv_bfloat16  g_f2wl [NLd*FCd*Dd];
__device__ __align__(128) __nv_bfloat16  g_o1wh [Dd*Dd];
__device__ __align__(128) __nv_bfloat16  g_o1wl [Dd*Dd];

// ---------------------------------------------------------------------------
// helpers
// ---------------------------------------------------------------------------
__device__ __forceinline__ void mma16816(float* d, const uint32_t* a,
                                         uint32_t b0, uint32_t b1) {
    asm volatile(
        "mma.sync.aligned.m16n8k16.row.col.f32.bf16.bf16.f32 "
        "{%0,%1,%2,%3}, {%4,%5,%6,%7}, {%8,%9}, {%0,%1,%2,%3};"
        : "+f"(d[0]), "+f"(d[1]), "+f"(d[2]), "+f"(d[3])
        : "r"(a[0]), "r"(a[1]), "r"(a[2]), "r"(a[3]), "r"(b0), "r"(b1));
}

__device__ __forceinline__ float ex2(float x) {
    float y;
    asm("ex2.approx.ftz.f32 %0, %1;" : "=f"(y) : "f"(x));
    return y;
}

__device__ __forceinline__ uint32_t pk2(float x, float y) {
    __nv_bfloat162 t = __floats2bfloat162_rn(x, y);
    return *reinterpret_cast<uint32_t*>(&t);
}

__device__ __forceinline__ void fsplit(float v, __nv_bfloat16& hi, __nv_bfloat16& lo) {
    hi = __float2bfloat16(v);
    lo = __float2bfloat16(v - __bfloat162float(hi));
}

__device__ __forceinline__ void pksplit(float x, float y, uint32_t& hi, uint32_t& lo) {
    __nv_bfloat16 xh = __float2bfloat16(x), yh = __float2bfloat16(y);
    __nv_bfloat162 th; th.x = xh; th.y = yh;
    hi = *reinterpret_cast<uint32_t*>(&th);
    lo = pk2(x - __bfloat162float(xh), y - __bfloat162float(yh));
}

__device__ __forceinline__ void stcs2(float* p, float a, float b) {
    asm volatile("st.global.cs.v2.f32 [%0], {%1,%2};" :: "l"(p), "f"(a), "f"(b));
}

// ---------------------------------------------------------------------------
// Weight conversion fp32 -> bf16 hi/lo (+ QKV packing)
// ---------------------------------------------------------------------------
__global__ void convert_w(const float* __restrict__ qw, const float* __restrict__ kw,
                          const float* __restrict__ vw, const float* __restrict__ ow,
                          const float* __restrict__ f1w, const float* __restrict__ f2w,
                          const float* __restrict__ o1w,
                          const float* __restrict__ qb, const float* __restrict__ kb,
                          const float* __restrict__ vb) {
    int i = blockIdx.x * 256 + threadIdx.x;
    const int n1 = NLd*Dd*128;
    const int n3 = NLd*Dd*FCd;
    const int n5 = Dd*Dd;
    if (i < n1) {
        int l = i / (Dd*128), rem = i % (Dd*128);
        size_t b = (size_t)(l*3)*Dd*128 + rem;
        fsplit(qw[i], g_qkvwh[b],            g_qkvwl[b]);
        fsplit(kw[i], g_qkvwh[b + Dd*128],   g_qkvwl[b + Dd*128]);
        fsplit(vw[i], g_qkvwh[b + 2*Dd*128], g_qkvwl[b + 2*Dd*128]);
        fsplit(ow[i], g_owh[i], g_owl[i]);
    }
    if (i < n3) {
        fsplit(f1w[i], g_f1wh[i], g_f1wl[i]);
        fsplit(f2w[i], g_f2wh[i], g_f2wl[i]);
    }
    if (i < n5) fsplit(o1w[i], g_o1wh[i], g_o1wl[i]);
    if (i < NLd*128) {
        int l = i >> 7, n = i & 127;
        g_qkvb[(l*3+0)*128 + n] = qb[i];
        g_qkvb[(l*3+1)*128 + n] = kb[i];
        g_qkvb[(l*3+2)*128 + n] = vb[i];
    }
}

// ---------------------------------------------------------------------------
// Embed: h = x @ in_w + in_b (fp32 + split)
// ---------------------------------------------------------------------------
__global__ void embed_kernel(const float* __restrict__ x,
                             const float* __restrict__ in_w,
                             const float* __restrict__ in_b) {
    int t = blockIdx.x, d = threadIdx.x;
    float x0 = x[t*2], x1 = x[t*2+1];
    float v = fmaf(x0, in_w[d], fmaf(x1, in_w[Dd + d], in_b[d]));
    size_t ix = (size_t)t*Dd + d;
    g_h[ix] = v;
    fsplit(v, g_hhi[ix], g_hlo[ix]);
}

// ---------------------------------------------------------------------------
// GEMM core: tile 128x64, 512 threads (16 warps: 8 M x 2 N). 3-term split MMA.
// ---------------------------------------------------------------------------
template<int K, bool OUT_B16, bool OUT_F32, bool RELU>
__device__ __forceinline__ void gemm_body(
        const __nv_bfloat16* __restrict__ Ahi,
        const __nv_bfloat16* __restrict__ Alo,
        const __nv_bfloat16* __restrict__ Whi,
        const __nv_bfloat16* __restrict__ Wlo,
        const float* __restrict__ bias,
        float* __restrict__ outF,
        __nv_bfloat16* __restrict__ outBh,
        __nv_bfloat16* __restrict__ outBl,
        int N, int row0, int col0) {
    extern __shared__ __nv_bfloat16 sm[];
    constexpr int SA = K + 8;
    __nv_bfloat16* sAh = sm;
    __nv_bfloat16* sAl = sm + 128 * SA;
    __nv_bfloat16* sWh = sm + 256 * SA;
    __nv_bfloat16* sWl = sWh + 64 * SA;

    const int tid = threadIdx.x, lane = tid & 31, warp = tid >> 5;

    constexpr int AV = K / 8;
    #pragma unroll 2
    for (int i = tid; i < 128 * AV; i += 512) {
        int r = i / AV, c = (i % AV) * 8;
        size_t g = (size_t)(row0 + r)*K + c;
        *reinterpret_cast<uint4*>(&sAh[r*SA + c]) = *reinterpret_cast<const uint4*>(&Ahi[g]);
        *reinterpret_cast<uint4*>(&sAl[r*SA + c]) = *reinterpret_cast<const uint4*>(&Alo[g]);
    }
    #pragma unroll 2
    for (int i = tid; i < 64 * K / 4; i += 512) {
        int k = i >> 4, n4 = (i & 15) * 4;
        size_t g = (size_t)k*N + col0 + n4;
        uint2 wh = *reinterpret_cast<const uint2*>(&Whi[g]);
        uint2 wl = *reinterpret_cast<const uint2*>(&Wlo[g]);
        __nv_bfloat16 th[4]; *reinterpret_cast<uint2*>(th) = wh;
        __nv_bfloat16 tl[4]; *reinterpret_cast<uint2*>(tl) = wl;
        #pragma unroll
        for (int j = 0; j < 4; j++) {
            sWh[(n4+j)*SA + k] = th[j];
            sWl[(n4+j)*SA + k] = tl[j];
        }
    }
    __syncthreads();

    float acc[4][4];
    #pragma unroll
    for (int i = 0; i < 4; i++)
        #pragma unroll
        for (int j = 0; j < 4; j++) acc[i][j] = 0.f;

    const int mwarp = warp >> 1, nwarp = warp & 1;
    const int ar = mwarp*16 + (lane >> 2);
    const int ac = (lane & 3) * 2;
    #pragma unroll
    for (int kk = 0; kk < K/16; kk++) {
        uint32_t ah[4], al[4];
        {
            const __nv_bfloat16* pa = &sAh[ar*SA + kk*16 + ac];
            ah[0] = *(const uint32_t*)pa;
            ah[1] = *(const uint32_t*)(pa + 8*SA);
            ah[2] = *(const uint32_t*)(pa + 8);
            ah[3] = *(const uint32_t*)(pa + 8*SA + 8);
            const __nv_bfloat16* pl = &sAl[ar*SA + kk*16 + ac];
            al[0] = *(const uint32_t*)pl;
            al[1] = *(const uint32_t*)(pl + 8*SA);
            al[2] = *(const uint32_t*)(pl + 8);
            al[3] = *(const uint32_t*)(pl + 8*SA + 8);
        }
        #pragma unroll
        for (int nt = 0; nt < 4; nt++) {
            int nrow = nwarp*32 + nt*8 + (lane>>2);
            const __nv_bfloat16* pbh = &sWh[nrow*SA + kk*16 + ac];
            uint32_t bh0 = *(const uint32_t*)pbh;
            uint32_t bh1 = *(const uint32_t*)(pbh + 8);
            const __nv_bfloat16* pbl = &sWl[nrow*SA + kk*16 + ac];
            uint32_t bl0 = *(const uint32_t*)pbl;
            uint32_t bl1 = *(const uint32_t*)(pbl + 8);
            mma16816(acc[nt], ah, bh0, bh1);
            mma16816(acc[nt], al, bh0, bh1);
            mma16816(acc[nt], ah, bl0, bl1);
        }
    }

    const int orow = row0 + mwarp*16 + (lane >> 2);
    #pragma unroll
    for (int nt = 0; nt < 4; nt++) {
        int c = col0 + nwarp*32 + nt*8 + (lane & 3)*2;
        float b0v = bias[c], b1v = bias[c+1];
        #pragma unroll
        for (int half = 0; half < 2; half++) {
            int r = orow + half*8;
            float v0 = acc[nt][half*2+0] + b0v;
            float v1 = acc[nt][half*2+1] + b1v;
            if (RELU) { v0 = fmaxf(v0, 0.f); v1 = fmaxf(v1, 0.f); }
            size_t o = (size_t)r*N + c;
            if (OUT_F32) { outF[o] = v0; outF[o+1] = v1; }
            if (OUT_B16) {
                __nv_bfloat16 h0, l0, h1, l1;
                fsplit(v0, h0, l0);
                fsplit(v1, h1, l1);
                outBh[o] = h0; outBh[o+1] = h1;
                outBl[o] = l0; outBl[o+1] = l1;
            }
        }
    }
}

template<int K, bool OUT_B16, bool OUT_F32, bool RELU>
__global__ __launch_bounds__(512) void gemm_bias(
        const __nv_bfloat16* __restrict__ Ahi, const __nv_bfloat16* __restrict__ Alo,
        const __nv_bfloat16* __restrict__ Whi, const __nv_bfloat16* __restrict__ Wlo,
        const float* __restrict__ bias,
        float* __restrict__ outF,
        __nv_bfloat16* __restrict__ outBh, __nv_bfloat16* __restrict__ outBl,
        int N) {
    gemm_body<K, OUT_B16, OUT_F32, RELU>(Ahi, Alo, Whi, Wlo, bias, outF, outBh, outBl,
                                         N, blockIdx.x*128, blockIdx.y*64);
}

// Fused QKV: grid (126, 6); blockIdx.y selects (q/k/v, col-half)
__global__ __launch_bounds__(512) void gemm_qkv(int layer) {
    int sel = blockIdx.y >> 1;
    int col0 = (blockIdx.y & 1) * 64;
    const __nv_bfloat16* Whi = g_qkvwh + ((size_t)(layer*3 + sel))*Dd*128;
    const __nv_bfloat16* Wlo = g_qkvwl + ((size_t)(layer*3 + sel))*Dd*128;
    const float* bias = g_qkvb + (layer*3 + sel)*128;
    __nv_bfloat16* oh = g_qkvh + (size_t)sel*BLd*128;
    __nv_bfloat16* ol = g_qkvl + (size_t)sel*BLd*128;
    gemm_body<256, true, false, false>(g_hhi, g_hlo, Whi, Wlo, bias, nullptr, oh, ol,
                                       128, blockIdx.x*128, col0);
}

// ---------------------------------------------------------------------------
// Attention v2: 256-query tile / CTA, 512 threads (16 warps x 16 rows),
// 256-key chunks. Two passes, m=0 (scores tiny => exact), ex2-folded scale.
// Pass A: row sums. Pass B: recompute S, P=ex2(s)/sum -> gmem (.cs) + PV.
// 3-term split MMA for QK & PV; pass-B QK uses dual accumulators for ILP.
// ---------------------------------------------------------------------------
#define QT 256          // query tile
#define KT 256          // key chunk
#define NCH 8           // 2048 / KT

// smem offsets in bf16 units
#define SQH 0
#define SQL 10240
#define SKH 20480
#define SKL 30720
#define SVH 40960       // [32][264] transposed
#define SVL 49408
#define SM_ATTN_BYTES ((57856)*2)

template<bool MASK>
__device__ __forceinline__ void qk_stats_chunk(
        const __nv_bfloat16* sKh, const __nv_bfloat16* sKl,
        const uint32_t aqh[2][4], const uint32_t aql[2][4],
        int k0, int fr, int fc, float& s0, float& s1) {
    #pragma unroll 1
    for (int gq = 0; gq < 8; gq++) {
        float acc[4][4];
        #pragma unroll
        for (int i = 0; i < 4; i++)
            #pragma unroll
            for (int j = 0; j < 4; j++) acc[i][j] = 0.f;
        #pragma unroll
        for (int nt = 0; nt < 4; nt++) {
            int nrow = gq*32 + nt*8 + fr;
            #pragma unroll
            for (int kk = 0; kk < 2; kk++) {
                const __nv_bfloat16* pbh = &sKh[nrow*40 + kk*16 + fc];
                uint32_t bh0 = *(const uint32_t*)pbh;
                uint32_t bh1 = *(const uint32_t*)(pbh + 8);
                const __nv_bfloat16* pbl = &sKl[nrow*40 + kk*16 + fc];
                uint32_t bl0 = *(const uint32_t*)pbl;
                uint32_t bl1 = *(const uint32_t*)(pbl + 8);
                mma16816(acc[nt], aqh[kk], bh0, bh1);
                mma16816(acc[nt], aql[kk], bh0, bh1);
                mma16816(acc[nt], aqh[kk], bl0, bl1);
            }
        }
        #pragma unroll
        for (int nt = 0; nt < 4; nt++) {
            float e0, e1, e2, e3;
            if (MASK) {
                int col = k0 + gq*32 + nt*8 + fc;
                bool ok = (col < Ld);
                e0 = ok ? ex2(acc[nt][0]*SC2f) : 0.f;
                e1 = ok ? ex2(acc[nt][1]*SC2f) : 0.f;
                e2 = ok ? ex2(acc[nt][2]*SC2f) : 0.f;
                e3 = ok ? ex2(acc[nt][3]*SC2f) : 0.f;
            } else {
                e0 = ex2(acc[nt][0]*SC2f);
                e1 = ex2(acc[nt][1]*SC2f);
                e2 = ex2(acc[nt][2]*SC2f);
                e3 = ex2(acc[nt][3]*SC2f);
            }
            s0 += e0 + e1;
            s1 += e2 + e3;
        }
    }
}

template<bool MASK>
__device__ __forceinline__ void qk_emit_chunk(
        const __nv_bfloat16* sKh, const __nv_bfloat16* sKl,
        const __nv_bfloat16* sVh, const __nv_bfloat16* sVl,
        const uint32_t aqh[2][4], const uint32_t aql[2][4],
        int k0, int fr, int fc, float inv0, float inv1,
        float* prow0, float* prow1, bool wr0, bool wr1,
        float oacc[4][4]) {
    #pragma unroll 1
    for (int g = 0; g < 16; g++) {
        float acc1[2][4], acc2[2][4];
        #pragma unroll
        for (int i = 0; i < 2; i++)
            #pragma unroll
            for (int j = 0; j < 4; j++) { acc1[i][j] = 0.f; acc2[i][j] = 0.f; }
        #pragma unroll
        for (int nt = 0; nt < 2; nt++) {
            int nrow = g*16 + nt*8 + fr;
            #pragma unroll
            for (int kk = 0; kk < 2; kk++) {
                const __nv_bfloat16* pbh = &sKh[nrow*40 + kk*16 + fc];
                uint32_t bh0 = *(const uint32_t*)pbh;
                uint32_t bh1 = *(const uint32_t*)(pbh + 8);
                const __nv_bfloat16* pbl = &sKl[nrow*40 + kk*16 + fc];
                uint32_t bl0 = *(const uint32_t*)pbl;
                uint32_t bl1 = *(const uint32_t*)(pbl + 8);
                mma16816(acc1[nt], aqh[kk], bh0, bh1);
                mma16816(acc2[nt], aql[kk], bh0, bh1);
                mma16816(acc2[nt], aqh[kk], bl0, bl1);
            }
        }
        int colb = k0 + g*16 + fc;
        bool ok0 = !MASK || (colb < Ld);
        bool ok1 = !MASK || (colb + 8 < Ld);
        float p00 = ok0 ? ex2((acc1[0][0]+acc2[0][0])*SC2f)*inv0 : 0.f;
        float p01 = ok0 ? ex2((acc1[0][1]+acc2[0][1])*SC2f)*inv0 : 0.f;
        float p02 = ok0 ? ex2((acc1[0][2]+acc2[0][2])*SC2f)*inv1 : 0.f;
        float p03 = ok0 ? ex2((acc1[0][3]+acc2[0][3])*SC2f)*inv1 : 0.f;
        float p10 = ok1 ? ex2((acc1[1][0]+acc2[1][0])*SC2f)*inv0 : 0.f;
        float p11 = ok1 ? ex2((acc1[1][1]+acc2[1][1])*SC2f)*inv0 : 0.f;
        float p12 = ok1 ? ex2((acc1[1][2]+acc2[1][2])*SC2f)*inv1 : 0.f;
        float p13 = ok1 ? ex2((acc1[1][3]+acc2[1][3])*SC2f)*inv1 : 0.f;

        if (wr0) {
            if (ok0) stcs2(&prow0[colb],     p00, p01);
            if (ok1) stcs2(&prow0[colb + 8], p10, p11);
        }
        if (wr1) {
            if (ok0) stcs2(&prow1[colb],     p02, p03);
            if (ok1) stcs2(&prow1[colb + 8], p12, p13);
        }

        uint32_t ah[4], al[4];
        pksplit(p00, p01, ah[0], al[0]);
        pksplit(p02, p03, ah[1], al[1]);
        pksplit(p10, p11, ah[2], al[2]);
        pksplit(p12, p13, ah[3], al[3]);

        #pragma unroll
        for (int dt = 0; dt < 4; dt++) {
            int nd = dt*8 + fr;
            const __nv_bfloat16* pbh = &sVh[nd*264 + g*16 + fc];
            uint32_t bh0 = *(const uint32_t*)pbh;
            uint32_t bh1 = *(const uint32_t*)(pbh + 8);
            const __nv_bfloat16* pbl = &sVl[nd*264 + g*16 + fc];
            uint32_t bl0 = *(const uint32_t*)pbl;
            uint32_t bl1 = *(const uint32_t*)(pbl + 8);
            mma16816(oacc[dt], ah, bh0, bh1);
            mma16816(oacc[dt], al, bh0, bh1);
            mma16816(oacc[dt], ah, bl0, bl1);
        }
    }
}

__global__ __launch_bounds__(512, 1) void attn_kernel(
        const __nv_bfloat16* __restrict__ qkvh,
        const __nv_bfloat16* __restrict__ qkvl,
        float* __restrict__ Pout,
        __nv_bfloat16* __restrict__ Oh, __nv_bfloat16* __restrict__ Ol) {
    extern __shared__ __nv_bfloat16 sm[];
    __nv_bfloat16* sQh = sm + SQH;
    __nv_bfloat16* sQl = sm + SQL;
    __nv_bfloat16* sKh = sm + SKH;
    __nv_bfloat16* sKl = sm + SKL;
    __nv_bfloat16* sVh = sm + SVH;
    __nv_bfloat16* sVl = sm + SVL;

    const int tid = threadIdx.x, lane = tid & 31, warp = tid >> 5;
    const int bh = blockIdx.y;
    const int b  = bh >> 2, h = bh & 3;
    const int q0 = blockIdx.x * QT;
    const size_t base = ((size_t)b*Ld*Hd + h)*DKd;
    const __nv_bfloat16* Qh = qkvh;
    const __nv_bfloat16* Ql = qkvl;
    const __nv_bfloat16* Kh = qkvh + (size_t)BLd*128;
    const __nv_bfloat16* Kl = qkvl + (size_t)BLd*128;
    const __nv_bfloat16* Vh = qkvh + (size_t)2*BLd*128;
    const __nv_bfloat16* Vl = qkvl + (size_t)2*BLd*128;

    // ---- Q tile (zero-padded) ----
    for (int i = tid; i < QT*16; i += 512) {
        int r = i >> 4, d2 = (i & 15) * 2;
        int row = q0 + r;
        uint32_t vh = 0, vl = 0;
        if (row < Ld) {
            size_t g = base + (size_t)row*128 + d2;
            vh = *(const uint32_t*)&Qh[g];
            vl = *(const uint32_t*)&Ql[g];
        }
        *(uint32_t*)&sQh[r*40 + d2] = vh;
        *(uint32_t*)&sQl[r*40 + d2] = vl;
    }
    __syncthreads();

    const int mrow = warp * 16;
    const int fr = lane >> 2, fc = (lane & 3) * 2;
    uint32_t aqh[2][4], aql[2][4];
    #pragma unroll
    for (int kk = 0; kk < 2; kk++) {
        const __nv_bfloat16* p = &sQh[(mrow + fr)*40 + kk*16 + fc];
        aqh[kk][0] = *(const uint32_t*)p;
        aqh[kk][1] = *(const uint32_t*)(p + 8*40);
        aqh[kk][2] = *(const uint32_t*)(p + 8);
        aqh[kk][3] = *(const uint32_t*)(p + 8*40 + 8);
        const __nv_bfloat16* pl = &sQl[(mrow + fr)*40 + kk*16 + fc];
        aql[kk][0] = *(const uint32_t*)pl;
        aql[kk][1] = *(const uint32_t*)(pl + 8*40);
        aql[kk][2] = *(const uint32_t*)(pl + 8);
        aql[kk][3] = *(const uint32_t*)(pl + 8*40 + 8);
    }

    float s0 = 0.f, s1 = 0.f;

    // ================= PASS A: row sums =================
    for (int ch = 0; ch < NCH; ch++) {
        const int k0 = ch * KT;
        __syncthreads();
        if (ch < NCH-1) {
            for (int i = tid; i < KT*16; i += 512) {
                int r = i >> 4, d2 = (i & 15) * 2;
                size_t g = base + (size_t)(k0 + r)*128 + d2;
                *(uint32_t*)&sKh[r*40 + d2] = *(const uint32_t*)&Kh[g];
                *(uint32_t*)&sKl[r*40 + d2] = *(const uint32_t*)&Kl[g];
            }
        } else {
            for (int i = tid; i < KT*16; i += 512) {
                int r = i >> 4, d2 = (i & 15) * 2;
                int s = k0 + r;
                uint32_t vh = 0, vl = 0;
                if (s < Ld) {
                    size_t g = base + (size_t)s*128 + d2;
                    vh = *(const uint32_t*)&Kh[g];
                    vl = *(const uint32_t*)&Kl[g];
                }
                *(uint32_t*)&sKh[r*40 + d2] = vh;
                *(uint32_t*)&sKl[r*40 + d2] = vl;
            }
        }
        __syncthreads();
        if (ch < NCH-1)
            qk_stats_chunk<false>(sKh, sKl, aqh, aql, k0, fr, fc, s0, s1);
        else
            qk_stats_chunk<true >(sKh, sKl, aqh, aql, k0, fr, fc, s0, s1);
    }

    // quad reduce sums (lanes in a quad cover complementary columns)
    s0 += __shfl_xor_sync(~0u, s0, 1);
    s0 += __shfl_xor_sync(~0u, s0, 2);
    s1 += __shfl_xor_sync(~0u, s1, 1);
    s1 += __shfl_xor_sync(~0u, s1, 2);
    const float inv0 = 1.f / s0, inv1 = 1.f / s1;

    // ================= PASS B: P out + PV =================
    float oacc[4][4];
    #pragma unroll
    for (int i = 0; i < 4; i++)
        #pragma unroll
        for (int j = 0; j < 4; j++) oacc[i][j] = 0.f;

    const int grow0 = q0 + mrow + fr;
    float* prow0 = &Pout[((size_t)bh*Ld + grow0)*Ld];
    float* prow1 = prow0 + 8*(size_t)Ld;
    const bool wr0 = (grow0 < Ld), wr1 = (grow0 + 8 < Ld);

    for (int ch = 0; ch < NCH; ch++) {
        const int k0 = ch * KT;
        __syncthreads();
        if (ch < NCH-1) {
            for (int i = tid; i < KT*16; i += 512) {
                int r = i >> 4, d2 = (i & 15) * 2;
                size_t g = base + (size_t)(k0 + r)*128 + d2;
                *(uint32_t*)&sKh[r*40 + d2] = *(const uint32_t*)&Kh[g];
                *(uint32_t*)&sKl[r*40 + d2] = *(const uint32_t*)&Kl[g];
            }
            for (int i = tid; i < KT*16; i += 512) {
                int s = i >> 4, d2 = (i & 15) * 2;
                size_t g = base + (size_t)(k0 + s)*128 + d2;
                uint32_t vh = *(const uint32_t*)&Vh[g];
                uint32_t vl = *(const uint32_t*)&Vl[g];
                __nv_bfloat162 h2 = *reinterpret_cast<__nv_bfloat162*>(&vh);
                __nv_bfloat162 l2 = *reinterpret_cast<__nv_bfloat162*>(&vl);
                sVh[ d2   *264 + s] = h2.x;
                sVh[(d2+1)*264 + s] = h2.y;
                sVl[ d2   *264 + s] = l2.x;
                sVl[(d2+1)*264 + s] = l2.y;
            }
        } else {
            for (int i = tid; i < KT*16; i += 512) {
                int r = i >> 4, d2 = (i & 15) * 2;
                int s = k0 + r;
                uint32_t vh = 0, vl = 0;
                if (s < Ld) {
                    size_t g = base + (size_t)s*128 + d2;
                    vh = *(const uint32_t*)&Kh[g];
                    vl = *(const uint32_t*)&Kl[g];
                }
                *(uint32_t*)&sKh[r*40 + d2] = vh;
                *(uint32_t*)&sKl[r*40 + d2] = vl;
            }
            for (int i = tid; i < KT*16; i += 512) {
                int s = i >> 4, d2 = (i & 15) * 2;
                int sg = k0 + s;
                uint32_t vh = 0, vl = 0;
                if (sg < Ld) {
                    size_t g = base + (size_t)sg*128 + d2;
                    vh = *(const uint32_t*)&Vh[g];
                    vl = *(const uint32_t*)&Vl[g];
                }
                __nv_bfloat162 h2 = *reinterpret_cast<__nv_bfloat162*>(&vh);
                __nv_bfloat162 l2 = *reinterpret_cast<__nv_bfloat162*>(&vl);
                sVh[ d2   *264 + s] = h2.x;
                sVh[(d2+1)*264 + s] = h2.y;
                sVl[ d2   *264 + s] = l2.x;
                sVl[(d2+1)*264 + s] = l2.y;
            }
        }
        __syncthreads();
        if (ch < NCH-1)
            qk_emit_chunk<false>(sKh, sKl, sVh, sVl, aqh, aql, k0, fr, fc,
                                 inv0, inv1, prow0, prow1, wr0, wr1, oacc);
        else
            qk_emit_chunk<true >(sKh, sKl, sVh, sVl, aqh, aql, k0, fr, fc,
                                 inv0, inv1, prow0, prow1, wr0, wr1, oacc);
    }

    // ---- write O (hi/lo) ----
    #pragma unroll
    for (int dt = 0; dt < 4; dt++) {
        int d = dt*8 + fc;
        if (wr0) {
            size_t g = base + (size_t)grow0*128 + d;
            __nv_bfloat16 hh, ll;
            fsplit(oacc[dt][0], hh, ll); Oh[g]   = hh; Ol[g]   = ll;
            fsplit(oacc[dt][1], hh, ll); Oh[g+1] = hh; Ol[g+1] = ll;
        }
        if (wr1) {
            size_t g = base + (size_t)(grow0+8)*128 + d;
            __nv_bfloat16 hh, ll;
            fsplit(oacc[dt][2], hh, ll); Oh[g]   = hh; Ol[g]   = ll;
            fsplit(oacc[dt][3], hh, ll); Oh[g+1] = hh; Ol[g+1] = ll;
        }
    }
}

// ---------------------------------------------------------------------------
// Fused residual + LayerNorm : h = LN(h + add) ; writes fp32 + split bf16
// ---------------------------------------------------------------------------
__global__ __launch_bounds__(256) void ln_kernel(const float* __restrict__ add,
                                                 const float* __restrict__ gam,
                                                 const float* __restrict__ bet) {
    int warp = threadIdx.x >> 5, lane = threadIdx.x & 31;
    int token = blockIdx.x * 8 + warp;
    const float* hp = &g_h[(size_t)token*Dd];
    const float* ap = &add[(size_t)token*Dd];
    float x[8], s = 0.f;
    #pragma unroll
    for (int j = 0; j < 8; j++) { x[j] = hp[lane*8 + j] + ap[lane*8 + j]; s += x[j]; }
    #pragma unroll
    for (int o = 16; o; o >>= 1) s += __shfl_xor_sync(~0u, s, o);
    float mean = s * (1.f/256.f);
    float v = 0.f;
    #pragma unroll
    for (int j = 0; j < 8; j++) { float d = x[j] - mean; v += d*d; }
    #pragma unroll
    for (int o = 16; o; o >>= 1) v += __shfl_xor_sync(~0u, v, o);
    float rstd = rsqrtf(v * (1.f/256.f) + EPSLN);
    float* op = &g_h[(size_t)token*Dd];
    #pragma unroll
    for (int j = 0; j < 8; j++) {
        int cix = lane*8 + j;
        float y = (x[j] - mean)*rstd*gam[cix] + bet[cix];
        op[cix] = y;
        size_t ix = (size_t)token*Dd + cix;
        __nv_bfloat16 hh, ll;
        fsplit(y, hh, ll);
        g_hhi[ix] = hh;
        g_hlo[ix] = ll;
    }
}

// ---------------------------------------------------------------------------
// Final head tail: out = relu_h(g_tmp fp32) @ o2w + o2b   (warp per token)
// ---------------------------------------------------------------------------
__global__ __launch_bounds__(256) void head2_kernel(const float* __restrict__ o2w,
                                                    const float* __restrict__ o2b,
                                                    float* __restrict__ out) {
    int warp = threadIdx.x >> 5, lane = threadIdx.x & 31;
    int token = blockIdx.x * 8 + warp;
    const float* hp = &g_tmp[(size_t)token*Dd];
    float a0 = 0.f, a1 = 0.f;
    #pragma unroll
    for (int j = 0; j < 8; j++) {
        int k = lane + j*32;
        float hv = hp[k];
        a0 = fmaf(hv, o2w[k*2],   a0);
        a1 = fmaf(hv, o2w[k*2+1], a1);
    }
    #pragma unroll
    for (int o = 16; o; o >>= 1) {
        a0 += __shfl_xor_sync(~0u, a0, o);
        a1 += __shfl_xor_sync(~0u, a1, o);
    }
    if (lane == 0) {
        out[(size_t)token*2]     = a0 + o2b[0];
        out[(size_t)token*2 + 1] = a1 + o2b[1];
    }
}

// ---------------------------------------------------------------------------
// Host orchestration
// ---------------------------------------------------------------------------
static inline void* symaddr(const void* s) {
    void* p = nullptr;
    cudaGetSymbolAddress(&p, s);
    return p;
}

extern "C" void kernel_launch(void* const* d_in, const int* in_sizes, int n_in,
                              void* d_out, int out_size) {
    const float* x    = (const float*)d_in[0];
    const float* in_w = (const float*)d_in[1];
    const float* in_b = (const float*)d_in[2];
    const float* qw   = (const float*)d_in[3];
    const float* qb   = (const float*)d_in[4];
    const float* kw   = (const float*)d_in[5];
    const float* kb   = (const float*)d_in[6];
    const float* vw   = (const float*)d_in[7];
    const float* vb   = (const float*)d_in[8];
    const float* ow   = (const float*)d_in[9];
    const float* ob   = (const float*)d_in[10];
    const float* f1w  = (const float*)d_in[11];
    const float* f1b  = (const float*)d_in[12];
    const float* f2w  = (const float*)d_in[13];
    const float* f2b  = (const float*)d_in[14];
    const float* n1g  = (const float*)d_in[15];
    const float* n1b  = (const float*)d_in[16];
    const float* n2g  = (const float*)d_in[17];
    const float* n2b  = (const float*)d_in[18];
    const float* o1w  = (const float*)d_in[19];
    const float* o1b  = (const float*)d_in[20];
    const float* o2w  = (const float*)d_in[21];
    const float* o2b  = (const float*)d_in[22];

    float* outp     = (float*)d_out;
    float* attn_out = outp + (size_t)Bd*Ld*2;

    __nv_bfloat16* p_hh   = (__nv_bfloat16*)symaddr(g_hhi);
    __nv_bfloat16* p_hl   = (__nv_bfloat16*)symaddr(g_hlo);
    __nv_bfloat16* p_qkvh = (__nv_bfloat16*)symaddr(g_qkvh);
    __nv_bfloat16* p_qkvl = (__nv_bfloat16*)symaddr(g_qkvl);
    __nv_bfloat16* p_oh   = (__nv_bfloat16*)symaddr(g_ohi);
    __nv_bfloat16* p_ol   = (__nv_bfloat16*)symaddr(g_olo);
    __nv_bfloat16* p_fh   = (__nv_bfloat16*)symaddr(g_fhi);
    __nv_bfloat16* p_fl   = (__nv_bfloat16*)symaddr(g_flo);
    float*         p_tmp  = (float*)symaddr(g_tmp);
    __nv_bfloat16* p_owh  = (__nv_bfloat16*)symaddr(g_owh);
    __nv_bfloat16* p_owl  = (__nv_bfloat16*)symaddr(g_owl);
    __nv_bfloat16* p_f1h  = (__nv_bfloat16*)symaddr(g_f1wh);
    __nv_bfloat16* p_f1l  = (__nv_bfloat16*)symaddr(g_f1wl);
    __nv_bfloat16* p_f2h  = (__nv_bfloat16*)symaddr(g_f2wh);
    __nv_bfloat16* p_f2l  = (__nv_bfloat16*)symaddr(g_f2wl);
    __nv_bfloat16* p_o1h  = (__nv_bfloat16*)symaddr(g_o1wh);
    __nv_bfloat16* p_o1l  = (__nv_bfloat16*)symaddr(g_o1wl);

    const int SM_G256 = 384*(256+8)*2;
    const int SM_G128 = 384*(128+8)*2;
    const int SM_G64  = 384*(64+8)*2;

    cudaFuncSetAttribute(gemm_qkv, cudaFuncAttributeMaxDynamicSharedMemorySize, SM_G256);
    cudaFuncSetAttribute(gemm_bias<256,true ,false,true >, cudaFuncAttributeMaxDynamicSharedMemorySize, SM_G256);
    cudaFuncSetAttribute(gemm_bias<256,false,true ,true >, cudaFuncAttributeMaxDynamicSharedMemorySize, SM_G256);
    cudaFuncSetAttribute(gemm_bias<128,false,true ,false>, cudaFuncAttributeMaxDynamicSharedMemorySize, SM_G128);
    cudaFuncSetAttribute(gemm_bias<64 ,false,true ,false>, cudaFuncAttributeMaxDynamicSharedMemorySize, SM_G64);
    cudaFuncSetAttribute(attn_kernel, cudaFuncAttributeMaxDynamicSharedMemorySize, SM_ATTN_BYTES);

    convert_w<<<384, 256>>>(qw, kw, vw, ow, f1w, f2w, o1w, qb, kb, vb);
    embed_kernel<<<BLd, Dd>>>(x, in_w, in_b);

    const dim3 gQKV (BLd/128, 6);
    const dim3 gProj(BLd/128, 4);   // N=256
    const dim3 gF1  (BLd/128, 1);   // N=64
    const dim3 gAttn((Ld + QT - 1)/QT, Bd*Hd);

    for (int i = 0; i < NLd; i++) {
        gemm_qkv<<<gQKV, 512, SM_G256>>>(i);

        attn_kernel<<<gAttn, 512, SM_ATTN_BYTES>>>(
            p_qkvh, p_qkvl,
            attn_out + (size_t)i*Bd*Hd*Ld*Ld, p_oh, p_ol);

        gemm_bias<128,false,true,false><<<gProj, 512, SM_G128>>>(
            p_oh, p_ol, p_owh + (size_t)i*128*Dd, p_owl + (size_t)i*128*Dd,
            ob + i*Dd, p_tmp, nullptr, nullptr, Dd);
        ln_kernel<<<BLd/8, 256>>>(p_tmp, n1g + i*Dd, n1b + i*Dd);

        gemm_bias<256,true,false,true><<<gF1, 512, SM_G256>>>(
            p_hh, p_hl, p_f1h + (size_t)i*Dd*FCd, p_f1l + (size_t)i*Dd*FCd,
            f1b + i*FCd, nullptr, p_fh, p_fl, FCd);
        gemm_bias<64,false,true,false><<<gProj, 512, SM_G64>>>(
            p_fh, p_fl, p_f2h + (size_t)i*FCd*Dd, p_f2l + (size_t)i*FCd*Dd,
            f2b + i*Dd, p_tmp, nullptr, nullptr, Dd);
        ln_kernel<<<BLd/8, 256>>>(p_tmp, n2g + i*Dd, n2b + i*Dd);
    }

    gemm_bias<256,false,true,true><<<gProj, 512, SM_G256>>>(
        p_hh, p_hl, p_o1h, p_o1l, o1b, p_tmp, nullptr, nullptr, Dd);
    head2_kernel<<<BLd/8, 256>>>(o2w, o2b, outp);
}

// round 7
// speedup vs baseline: 4.3421x; 1.0902x over previous
#include <cuda_runtime.h>
#include <cuda_bf16.h>
#include <stdint.h>

#define Bd  8
#define Ld  2016
#define Hd  4
#define DKd 32
#define Dd  256
#define FCd 64
#define NLd 3
#define BLd (Bd*Ld)          // 16128 tokens

#define SC2f 0.09016844005556f   // (1/sqrt(256)) * log2(e)
#define EPSLN 1e-5f

// ---------------------------------------------------------------------------
// Device scratch (no allocation allowed). hi/lo split bf16 pairs everywhere.
// ---------------------------------------------------------------------------
__device__ __align__(128) float          g_h    [BLd*Dd];
__device__ __align__(128) __nv_bfloat16  g_hhi  [BLd*Dd];
__device__ __align__(128) __nv_bfloat16  g_hlo  [BLd*Dd];
__device__ __align__(128) __nv_bfloat16  g_qkvh [3*BLd*128];
__device__ __align__(128) __nv_bfloat16  g_qkvl [3*BLd*128];
__device__ __align__(128) __nv_bfloat16  g_ohi  [BLd*128];
__device__ __align__(128) __nv_bfloat16  g_olo  [BLd*128];
__device__ __align__(128) float          g_tmp  [BLd*Dd];
__device__ __align__(128) __nv_bfloat16  g_fhi  [BLd*FCd];
__device__ __align__(128) __nv_bfloat16  g_flo  [BLd*FCd];
// split weights
__device__ __align__(128) __nv_bfloat16  g_qkvwh[NLd*3*Dd*128];
__device__ __align__(128) __nv_bfloat16  g_qkvwl[NLd*3*Dd*128];
__device__ __align__(128) float          g_qkvb [NLd*3*128];
__device__ __align__(128) __nv_bfloat16  g_owh  [NLd*128*Dd];
__device__ __align__(128) __nv_bfloat16  g_owl  [NLd*128*Dd];
__device__ __align__(128) __nv_bfloat16  g_f1wh [NLd*Dd*FCd];
__device__ __align__(128) __nv_bfloat16  g_f1wl [NLd*Dd*FCd];
__device__ __align__(128) __nv_bfloat16  g_f2wh [NLd*FCd*Dd];
__device__ __align__(128) __nv_bfloat16  g_f2wl [NLd*FCd*Dd];
__device__ __align__(128) __nv_bfloat16  g_o1wh [Dd*Dd];
__device__ __align__(128) __nv_bfloat16  g_o1wl [Dd*Dd];

// ---------------------------------------------------------------------------
// helpers
// ---------------------------------------------------------------------------
__device__ __forceinline__ void mma16816(float* d, const uint32_t* a,
                                         uint32_t b0, uint32_t b1) {
    asm volatile(
        "mma.sync.aligned.m16n8k16.row.col.f32.bf16.bf16.f32 "
        "{%0,%1,%2,%3}, {%4,%5,%6,%7}, {%8,%9}, {%0,%1,%2,%3};"
        : "+f"(d[0]), "+f"(d[1]), "+f"(d[2]), "+f"(d[3])
        : "r"(a[0]), "r"(a[1]), "r"(a[2]), "r"(a[3]), "r"(b0), "r"(b1));
}

__device__ __forceinline__ void ldsm4(uint32_t& r0, uint32_t& r1,
                                      uint32_t& r2, uint32_t& r3, uint32_t a) {
    asm volatile("ldmatrix.sync.aligned.m8n8.x4.shared.b16 {%0,%1,%2,%3}, [%4];"
        : "=r"(r0), "=r"(r1), "=r"(r2), "=r"(r3) : "r"(a));
}

__device__ __forceinline__ void ldsm4t(uint32_t& r0, uint32_t& r1,
                                       uint32_t& r2, uint32_t& r3, uint32_t a) {
    asm volatile("ldmatrix.sync.aligned.m8n8.x4.trans.shared.b16 {%0,%1,%2,%3}, [%4];"
        : "=r"(r0), "=r"(r1), "=r"(r2), "=r"(r3) : "r"(a));
}

__device__ __forceinline__ void cpa16(uint32_t dst, const void* src, int srcsize) {
    asm volatile("cp.async.cg.shared.global [%0], [%1], 16, %2;"
        :: "r"(dst), "l"(src), "r"(srcsize));
}
__device__ __forceinline__ void cpa_commit() {
    asm volatile("cp.async.commit_group;" ::: "memory");
}
template<int N>
__device__ __forceinline__ void cpa_wait() {
    asm volatile("cp.async.wait_group %0;" :: "n"(N) : "memory");
}

__device__ __forceinline__ float ex2(float x) {
    float y;
    asm("ex2.approx.ftz.f32 %0, %1;" : "=f"(y) : "f"(x));
    return y;
}

__device__ __forceinline__ uint32_t pk2(float x, float y) {
    __nv_bfloat162 t = __floats2bfloat162_rn(x, y);
    return *reinterpret_cast<uint32_t*>(&t);
}

__device__ __forceinline__ void fsplit(float v, __nv_bfloat16& hi, __nv_bfloat16& lo) {
    hi = __float2bfloat16(v);
    lo = __float2bfloat16(v - __bfloat162float(hi));
}

__device__ __forceinline__ void pksplit(float x, float y, uint32_t& hi, uint32_t& lo) {
    __nv_bfloat16 xh = __float2bfloat16(x), yh = __float2bfloat16(y);
    __nv_bfloat162 th; th.x = xh; th.y = yh;
    hi = *reinterpret_cast<uint32_t*>(&th);
    lo = pk2(x - __bfloat162float(xh), y - __bfloat162float(yh));
}

__device__ __forceinline__ void stcs2(float* p, float a, float b) {
    asm volatile("st.global.cs.v2.f32 [%0], {%1,%2};" :: "l"(p), "f"(a), "f"(b));
}

// ---------------------------------------------------------------------------
// Weight conversion fp32 -> bf16 hi/lo (+ QKV packing)
// ---------------------------------------------------------------------------
__global__ void convert_w(const float* __restrict__ qw, const float* __restrict__ kw,
                          const float* __restrict__ vw, const float* __restrict__ ow,
                          const float* __restrict__ f1w, const float* __restrict__ f2w,
                          const float* __restrict__ o1w,
                          const float* __restrict__ qb, const float* __restrict__ kb,
                          const float* __restrict__ vb) {
    int i = blockIdx.x * 256 + threadIdx.x;
    const int n1 = NLd*Dd*128;
    const int n3 = NLd*Dd*FCd;
    const int n5 = Dd*Dd;
    if (i < n1) {
        int l = i / (Dd*128), rem = i % (Dd*128);
        size_t b = (size_t)(l*3)*Dd*128 + rem;
        fsplit(qw[i], g_qkvwh[b],            g_qkvwl[b]);
        fsplit(kw[i], g_qkvwh[b + Dd*128],   g_qkvwl[b + Dd*128]);
        fsplit(vw[i], g_qkvwh[b + 2*Dd*128], g_qkvwl[b + 2*Dd*128]);
        fsplit(ow[i], g_owh[i], g_owl[i]);
    }
    if (i < n3) {
        fsplit(f1w[i], g_f1wh[i], g_f1wl[i]);
        fsplit(f2w[i], g_f2wh[i], g_f2wl[i]);
    }
    if (i < n5) fsplit(o1w[i], g_o1wh[i], g_o1wl[i]);
    if (i < NLd*128) {
        int l = i >> 7, n = i & 127;
        g_qkvb[(l*3+0)*128 + n] = qb[i];
        g_qkvb[(l*3+1)*128 + n] = kb[i];
        g_qkvb[(l*3+2)*128 + n] = vb[i];
    }
}

// ---------------------------------------------------------------------------
// Embed: h = x @ in_w + in_b (fp32 + split)
// ---------------------------------------------------------------------------
__global__ void embed_kernel(const float* __restrict__ x,
                             const float* __restrict__ in_w,
                             const float* __restrict__ in_b) {
    int t = blockIdx.x, d = threadIdx.x;
    float x0 = x[t*2], x1 = x[t*2+1];
    float v = fmaf(x0, in_w[d], fmaf(x1, in_w[Dd + d], in_b[d]));
    size_t ix = (size_t)t*Dd + d;
    g_h[ix] = v;
    fsplit(v, g_hhi[ix], g_hlo[ix]);
}

// ---------------------------------------------------------------------------
// GEMM core: tile 128x64, 512 threads (16 warps: 8 M x 2 N). 3-term split MMA.
// ---------------------------------------------------------------------------
template<int K, bool OUT_B16, bool OUT_F32, bool RELU>
__device__ __forceinline__ void gemm_body(
        const __nv_bfloat16* __restrict__ Ahi,
        const __nv_bfloat16* __restrict__ Alo,
        const __nv_bfloat16* __restrict__ Whi,
        const __nv_bfloat16* __restrict__ Wlo,
        const float* __restrict__ bias,
        float* __restrict__ outF,
        __nv_bfloat16* __restrict__ outBh,
        __nv_bfloat16* __restrict__ outBl,
        int N, int row0, int col0) {
    extern __shared__ __nv_bfloat16 sm[];
    constexpr int SA = K + 8;
    __nv_bfloat16* sAh = sm;
    __nv_bfloat16* sAl = sm + 128 * SA;
    __nv_bfloat16* sWh = sm + 256 * SA;
    __nv_bfloat16* sWl = sWh + 64 * SA;

    const int tid = threadIdx.x, lane = tid & 31, warp = tid >> 5;

    constexpr int AV = K / 8;
    #pragma unroll 2
    for (int i = tid; i < 128 * AV; i += 512) {
        int r = i / AV, c = (i % AV) * 8;
        size_t g = (size_t)(row0 + r)*K + c;
        *reinterpret_cast<uint4*>(&sAh[r*SA + c]) = *reinterpret_cast<const uint4*>(&Ahi[g]);
        *reinterpret_cast<uint4*>(&sAl[r*SA + c]) = *reinterpret_cast<const uint4*>(&Alo[g]);
    }
    #pragma unroll 2
    for (int i = tid; i < 64 * K / 4; i += 512) {
        int k = i >> 4, n4 = (i & 15) * 4;
        size_t g = (size_t)k*N + col0 + n4;
        uint2 wh = *reinterpret_cast<const uint2*>(&Whi[g]);
        uint2 wl = *reinterpret_cast<const uint2*>(&Wlo[g]);
        __nv_bfloat16 th[4]; *reinterpret_cast<uint2*>(th) = wh;
        __nv_bfloat16 tl[4]; *reinterpret_cast<uint2*>(tl) = wl;
        #pragma unroll
        for (int j = 0; j < 4; j++) {
            sWh[(n4+j)*SA + k] = th[j];
            sWl[(n4+j)*SA + k] = tl[j];
        }
    }
    __syncthreads();

    float acc[4][4];
    #pragma unroll
    for (int i = 0; i < 4; i++)
        #pragma unroll
        for (int j = 0; j < 4; j++) acc[i][j] = 0.f;

    const int mwarp = warp >> 1, nwarp = warp & 1;
    const int ar = mwarp*16 + (lane >> 2);
    const int ac = (lane & 3) * 2;
    #pragma unroll
    for (int kk = 0; kk < K/16; kk++) {
        uint32_t ah[4], al[4];
        {
            const __nv_bfloat16* pa = &sAh[ar*SA + kk*16 + ac];
            ah[0] = *(const uint32_t*)pa;
            ah[1] = *(const uint32_t*)(pa + 8*SA);
            ah[2] = *(const uint32_t*)(pa + 8);
            ah[3] = *(const uint32_t*)(pa + 8*SA + 8);
            const __nv_bfloat16* pl = &sAl[ar*SA + kk*16 + ac];
            al[0] = *(const uint32_t*)pl;
            al[1] = *(const uint32_t*)(pl + 8*SA);
            al[2] = *(const uint32_t*)(pl + 8);
            al[3] = *(const uint32_t*)(pl + 8*SA + 8);
        }
        #pragma unroll
        for (int nt = 0; nt < 4; nt++) {
            int nrow = nwarp*32 + nt*8 + (lane>>2);
            const __nv_bfloat16* pbh = &sWh[nrow*SA + kk*16 + ac];
            uint32_t bh0 = *(const uint32_t*)pbh;
            uint32_t bh1 = *(const uint32_t*)(pbh + 8);
            const __nv_bfloat16* pbl = &sWl[nrow*SA + kk*16 + ac];
            uint32_t bl0 = *(const uint32_t*)pbl;
            uint32_t bl1 = *(const uint32_t*)(pbl + 8);
            mma16816(acc[nt], ah, bh0, bh1);
            mma16816(acc[nt], al, bh0, bh1);
            mma16816(acc[nt], ah, bl0, bl1);
        }
    }

    const int orow = row0 + mwarp*16 + (lane >> 2);
    #pragma unroll
    for (int nt = 0; nt < 4; nt++) {
        int c = col0 + nwarp*32 + nt*8 + (lane & 3)*2;
        float b0v = bias[c], b1v = bias[c+1];
        #pragma unroll
        for (int half = 0; half < 2; half++) {
            int r = orow + half*8;
            float v0 = acc[nt][half*2+0] + b0v;
            float v1 = acc[nt][half*2+1] + b1v;
            if (RELU) { v0 = fmaxf(v0, 0.f); v1 = fmaxf(v1, 0.f); }
            size_t o = (size_t)r*N + c;
            if (OUT_F32) { outF[o] = v0; outF[o+1] = v1; }
            if (OUT_B16) {
                __nv_bfloat16 h0, l0, h1, l1;
                fsplit(v0, h0, l0);
                fsplit(v1, h1, l1);
                outBh[o] = h0; outBh[o+1] = h1;
                outBl[o] = l0; outBl[o+1] = l1;
            }
        }
    }
}

template<int K, bool OUT_B16, bool OUT_F32, bool RELU>
__global__ __launch_bounds__(512) void gemm_bias(
        const __nv_bfloat16* __restrict__ Ahi, const __nv_bfloat16* __restrict__ Alo,
        const __nv_bfloat16* __restrict__ Whi, const __nv_bfloat16* __restrict__ Wlo,
        const float* __restrict__ bias,
        float* __restrict__ outF,
        __nv_bfloat16* __restrict__ outBh, __nv_bfloat16* __restrict__ outBl,
        int N) {
    gemm_body<K, OUT_B16, OUT_F32, RELU>(Ahi, Alo, Whi, Wlo, bias, outF, outBh, outBl,
                                         N, blockIdx.x*128, blockIdx.y*64);
}

// Fused QKV: grid (126, 6); blockIdx.y selects (q/k/v, col-half)
__global__ __launch_bounds__(512) void gemm_qkv(int layer) {
    int sel = blockIdx.y >> 1;
    int col0 = (blockIdx.y & 1) * 64;
    const __nv_bfloat16* Whi = g_qkvwh + ((size_t)(layer*3 + sel))*Dd*128;
    const __nv_bfloat16* Wlo = g_qkvwl + ((size_t)(layer*3 + sel))*Dd*128;
    const float* bias = g_qkvb + (layer*3 + sel)*128;
    __nv_bfloat16* oh = g_qkvh + (size_t)sel*BLd*128;
    __nv_bfloat16* ol = g_qkvl + (size_t)sel*BLd*128;
    gemm_body<256, true, false, false>(g_hhi, g_hlo, Whi, Wlo, bias, nullptr, oh, ol,
                                       128, blockIdx.x*128, col0);
}

// ---------------------------------------------------------------------------
// Attention v3.1: 256-query tile, 512 threads (16 warps x 16 rows), 256-key
// chunks, cp.async double-buffered K/V staging, ldmatrix fragment loads,
// Q fragments direct from gmem. Two passes, m=0, ex2-folded scale.
// Padding keys (2016..2047) are zfilled -> score exactly 0 -> exp exactly 1:
// corrected by subtracting 32.0 from each reduced row-sum (exact).
// ---------------------------------------------------------------------------
#define QT 256
#define KT 256
#define NCH 8
#define NPAD 32.0f            // 2048 - 2016 phantom keys, each contributing 1.0

#define KBUF 10240            // elements per K (or V) buffer: 256*40
#define SM_ATTN_BYTES (8*KBUF*2)   // 163840

struct AttnSmem {
    uint32_t kh, kl, vh, vl;  // u32 shared-space base addresses
};

__device__ __forceinline__ void stageK(const AttnSmem& S, int buf, int ch,
        const __nv_bfloat16* Kh, const __nv_bfloat16* Kl, size_t base, int tid) {
    const int k0 = ch * KT;
    #pragma unroll
    for (int it = 0; it < 4; it++) {
        int o = tid + it*512;
        int half = o >> 10;
        int r = (o & 1023) >> 2;
        int c = (o & 3) * 8;
        int s = k0 + r;
        bool ok = s < Ld;
        const __nv_bfloat16* src = (half ? Kl : Kh) + base + (size_t)(ok ? s : 0)*128 + c;
        uint32_t dst = (half ? S.kl : S.kh) + (buf*KBUF + r*40 + c)*2;
        cpa16(dst, src, ok ? 16 : 0);
    }
}

__device__ __forceinline__ void stageV(const AttnSmem& S, int buf, int ch,
        const __nv_bfloat16* Vh, const __nv_bfloat16* Vl, size_t base, int tid) {
    const int k0 = ch * KT;
    #pragma unroll
    for (int it = 0; it < 4; it++) {
        int o = tid + it*512;
        int half = o >> 10;
        int r = (o & 1023) >> 2;
        int c = (o & 3) * 8;
        int s = k0 + r;
        bool ok = s < Ld;
        const __nv_bfloat16* src = (half ? Vl : Vh) + base + (size_t)(ok ? s : 0)*128 + c;
        uint32_t dst = (half ? S.vl : S.vh) + (buf*KBUF + r*40 + c)*2;
        cpa16(dst, src, ok ? 16 : 0);
    }
}

__device__ __forceinline__ void qk_stats_chunk(
        uint32_t kh_u, uint32_t kl_u, int laneK,
        const uint32_t aqh[2][4], const uint32_t aql[2][4],
        float& s0, float& s1) {
    #pragma unroll 1
    for (int gq = 0; gq < 8; gq++) {
        float acc[4][4];
        #pragma unroll
        for (int i = 0; i < 4; i++)
            #pragma unroll
            for (int j = 0; j < 4; j++) acc[i][j] = 0.f;
        #pragma unroll
        for (int pair = 0; pair < 2; pair++) {
            int be = (gq*32 + pair*16)*40;
            #pragma unroll
            for (int kk = 0; kk < 2; kk++) {
                uint32_t bh0, bh1, bh2, bh3, bl0, bl1, bl2, bl3;
                uint32_t off = (be + kk*16 + laneK)*2;
                ldsm4(bh0, bh1, bh2, bh3, kh_u + off);
                ldsm4(bl0, bl1, bl2, bl3, kl_u + off);
                mma16816(acc[pair*2  ], aqh[kk], bh0, bh1);
                mma16816(acc[pair*2  ], aql[kk], bh0, bh1);
                mma16816(acc[pair*2  ], aqh[kk], bl0, bl1);
                mma16816(acc[pair*2+1], aqh[kk], bh2, bh3);
                mma16816(acc[pair*2+1], aql[kk], bh2, bh3);
                mma16816(acc[pair*2+1], aqh[kk], bl2, bl3);
            }
        }
        #pragma unroll
        for (int nt = 0; nt < 4; nt++) {
            s0 += ex2(acc[nt][0]*SC2f) + ex2(acc[nt][1]*SC2f);
            s1 += ex2(acc[nt][2]*SC2f) + ex2(acc[nt][3]*SC2f);
        }
    }
}

template<bool MASK>
__device__ __forceinline__ void qk_emit_chunk(
        uint32_t kh_u, uint32_t kl_u, uint32_t vh_u, uint32_t vl_u,
        int laneK, int laneV,
        const uint32_t aqh[2][4], const uint32_t aql[2][4],
        int k0, int fc, float inv0, float inv1,
        float* prow0, float* prow1, bool wr0, bool wr1,
        float oacc[4][4]) {
    #pragma unroll 1
    for (int g = 0; g < 16; g++) {
        int kbe = g*16*40;
        float acc1[2][4], acc2[2][4];
        #pragma unroll
        for (int i = 0; i < 2; i++)
            #pragma unroll
            for (int j = 0; j < 4; j++) { acc1[i][j] = 0.f; acc2[i][j] = 0.f; }
        #pragma unroll
        for (int kk = 0; kk < 2; kk++) {
            uint32_t bh0, bh1, bh2, bh3, bl0, bl1, bl2, bl3;
            uint32_t off = (kbe + kk*16 + laneK)*2;
            ldsm4(bh0, bh1, bh2, bh3, kh_u + off);
            ldsm4(bl0, bl1, bl2, bl3, kl_u + off);
            mma16816(acc1[0], aqh[kk], bh0, bh1);
            mma16816(acc2[0], aql[kk], bh0, bh1);
            mma16816(acc2[0], aqh[kk], bl0, bl1);
            mma16816(acc1[1], aqh[kk], bh2, bh3);
            mma16816(acc2[1], aql[kk], bh2, bh3);
            mma16816(acc2[1], aqh[kk], bl2, bl3);
        }
        int colb = k0 + g*16 + fc;
        bool ok0 = !MASK || (colb < Ld);
        bool ok1 = !MASK || (colb + 8 < Ld);
        float p00 = ok0 ? ex2((acc1[0][0]+acc2[0][0])*SC2f)*inv0 : 0.f;
        float p01 = ok0 ? ex2((acc1[0][1]+acc2[0][1])*SC2f)*inv0 : 0.f;
        float p02 = ok0 ? ex2((acc1[0][2]+acc2[0][2])*SC2f)*inv1 : 0.f;
        float p03 = ok0 ? ex2((acc1[0][3]+acc2[0][3])*SC2f)*inv1 : 0.f;
        float p10 = ok1 ? ex2((acc1[1][0]+acc2[1][0])*SC2f)*inv0 : 0.f;
        float p11 = ok1 ? ex2((acc1[1][1]+acc2[1][1])*SC2f)*inv0 : 0.f;
        float p12 = ok1 ? ex2((acc1[1][2]+acc2[1][2])*SC2f)*inv1 : 0.f;
        float p13 = ok1 ? ex2((acc1[1][3]+acc2[1][3])*SC2f)*inv1 : 0.f;

        if (wr0) {
            if (ok0) stcs2(&prow0[colb],     p00, p01);
            if (ok1) stcs2(&prow0[colb + 8], p10, p11);
        }
        if (wr1) {
            if (ok0) stcs2(&prow1[colb],     p02, p03);
            if (ok1) stcs2(&prow1[colb + 8], p12, p13);
        }

        uint32_t ah[4], al[4];
        pksplit(p00, p01, ah[0], al[0]);
        pksplit(p02, p03, ah[1], al[1]);
        pksplit(p10, p11, ah[2], al[2]);
        pksplit(p12, p13, ah[3], al[3]);

        #pragma unroll
        for (int dp = 0; dp < 2; dp++) {
            uint32_t vb0, vb1, vb2, vb3, wl0, wl1, wl2, wl3;
            uint32_t off = (kbe + dp*16 + laneV)*2;
            ldsm4t(vb0, vb1, vb2, vb3, vh_u + off);
            ldsm4t(wl0, wl1, wl2, wl3, vl_u + off);
            mma16816(oacc[dp*2  ], ah, vb0, vb1);
            mma16816(oacc[dp*2  ], al, vb0, vb1);
            mma16816(oacc[dp*2  ], ah, wl0, wl1);
            mma16816(oacc[dp*2+1], ah, vb2, vb3);
            mma16816(oacc[dp*2+1], al, vb2, vb3);
            mma16816(oacc[dp*2+1], ah, wl2, wl3);
        }
    }
}

__global__ __launch_bounds__(512, 1) void attn_kernel(
        const __nv_bfloat16* __restrict__ qkvh,
        const __nv_bfloat16* __restrict__ qkvl,
        float* __restrict__ Pout,
        __nv_bfloat16* __restrict__ Oh, __nv_bfloat16* __restrict__ Ol) {
    extern __shared__ __nv_bfloat16 sm[];
    uint32_t sm_u = (uint32_t)__cvta_generic_to_shared(sm);
    AttnSmem S;
    S.kh = sm_u;
    S.kl = sm_u + 2*KBUF*2;
    S.vh = sm_u + 4*KBUF*2;
    S.vl = sm_u + 6*KBUF*2;

    const int tid = threadIdx.x, lane = tid & 31, warp = tid >> 5;
    const int bh = blockIdx.y;
    const int b  = bh >> 2, h = bh & 3;
    const int q0 = blockIdx.x * QT;
    const size_t base = ((size_t)b*Ld*Hd + h)*DKd;
    const __nv_bfloat16* Qh = qkvh;
    const __nv_bfloat16* Ql = qkvl;
    const __nv_bfloat16* Kh = qkvh + (size_t)BLd*128;
    const __nv_bfloat16* Kl = qkvl + (size_t)BLd*128;
    const __nv_bfloat16* Vh = qkvh + (size_t)2*BLd*128;
    const __nv_bfloat16* Vl = qkvl + (size_t)2*BLd*128;

    const int mrow = warp * 16;
    const int fr = lane >> 2, fc = (lane & 3) * 2;
    const int lr = lane & 7, sel = lane >> 3;
    const int laneK = ((sel>>1)*8 + lr)*40 + (sel&1)*8;
    const int laneV = ((sel&1)*8 + lr)*40 + (sel>>1)*8;

    // ---- Q fragments straight from gmem ----
    const int r0g = q0 + mrow + fr, r1g = r0g + 8;
    const bool q0ok = (r0g < Ld), q1ok = (r1g < Ld);
    uint32_t aqh[2][4], aql[2][4];
    #pragma unroll
    for (int kk = 0; kk < 2; kk++) {
        int c = kk*16 + fc;
        size_t g0 = base + (size_t)r0g*128 + c;
        size_t g1 = base + (size_t)r1g*128 + c;
        aqh[kk][0] = q0ok ? *(const uint32_t*)&Qh[g0]     : 0;
        aqh[kk][1] = q1ok ? *(const uint32_t*)&Qh[g1]     : 0;
        aqh[kk][2] = q0ok ? *(const uint32_t*)&Qh[g0 + 8] : 0;
        aqh[kk][3] = q1ok ? *(const uint32_t*)&Qh[g1 + 8] : 0;
        aql[kk][0] = q0ok ? *(const uint32_t*)&Ql[g0]     : 0;
        aql[kk][1] = q1ok ? *(const uint32_t*)&Ql[g1]     : 0;
        aql[kk][2] = q0ok ? *(const uint32_t*)&Ql[g0 + 8] : 0;
        aql[kk][3] = q1ok ? *(const uint32_t*)&Ql[g1 + 8] : 0;
    }

    float s0 = 0.f, s1 = 0.f;

    // ================= PASS A: row sums (K only, double-buffered) =========
    stageK(S, 0, 0, Kh, Kl, base, tid); cpa_commit();
    stageK(S, 1, 1, Kh, Kl, base, tid); cpa_commit();
    #pragma unroll 1
    for (int ch = 0; ch < NCH; ch++) {
        if (ch < NCH-1) cpa_wait<1>(); else cpa_wait<0>();
        __syncthreads();
        int buf = ch & 1;
        qk_stats_chunk(S.kh + buf*KBUF*2, S.kl + buf*KBUF*2, laneK, aqh, aql, s0, s1);
        __syncthreads();
        if (ch + 2 < NCH) { stageK(S, buf, ch+2, Kh, Kl, base, tid); cpa_commit(); }
    }

    // prologue for pass B overlaps the reduction
    stageK(S, 0, 0, Kh, Kl, base, tid);
    stageV(S, 0, 0, Vh, Vl, base, tid); cpa_commit();
    stageK(S, 1, 1, Kh, Kl, base, tid);
    stageV(S, 1, 1, Vh, Vl, base, tid); cpa_commit();

    s0 += __shfl_xor_sync(~0u, s0, 1);
    s0 += __shfl_xor_sync(~0u, s0, 2);
    s1 += __shfl_xor_sync(~0u, s1, 1);
    s1 += __shfl_xor_sync(~0u, s1, 2);
    // Remove phantom-key contributions: 32 zfilled keys scored exactly 0,
    // each adding ex2(0)=1.0 exactly to every row sum.
    s0 -= NPAD;
    s1 -= NPAD;
    const float inv0 = 1.f / s0, inv1 = 1.f / s1;

    // ================= PASS B: P out + PV =================
    float oacc[4][4];
    #pragma unroll
    for (int i = 0; i < 4; i++)
        #pragma unroll
        for (int j = 0; j < 4; j++) oacc[i][j] = 0.f;

    float* prow0 = &Pout[((size_t)bh*Ld + r0g)*Ld];
    float* prow1 = prow0 + 8*(size_t)Ld;

    #pragma unroll 1
    for (int ch = 0; ch < NCH; ch++) {
        if (ch < NCH-1) cpa_wait<1>(); else cpa_wait<0>();
        __syncthreads();
        int buf = ch & 1;
        uint32_t kh_u = S.kh + buf*KBUF*2, kl_u = S.kl + buf*KBUF*2;
        uint32_t vh_u = S.vh + buf*KBUF*2, vl_u = S.vl + buf*KBUF*2;
        if (ch < NCH-1)
            qk_emit_chunk<false>(kh_u, kl_u, vh_u, vl_u, laneK, laneV, aqh, aql,
                                 ch*KT, fc, inv0, inv1, prow0, prow1, q0ok, q1ok, oacc);
        else
            qk_emit_chunk<true >(kh_u, kl_u, vh_u, vl_u, laneK, laneV, aqh, aql,
                                 ch*KT, fc, inv0, inv1, prow0, prow1, q0ok, q1ok, oacc);
        __syncthreads();
        if (ch + 2 < NCH) {
            stageK(S, buf, ch+2, Kh, Kl, base, tid);
            stageV(S, buf, ch+2, Vh, Vl, base, tid);
            cpa_commit();
        }
    }

    // ---- write O (hi/lo) ----
    #pragma unroll
    for (int dt = 0; dt < 4; dt++) {
        int d = dt*8 + fc;
        if (q0ok) {
            size_t g = base + (size_t)r0g*128 + d;
            __nv_bfloat16 hh, ll;
            fsplit(oacc[dt][0], hh, ll); Oh[g]   = hh; Ol[g]   = ll;
            fsplit(oacc[dt][1], hh, ll); Oh[g+1] = hh; Ol[g+1] = ll;
        }
        if (q1ok) {
            size_t g = base + (size_t)r1g*128 + d;
            __nv_bfloat16 hh, ll;
            fsplit(oacc[dt][2], hh, ll); Oh[g]   = hh; Ol[g]   = ll;
            fsplit(oacc[dt][3], hh, ll); Oh[g+1] = hh; Ol[g+1] = ll;
        }
    }
}

// ---------------------------------------------------------------------------
// Fused residual + LayerNorm : h = LN(h + add) ; writes fp32 + split bf16
// ---------------------------------------------------------------------------
__global__ __launch_bounds__(256) void ln_kernel(const float* __restrict__ add,
                                                 const float* __restrict__ gam,
                                                 const float* __restrict__ bet) {
    int warp = threadIdx.x >> 5, lane = threadIdx.x & 31;
    int token = blockIdx.x * 8 + warp;
    const float* hp = &g_h[(size_t)token*Dd];
    const float* ap = &add[(size_t)token*Dd];
    float x[8], s = 0.f;
    #pragma unroll
    for (int j = 0; j < 8; j++) { x[j] = hp[lane*8 + j] + ap[lane*8 + j]; s += x[j]; }
    #pragma unroll
    for (int o = 16; o; o >>= 1) s += __shfl_xor_sync(~0u, s, o);
    float mean = s * (1.f/256.f);
    float v = 0.f;
    #pragma unroll
    for (int j = 0; j < 8; j++) { float d = x[j] - mean; v += d*d; }
    #pragma unroll
    for (int o = 16; o; o >>= 1) v += __shfl_xor_sync(~0u, v, o);
    float rstd = rsqrtf(v * (1.f/256.f) + EPSLN);
    float* op = &g_h[(size_t)token*Dd];
    #pragma unroll
    for (int j = 0; j < 8; j++) {
        int cix = lane*8 + j;
        float y = (x[j] - mean)*rstd*gam[cix] + bet[cix];
        op[cix] = y;
        size_t ix = (size_t)token*Dd + cix;
        __nv_bfloat16 hh, ll;
        fsplit(y, hh, ll);
        g_hhi[ix] = hh;
        g_hlo[ix] = ll;
    }
}

// ---------------------------------------------------------------------------
// Final head tail: out = relu_h(g_tmp fp32) @ o2w + o2b   (warp per token)
// ---------------------------------------------------------------------------
__global__ __launch_bounds__(256) void head2_kernel(const float* __restrict__ o2w,
                                                    const float* __restrict__ o2b,
                                                    float* __restrict__ out) {
    int warp = threadIdx.x >> 5, lane = threadIdx.x & 31;
    int token = blockIdx.x * 8 + warp;
    const float* hp = &g_tmp[(size_t)token*Dd];
    float a0 = 0.f, a1 = 0.f;
    #pragma unroll
    for (int j = 0; j < 8; j++) {
        int k = lane + j*32;
        float hv = hp[k];
        a0 = fmaf(hv, o2w[k*2],   a0);
        a1 = fmaf(hv, o2w[k*2+1], a1);
    }
    #pragma unroll
    for (int o = 16; o; o >>= 1) {
        a0 += __shfl_xor_sync(~0u, a0, o);
        a1 += __shfl_xor_sync(~0u, a1, o);
    }
    if (lane == 0) {
        out[(size_t)token*2]     = a0 + o2b[0];
        out[(size_t)token*2 + 1] = a1 + o2b[1];
    }
}

// ---------------------------------------------------------------------------
// Host orchestration
// ---------------------------------------------------------------------------
static inline void* symaddr(const void* s) {
    void* p = nullptr;
    cudaGetSymbolAddress(&p, s);
    return p;
}

extern "C" void kernel_launch(void* const* d_in, const int* in_sizes, int n_in,
                              void* d_out, int out_size) {
    const float* x    = (const float*)d_in[0];
    const float* in_w = (const float*)d_in[1];
    const float* in_b = (const float*)d_in[2];
    const float* qw   = (const float*)d_in[3];
    const float* qb   = (const float*)d_in[4];
    const float* kw   = (const float*)d_in[5];
    const float* kb   = (const float*)d_in[6];
    const float* vw   = (const float*)d_in[7];
    const float* vb   = (const float*)d_in[8];
    const float* ow   = (const float*)d_in[9];
    const float* ob   = (const float*)d_in[10];
    const float* f1w  = (const float*)d_in[11];
    const float* f1b  = (const float*)d_in[12];
    const float* f2w  = (const float*)d_in[13];
    const float* f2b  = (const float*)d_in[14];
    const float* n1g  = (const float*)d_in[15];
    const float* n1b  = (const float*)d_in[16];
    const float* n2g  = (const float*)d_in[17];
    const float* n2b  = (const float*)d_in[18];
    const float* o1w  = (const float*)d_in[19];
    const float* o1b  = (const float*)d_in[20];
    const float* o2w  = (const float*)d_in[21];
    const float* o2b  = (const float*)d_in[22];

    float* outp     = (float*)d_out;
    float* attn_out = outp + (size_t)Bd*Ld*2;

    __nv_bfloat16* p_hh   = (__nv_bfloat16*)symaddr(g_hhi);
    __nv_bfloat16* p_hl   = (__nv_bfloat16*)symaddr(g_hlo);
    __nv_bfloat16* p_qkvh = (__nv_bfloat16*)symaddr(g_qkvh);
    __nv_bfloat16* p_qkvl = (__nv_bfloat16*)symaddr(g_qkvl);
    __nv_bfloat16* p_oh   = (__nv_bfloat16*)symaddr(g_ohi);
    __nv_bfloat16* p_ol   = (__nv_bfloat16*)symaddr(g_olo);
    __nv_bfloat16* p_fh   = (__nv_bfloat16*)symaddr(g_fhi);
    __nv_bfloat16* p_fl   = (__nv_bfloat16*)symaddr(g_flo);
    float*         p_tmp  = (float*)symaddr(g_tmp);
    __nv_bfloat16* p_owh  = (__nv_bfloat16*)symaddr(g_owh);
    __nv_bfloat16* p_owl  = (__nv_bfloat16*)symaddr(g_owl);
    __nv_bfloat16* p_f1h  = (__nv_bfloat16*)symaddr(g_f1wh);
    __nv_bfloat16* p_f1l  = (__nv_bfloat16*)symaddr(g_f1wl);
    __nv_bfloat16* p_f2h  = (__nv_bfloat16*)symaddr(g_f2wh);
    __nv_bfloat16* p_f2l  = (__nv_bfloat16*)symaddr(g_f2wl);
    __nv_bfloat16* p_o1h  = (__nv_bfloat16*)symaddr(g_o1wh);
    __nv_bfloat16* p_o1l  = (__nv_bfloat16*)symaddr(g_o1wl);

    const int SM_G256 = 384*(256+8)*2;
    const int SM_G128 = 384*(128+8)*2;
    const int SM_G64  = 384*(64+8)*2;

    cudaFuncSetAttribute(gemm_qkv, cudaFuncAttributeMaxDynamicSharedMemorySize, SM_G256);
    cudaFuncSetAttribute(gemm_bias<256,true ,false,true >, cudaFuncAttributeMaxDynamicSharedMemorySize, SM_G256);
    cudaFuncSetAttribute(gemm_bias<256,false,true ,true >, cudaFuncAttributeMaxDynamicSharedMemorySize, SM_G256);
    cudaFuncSetAttribute(gemm_bias<128,false,true ,false>, cudaFuncAttributeMaxDynamicSharedMemorySize, SM_G128);
    cudaFuncSetAttribute(gemm_bias<64 ,false,true ,false>, cudaFuncAttributeMaxDynamicSharedMemorySize, SM_G64);
    cudaFuncSetAttribute(attn_kernel, cudaFuncAttributeMaxDynamicSharedMemorySize, SM_ATTN_BYTES);

    convert_w<<<384, 256>>>(qw, kw, vw, ow, f1w, f2w, o1w, qb, kb, vb);
    embed_kernel<<<BLd, Dd>>>(x, in_w, in_b);

    const dim3 gQKV (BLd/128, 6);
    const dim3 gProj(BLd/128, 4);   // N=256
    const dim3 gF1  (BLd/128, 1);   // N=64
    const dim3 gAttn((Ld + QT - 1)/QT, Bd*Hd);

    for (int i = 0; i < NLd; i++) {
        gemm_qkv<<<gQKV, 512, SM_G256>>>(i);

        attn_kernel<<<gAttn, 512, SM_ATTN_BYTES>>>(
            p_qkvh, p_qkvl,
            attn_out + (size_t)i*Bd*Hd*Ld*Ld, p_oh, p_ol);

        gemm_bias<128,false,true,false><<<gProj, 512, SM_G128>>>(
            p_oh, p_ol, p_owh + (size_t)i*128*Dd, p_owl + (size_t)i*128*Dd,
            ob + i*Dd, p_tmp, nullptr, nullptr, Dd);
        ln_kernel<<<BLd/8, 256>>>(p_tmp, n1g + i*Dd, n1b + i*Dd);

        gemm_bias<256,true,false,true><<<gF1, 512, SM_G256>>>(
            p_hh, p_hl, p_f1h + (size_t)i*Dd*FCd, p_f1l + (size_t)i*Dd*FCd,
            f1b + i*FCd, nullptr, p_fh, p_fl, FCd);
        gemm_bias<64,false,true,false><<<gProj, 512, SM_G64>>>(
            p_fh, p_fl, p_f2h + (size_t)i*FCd*Dd, p_f2l + (size_t)i*FCd*Dd,
            f2b + i*Dd, p_tmp, nullptr, nullptr, Dd);
        ln_kernel<<<BLd/8, 256>>>(p_tmp, n2g + i*Dd, n2b + i*Dd);
    }

    gemm_bias<256,false,true,true><<<gProj, 512, SM_G256>>>(
        p_hh, p_hl, p_o1h, p_o1l, o1b, p_tmp, nullptr, nullptr, Dd);
    head2_kernel<<<BLd/8, 256>>>(o2w, o2b, outp);
}

// round 8
// speedup vs baseline: 4.5235x; 1.0418x over previous
#include <cuda_runtime.h>
#include <cuda_bf16.h>
#include <stdint.h>

#define Bd  8
#define Ld  2016
#define Hd  4
#define DKd 32
#define Dd  256
#define FCd 64
#define NLd 3
#define BLd (Bd*Ld)          // 16128 tokens

#define SC2f 0.09016844005556f   // (1/sqrt(256)) * log2(e)
#define EPSLN 1e-5f

// ---------------------------------------------------------------------------
// Device scratch (no allocation allowed). hi/lo split bf16 pairs everywhere.
// ---------------------------------------------------------------------------
__device__ __align__(128) float          g_h    [BLd*Dd];
__device__ __align__(128) __nv_bfloat16  g_hhi  [BLd*Dd];
__device__ __align__(128) __nv_bfloat16  g_hlo  [BLd*Dd];
__device__ __align__(128) __nv_bfloat16  g_qkvh [3*BLd*128];
__device__ __align__(128) __nv_bfloat16  g_qkvl [3*BLd*128];
__device__ __align__(128) __nv_bfloat16  g_ohi  [BLd*128];
__device__ __align__(128) __nv_bfloat16  g_olo  [BLd*128];
__device__ __align__(128) float          g_tmp  [BLd*Dd];
__device__ __align__(128) __nv_bfloat16  g_fhi  [BLd*FCd];
__device__ __align__(128) __nv_bfloat16  g_flo  [BLd*FCd];
// split weights
__device__ __align__(128) __nv_bfloat16  g_qkvwh[NLd*3*Dd*128];
__device__ __align__(128) __nv_bfloat16  g_qkvwl[NLd*3*Dd*128];
__device__ __align__(128) float          g_qkvb [NLd*3*128];
__device__ __align__(128) __nv_bfloat16  g_owh  [NLd*128*Dd];
__device__ __align__(128) __nv_bfloat16  g_owl  [NLd*128*Dd];
__device__ __align__(128) __nv_bfloat16  g_f1wh [NLd*Dd*FCd];
__device__ __align__(128) __nv_bfloat16  g_f1wl [NLd*Dd*FCd];
__device__ __align__(128) __nv_bfloat16  g_f2wh [NLd*FCd*Dd];
__device__ __align__(128) __nv_bfloat16  g_f2wl [NLd*FCd*Dd];
__device__ __align__(128) __nv_bfloat16  g_o1wh [Dd*Dd];
__device__ __align__(128) __nv_bfloat16  g_o1wl [Dd*Dd];

// ---------------------------------------------------------------------------
// helpers
// ---------------------------------------------------------------------------
__device__ __forceinline__ void mma16816(float* d, const uint32_t* a,
                                         uint32_t b0, uint32_t b1) {
    asm volatile(
        "mma.sync.aligned.m16n8k16.row.col.f32.bf16.bf16.f32 "
        "{%0,%1,%2,%3}, {%4,%5,%6,%7}, {%8,%9}, {%0,%1,%2,%3};"
        : "+f"(d[0]), "+f"(d[1]), "+f"(d[2]), "+f"(d[3])
        : "r"(a[0]), "r"(a[1]), "r"(a[2]), "r"(a[3]), "r"(b0), "r"(b1));
}

__device__ __forceinline__ void ldsm4(uint32_t& r0, uint32_t& r1,
                                      uint32_t& r2, uint32_t& r3, uint32_t a) {
    asm volatile("ldmatrix.sync.aligned.m8n8.x4.shared.b16 {%0,%1,%2,%3}, [%4];"
        : "=r"(r0), "=r"(r1), "=r"(r2), "=r"(r3) : "r"(a));
}

__device__ __forceinline__ void ldsm4t(uint32_t& r0, uint32_t& r1,
                                       uint32_t& r2, uint32_t& r3, uint32_t a) {
    asm volatile("ldmatrix.sync.aligned.m8n8.x4.trans.shared.b16 {%0,%1,%2,%3}, [%4];"
        : "=r"(r0), "=r"(r1), "=r"(r2), "=r"(r3) : "r"(a));
}

__device__ __forceinline__ void cpa16(uint32_t dst, const void* src, int srcsize) {
    asm volatile("cp.async.cg.shared.global [%0], [%1], 16, %2;"
        :: "r"(dst), "l"(src), "r"(srcsize));
}
__device__ __forceinline__ void cpa_commit() {
    asm volatile("cp.async.commit_group;" ::: "memory");
}
template<int N>
__device__ __forceinline__ void cpa_wait() {
    asm volatile("cp.async.wait_group %0;" :: "n"(N) : "memory");
}

__device__ __forceinline__ float ex2(float x) {
    float y;
    asm("ex2.approx.ftz.f32 %0, %1;" : "=f"(y) : "f"(x));
    return y;
}

__device__ __forceinline__ uint32_t pk2(float x, float y) {
    __nv_bfloat162 t = __floats2bfloat162_rn(x, y);
    return *reinterpret_cast<uint32_t*>(&t);
}

__device__ __forceinline__ void fsplit(float v, __nv_bfloat16& hi, __nv_bfloat16& lo) {
    hi = __float2bfloat16(v);
    lo = __float2bfloat16(v - __bfloat162float(hi));
}

__device__ __forceinline__ void pksplit(float x, float y, uint32_t& hi, uint32_t& lo) {
    __nv_bfloat16 xh = __float2bfloat16(x), yh = __float2bfloat16(y);
    __nv_bfloat162 th; th.x = xh; th.y = yh;
    hi = *reinterpret_cast<uint32_t*>(&th);
    lo = pk2(x - __bfloat162float(xh), y - __bfloat162float(yh));
}

__device__ __forceinline__ void stcs2(float* p, float a, float b) {
    asm volatile("st.global.cs.v2.f32 [%0], {%1,%2};" :: "l"(p), "f"(a), "f"(b));
}

// ---------------------------------------------------------------------------
// Weight conversion fp32 -> bf16 hi/lo (+ QKV packing)
// ---------------------------------------------------------------------------
__global__ void convert_w(const float* __restrict__ qw, const float* __restrict__ kw,
                          const float* __restrict__ vw, const float* __restrict__ ow,
                          const float* __restrict__ f1w, const float* __restrict__ f2w,
                          const float* __restrict__ o1w,
                          const float* __restrict__ qb, const float* __restrict__ kb,
                          const float* __restrict__ vb) {
    int i = blockIdx.x * 256 + threadIdx.x;
    const int n1 = NLd*Dd*128;
    const int n3 = NLd*Dd*FCd;
    const int n5 = Dd*Dd;
    if (i < n1) {
        int l = i / (Dd*128), rem = i % (Dd*128);
        size_t b = (size_t)(l*3)*Dd*128 + rem;
        fsplit(qw[i], g_qkvwh[b],            g_qkvwl[b]);
        fsplit(kw[i], g_qkvwh[b + Dd*128],   g_qkvwl[b + Dd*128]);
        fsplit(vw[i], g_qkvwh[b + 2*Dd*128], g_qkvwl[b + 2*Dd*128]);
        fsplit(ow[i], g_owh[i], g_owl[i]);
    }
    if (i < n3) {
        fsplit(f1w[i], g_f1wh[i], g_f1wl[i]);
        fsplit(f2w[i], g_f2wh[i], g_f2wl[i]);
    }
    if (i < n5) fsplit(o1w[i], g_o1wh[i], g_o1wl[i]);
    if (i < NLd*128) {
        int l = i >> 7, n = i & 127;
        g_qkvb[(l*3+0)*128 + n] = qb[i];
        g_qkvb[(l*3+1)*128 + n] = kb[i];
        g_qkvb[(l*3+2)*128 + n] = vb[i];
    }
}

// ---------------------------------------------------------------------------
// Embed: h = x @ in_w + in_b (fp32 + split)
// ---------------------------------------------------------------------------
__global__ void embed_kernel(const float* __restrict__ x,
                             const float* __restrict__ in_w,
                             const float* __restrict__ in_b) {
    int t = blockIdx.x, d = threadIdx.x;
    float x0 = x[t*2], x1 = x[t*2+1];
    float v = fmaf(x0, in_w[d], fmaf(x1, in_w[Dd + d], in_b[d]));
    size_t ix = (size_t)t*Dd + d;
    g_h[ix] = v;
    fsplit(v, g_hhi[ix], g_hlo[ix]);
}

// ---------------------------------------------------------------------------
// GEMM core: tile 128x64, 512 threads (16 warps: 8 M x 2 N). 3-term split MMA.
// ---------------------------------------------------------------------------
template<int K, bool OUT_B16, bool OUT_F32, bool RELU>
__device__ __forceinline__ void gemm_body(
        const __nv_bfloat16* __restrict__ Ahi,
        const __nv_bfloat16* __restrict__ Alo,
        const __nv_bfloat16* __restrict__ Whi,
        const __nv_bfloat16* __restrict__ Wlo,
        const float* __restrict__ bias,
        float* __restrict__ outF,
        __nv_bfloat16* __restrict__ outBh,
        __nv_bfloat16* __restrict__ outBl,
        int N, int row0, int col0) {
    extern __shared__ __nv_bfloat16 sm[];
    constexpr int SA = K + 8;
    __nv_bfloat16* sAh = sm;
    __nv_bfloat16* sAl = sm + 128 * SA;
    __nv_bfloat16* sWh = sm + 256 * SA;
    __nv_bfloat16* sWl = sWh + 64 * SA;

    const int tid = threadIdx.x, lane = tid & 31, warp = tid >> 5;

    constexpr int AV = K / 8;
    #pragma unroll 2
    for (int i = tid; i < 128 * AV; i += 512) {
        int r = i / AV, c = (i % AV) * 8;
        size_t g = (size_t)(row0 + r)*K + c;
        *reinterpret_cast<uint4*>(&sAh[r*SA + c]) = *reinterpret_cast<const uint4*>(&Ahi[g]);
        *reinterpret_cast<uint4*>(&sAl[r*SA + c]) = *reinterpret_cast<const uint4*>(&Alo[g]);
    }
    #pragma unroll 2
    for (int i = tid; i < 64 * K / 4; i += 512) {
        int k = i >> 4, n4 = (i & 15) * 4;
        size_t g = (size_t)k*N + col0 + n4;
        uint2 wh = *reinterpret_cast<const uint2*>(&Whi[g]);
        uint2 wl = *reinterpret_cast<const uint2*>(&Wlo[g]);
        __nv_bfloat16 th[4]; *reinterpret_cast<uint2*>(th) = wh;
        __nv_bfloat16 tl[4]; *reinterpret_cast<uint2*>(tl) = wl;
        #pragma unroll
        for (int j = 0; j < 4; j++) {
            sWh[(n4+j)*SA + k] = th[j];
            sWl[(n4+j)*SA + k] = tl[j];
        }
    }
    __syncthreads();

    float acc[4][4];
    #pragma unroll
    for (int i = 0; i < 4; i++)
        #pragma unroll
        for (int j = 0; j < 4; j++) acc[i][j] = 0.f;

    const int mwarp = warp >> 1, nwarp = warp & 1;
    const int ar = mwarp*16 + (lane >> 2);
    const int ac = (lane & 3) * 2;
    #pragma unroll
    for (int kk = 0; kk < K/16; kk++) {
        uint32_t ah[4], al[4];
        {
            const __nv_bfloat16* pa = &sAh[ar*SA + kk*16 + ac];
            ah[0] = *(const uint32_t*)pa;
            ah[1] = *(const uint32_t*)(pa + 8*SA);
            ah[2] = *(const uint32_t*)(pa + 8);
            ah[3] = *(const uint32_t*)(pa + 8*SA + 8);
            const __nv_bfloat16* pl = &sAl[ar*SA + kk*16 + ac];
            al[0] = *(const uint32_t*)pl;
            al[1] = *(const uint32_t*)(pl + 8*SA);
            al[2] = *(const uint32_t*)(pl + 8);
            al[3] = *(const uint32_t*)(pl + 8*SA + 8);
        }
        #pragma unroll
        for (int nt = 0; nt < 4; nt++) {
            int nrow = nwarp*32 + nt*8 + (lane>>2);
            const __nv_bfloat16* pbh = &sWh[nrow*SA + kk*16 + ac];
            uint32_t bh0 = *(const uint32_t*)pbh;
            uint32_t bh1 = *(const uint32_t*)(pbh + 8);
            const __nv_bfloat16* pbl = &sWl[nrow*SA + kk*16 + ac];
            uint32_t bl0 = *(const uint32_t*)pbl;
            uint32_t bl1 = *(const uint32_t*)(pbl + 8);
            mma16816(acc[nt], ah, bh0, bh1);
            mma16816(acc[nt], al, bh0, bh1);
            mma16816(acc[nt], ah, bl0, bl1);
        }
    }

    const int orow = row0 + mwarp*16 + (lane >> 2);
    #pragma unroll
    for (int nt = 0; nt < 4; nt++) {
        int c = col0 + nwarp*32 + nt*8 + (lane & 3)*2;
        float b0v = bias[c], b1v = bias[c+1];
        #pragma unroll
        for (int half = 0; half < 2; half++) {
            int r = orow + half*8;
            float v0 = acc[nt][half*2+0] + b0v;
            float v1 = acc[nt][half*2+1] + b1v;
            if (RELU) { v0 = fmaxf(v0, 0.f); v1 = fmaxf(v1, 0.f); }
            size_t o = (size_t)r*N + c;
            if (OUT_F32) { outF[o] = v0; outF[o+1] = v1; }
            if (OUT_B16) {
                __nv_bfloat16 h0, l0, h1, l1;
                fsplit(v0, h0, l0);
                fsplit(v1, h1, l1);
                outBh[o] = h0; outBh[o+1] = h1;
                outBl[o] = l0; outBl[o+1] = l1;
            }
        }
    }
}

template<int K, bool OUT_B16, bool OUT_F32, bool RELU>
__global__ __launch_bounds__(512) void gemm_bias(
        const __nv_bfloat16* __restrict__ Ahi, const __nv_bfloat16* __restrict__ Alo,
        const __nv_bfloat16* __restrict__ Whi, const __nv_bfloat16* __restrict__ Wlo,
        const float* __restrict__ bias,
        float* __restrict__ outF,
        __nv_bfloat16* __restrict__ outBh, __nv_bfloat16* __restrict__ outBl,
        int N) {
    gemm_body<K, OUT_B16, OUT_F32, RELU>(Ahi, Alo, Whi, Wlo, bias, outF, outBh, outBl,
                                         N, blockIdx.x*128, blockIdx.y*64);
}

// Fused QKV: grid (126, 6); blockIdx.y selects (q/k/v, col-half)
__global__ __launch_bounds__(512) void gemm_qkv(int layer) {
    int sel = blockIdx.y >> 1;
    int col0 = (blockIdx.y & 1) * 64;
    const __nv_bfloat16* Whi = g_qkvwh + ((size_t)(layer*3 + sel))*Dd*128;
    const __nv_bfloat16* Wlo = g_qkvwl + ((size_t)(layer*3 + sel))*Dd*128;
    const float* bias = g_qkvb + (layer*3 + sel)*128;
    __nv_bfloat16* oh = g_qkvh + (size_t)sel*BLd*128;
    __nv_bfloat16* ol = g_qkvl + (size_t)sel*BLd*128;
    gemm_body<256, true, false, false>(g_hhi, g_hlo, Whi, Wlo, bias, nullptr, oh, ol,
                                       128, blockIdx.x*128, col0);
}

// ---------------------------------------------------------------------------
// Attention v4: 128-query tile, 256 threads (8 warps x 16 rows), 128-key
// chunks, cp.async double-buffered staging, ldmatrix fragments, Q from gmem.
// smem 80KB -> 2 CTAs/SM. Two passes, m=0, ex2-folded scale.
// Pass A: 2-term QK (drops Qh*Kl; only K_hi staged) -> row sums.
// Pass B: exact 3-term QK, P out (.cs), 3-term PV.
// Padding keys zfilled -> score exactly 0 -> exp exactly 1 -> subtract 32.
// ---------------------------------------------------------------------------
#define QT 128
#define KT 128
#define NCH 16
#define NPAD 32.0f            // 2048 - 2016 phantom keys, each contributing 1.0

#define KBUF 5120             // elements per buffer: 128*40
#define SM_ATTN_BYTES (8*KBUF*2)   // 81920

struct AttnSmem {
    uint32_t kh, kl, vh, vl;  // u32 shared-space base addresses
};

// Pass A: stage K_hi only (2-term pass A never reads K_lo)
__device__ __forceinline__ void stageKhi(const AttnSmem& S, int buf, int ch,
        const __nv_bfloat16* Kh, size_t base, int tid) {
    const int k0 = ch * KT;
    #pragma unroll
    for (int it = 0; it < 2; it++) {
        int o = tid + it*256;          // 512 transfers: 128 rows x 32 dims
        int r = o >> 2;
        int c = (o & 3) * 8;
        int s = k0 + r;
        bool ok = s < Ld;
        const __nv_bfloat16* src = Kh + base + (size_t)(ok ? s : 0)*128 + c;
        uint32_t dst = S.kh + (buf*KBUF + r*40 + c)*2;
        cpa16(dst, src, ok ? 16 : 0);
    }
}

__device__ __forceinline__ void stageK(const AttnSmem& S, int buf, int ch,
        const __nv_bfloat16* Kh, const __nv_bfloat16* Kl, size_t base, int tid) {
    const int k0 = ch * KT;
    #pragma unroll
    for (int it = 0; it < 4; it++) {
        int o = tid + it*256;          // 1024 transfers (hi+lo)
        int half = o >> 9;
        int r = (o & 511) >> 2;
        int c = (o & 3) * 8;
        int s = k0 + r;
        bool ok = s < Ld;
        const __nv_bfloat16* src = (half ? Kl : Kh) + base + (size_t)(ok ? s : 0)*128 + c;
        uint32_t dst = (half ? S.kl : S.kh) + (buf*KBUF + r*40 + c)*2;
        cpa16(dst, src, ok ? 16 : 0);
    }
}

__device__ __forceinline__ void stageV(const AttnSmem& S, int buf, int ch,
        const __nv_bfloat16* Vh, const __nv_bfloat16* Vl, size_t base, int tid) {
    const int k0 = ch * KT;
    #pragma unroll
    for (int it = 0; it < 4; it++) {
        int o = tid + it*256;
        int half = o >> 9;
        int r = (o & 511) >> 2;
        int c = (o & 3) * 8;
        int s = k0 + r;
        bool ok = s < Ld;
        const __nv_bfloat16* src = (half ? Vl : Vh) + base + (size_t)(ok ? s : 0)*128 + c;
        uint32_t dst = (half ? S.vl : S.vh) + (buf*KBUF + r*40 + c)*2;
        cpa16(dst, src, ok ? 16 : 0);
    }
}

// Pass A stats: 2-term QK (Qh*Kh + Ql*Kh)
__device__ __forceinline__ void qk_stats_chunk(
        uint32_t kh_u, int laneK,
        const uint32_t aqh[2][4], const uint32_t aql[2][4],
        float& s0, float& s1) {
    #pragma unroll 1
    for (int gq = 0; gq < 4; gq++) {
        float acc[4][4];
        #pragma unroll
        for (int i = 0; i < 4; i++)
            #pragma unroll
            for (int j = 0; j < 4; j++) acc[i][j] = 0.f;
        #pragma unroll
        for (int pair = 0; pair < 2; pair++) {
            int be = (gq*32 + pair*16)*40;
            #pragma unroll
            for (int kk = 0; kk < 2; kk++) {
                uint32_t bh0, bh1, bh2, bh3;
                uint32_t off = (be + kk*16 + laneK)*2;
                ldsm4(bh0, bh1, bh2, bh3, kh_u + off);
                mma16816(acc[pair*2  ], aqh[kk], bh0, bh1);
                mma16816(acc[pair*2  ], aql[kk], bh0, bh1);
                mma16816(acc[pair*2+1], aqh[kk], bh2, bh3);
                mma16816(acc[pair*2+1], aql[kk], bh2, bh3);
            }
        }
        #pragma unroll
        for (int nt = 0; nt < 4; nt++) {
            s0 += ex2(acc[nt][0]*SC2f) + ex2(acc[nt][1]*SC2f);
            s1 += ex2(acc[nt][2]*SC2f) + ex2(acc[nt][3]*SC2f);
        }
    }
}

template<bool MASK>
__device__ __forceinline__ void qk_emit_chunk(
        uint32_t kh_u, uint32_t kl_u, uint32_t vh_u, uint32_t vl_u,
        int laneK, int laneV,
        const uint32_t aqh[2][4], const uint32_t aql[2][4],
        int k0, int fc, float inv0, float inv1,
        float* prow0, float* prow1, bool wr0, bool wr1,
        float oacc[4][4]) {
    #pragma unroll 1
    for (int g = 0; g < 8; g++) {
        int kbe = g*16*40;
        float acc1[2][4], acc2[2][4];
        #pragma unroll
        for (int i = 0; i < 2; i++)
            #pragma unroll
            for (int j = 0; j < 4; j++) { acc1[i][j] = 0.f; acc2[i][j] = 0.f; }
        #pragma unroll
        for (int kk = 0; kk < 2; kk++) {
            uint32_t bh0, bh1, bh2, bh3, bl0, bl1, bl2, bl3;
            uint32_t off = (kbe + kk*16 + laneK)*2;
            ldsm4(bh0, bh1, bh2, bh3, kh_u + off);
            ldsm4(bl0, bl1, bl2, bl3, kl_u + off);
            mma16816(acc1[0], aqh[kk], bh0, bh1);
            mma16816(acc2[0], aql[kk], bh0, bh1);
            mma16816(acc2[0], aqh[kk], bl0, bl1);
            mma16816(acc1[1], aqh[kk], bh2, bh3);
            mma16816(acc2[1], aql[kk], bh2, bh3);
            mma16816(acc2[1], aqh[kk], bl2, bl3);
        }
        int colb = k0 + g*16 + fc;
        bool ok0 = !MASK || (colb < Ld);
        bool ok1 = !MASK || (colb + 8 < Ld);
        float p00 = ok0 ? ex2((acc1[0][0]+acc2[0][0])*SC2f)*inv0 : 0.f;
        float p01 = ok0 ? ex2((acc1[0][1]+acc2[0][1])*SC2f)*inv0 : 0.f;
        float p02 = ok0 ? ex2((acc1[0][2]+acc2[0][2])*SC2f)*inv1 : 0.f;
        float p03 = ok0 ? ex2((acc1[0][3]+acc2[0][3])*SC2f)*inv1 : 0.f;
        float p10 = ok1 ? ex2((acc1[1][0]+acc2[1][0])*SC2f)*inv0 : 0.f;
        float p11 = ok1 ? ex2((acc1[1][1]+acc2[1][1])*SC2f)*inv0 : 0.f;
        float p12 = ok1 ? ex2((acc1[1][2]+acc2[1][2])*SC2f)*inv1 : 0.f;
        float p13 = ok1 ? ex2((acc1[1][3]+acc2[1][3])*SC2f)*inv1 : 0.f;

        if (wr0) {
            if (ok0) stcs2(&prow0[colb],     p00, p01);
            if (ok1) stcs2(&prow0[colb + 8], p10, p11);
        }
        if (wr1) {
            if (ok0) stcs2(&prow1[colb],     p02, p03);
            if (ok1) stcs2(&prow1[colb + 8], p12, p13);
        }

        uint32_t ah[4], al[4];
        pksplit(p00, p01, ah[0], al[0]);
        pksplit(p02, p03, ah[1], al[1]);
        pksplit(p10, p11, ah[2], al[2]);
        pksplit(p12, p13, ah[3], al[3]);

        #pragma unroll
        for (int dp = 0; dp < 2; dp++) {
            uint32_t vb0, vb1, vb2, vb3, wl0, wl1, wl2, wl3;
            uint32_t off = (kbe + dp*16 + laneV)*2;
            ldsm4t(vb0, vb1, vb2, vb3, vh_u + off);
            ldsm4t(wl0, wl1, wl2, wl3, vl_u + off);
            mma16816(oacc[dp*2  ], ah, vb0, vb1);
            mma16816(oacc[dp*2  ], al, vb0, vb1);
            mma16816(oacc[dp*2  ], ah, wl0, wl1);
            mma16816(oacc[dp*2+1], ah, vb2, vb3);
            mma16816(oacc[dp*2+1], al, vb2, vb3);
            mma16816(oacc[dp*2+1], ah, wl2, wl3);
        }
    }
}

__global__ __launch_bounds__(256, 2) void attn_kernel(
        const __nv_bfloat16* __restrict__ qkvh,
        const __nv_bfloat16* __restrict__ qkvl,
        float* __restrict__ Pout,
        __nv_bfloat16* __restrict__ Oh, __nv_bfloat16* __restrict__ Ol) {
    extern __shared__ __nv_bfloat16 sm[];
    uint32_t sm_u = (uint32_t)__cvta_generic_to_shared(sm);
    AttnSmem S;
    S.kh = sm_u;
    S.kl = sm_u + 2*KBUF*2;
    S.vh = sm_u + 4*KBUF*2;
    S.vl = sm_u + 6*KBUF*2;

    const int tid = threadIdx.x, lane = tid & 31, warp = tid >> 5;
    const int bh = blockIdx.y;
    const int b  = bh >> 2, h = bh & 3;
    const int q0 = blockIdx.x * QT;
    const size_t base = ((size_t)b*Ld*Hd + h)*DKd;
    const __nv_bfloat16* Qh = qkvh;
    const __nv_bfloat16* Ql = qkvl;
    const __nv_bfloat16* Kh = qkvh + (size_t)BLd*128;
    const __nv_bfloat16* Kl = qkvl + (size_t)BLd*128;
    const __nv_bfloat16* Vh = qkvh + (size_t)2*BLd*128;
    const __nv_bfloat16* Vl = qkvl + (size_t)2*BLd*128;

    const int mrow = warp * 16;
    const int fr = lane >> 2, fc = (lane & 3) * 2;
    const int lr = lane & 7, sel = lane >> 3;
    const int laneK = ((sel>>1)*8 + lr)*40 + (sel&1)*8;
    const int laneV = ((sel&1)*8 + lr)*40 + (sel>>1)*8;

    // ---- Q fragments straight from gmem ----
    const int r0g = q0 + mrow + fr, r1g = r0g + 8;
    const bool q0ok = (r0g < Ld), q1ok = (r1g < Ld);
    uint32_t aqh[2][4], aql[2][4];
    #pragma unroll
    for (int kk = 0; kk < 2; kk++) {
        int c = kk*16 + fc;
        size_t g0 = base + (size_t)r0g*128 + c;
        size_t g1 = base + (size_t)r1g*128 + c;
        aqh[kk][0] = q0ok ? *(const uint32_t*)&Qh[g0]     : 0;
        aqh[kk][1] = q1ok ? *(const uint32_t*)&Qh[g1]     : 0;
        aqh[kk][2] = q0ok ? *(const uint32_t*)&Qh[g0 + 8] : 0;
        aqh[kk][3] = q1ok ? *(const uint32_t*)&Qh[g1 + 8] : 0;
        aql[kk][0] = q0ok ? *(const uint32_t*)&Ql[g0]     : 0;
        aql[kk][1] = q1ok ? *(const uint32_t*)&Ql[g1]     : 0;
        aql[kk][2] = q0ok ? *(const uint32_t*)&Ql[g0 + 8] : 0;
        aql[kk][3] = q1ok ? *(const uint32_t*)&Ql[g1 + 8] : 0;
    }

    float s0 = 0.f, s1 = 0.f;

    // ======== PASS A: row sums (K_hi only, double-buffered) ========
    stageKhi(S, 0, 0, Kh, base, tid); cpa_commit();
    stageKhi(S, 1, 1, Kh, base, tid); cpa_commit();
    #pragma unroll 1
    for (int ch = 0; ch < NCH; ch++) {
        if (ch < NCH-1) cpa_wait<1>(); else cpa_wait<0>();
        __syncthreads();
        int buf = ch & 1;
        qk_stats_chunk(S.kh + buf*KBUF*2, laneK, aqh, aql, s0, s1);
        __syncthreads();
        if (ch + 2 < NCH) { stageKhi(S, buf, ch+2, Kh, base, tid); cpa_commit(); }
    }

    // prologue for pass B overlaps the reduction
    stageK(S, 0, 0, Kh, Kl, base, tid);
    stageV(S, 0, 0, Vh, Vl, base, tid); cpa_commit();
    stageK(S, 1, 1, Kh, Kl, base, tid);
    stageV(S, 1, 1, Vh, Vl, base, tid); cpa_commit();

    s0 += __shfl_xor_sync(~0u, s0, 1);
    s0 += __shfl_xor_sync(~0u, s0, 2);
    s1 += __shfl_xor_sync(~0u, s1, 1);
    s1 += __shfl_xor_sync(~0u, s1, 2);
    // Remove phantom-key contributions: zfilled keys score exactly 0 -> exp = 1.
    s0 -= NPAD;
    s1 -= NPAD;
    const float inv0 = 1.f / s0, inv1 = 1.f / s1;

    // ======== PASS B: P out + PV ========
    float oacc[4][4];
    #pragma unroll
    for (int i = 0; i < 4; i++)
        #pragma unroll
        for (int j = 0; j < 4; j++) oacc[i][j] = 0.f;

    float* prow0 = &Pout[((size_t)bh*Ld + r0g)*Ld];
    float* prow1 = prow0 + 8*(size_t)Ld;

    #pragma unroll 1
    for (int ch = 0; ch < NCH; ch++) {
        if (ch < NCH-1) cpa_wait<1>(); else cpa_wait<0>();
        __syncthreads();
        int buf = ch & 1;
        uint32_t kh_u = S.kh + buf*KBUF*2, kl_u = S.kl + buf*KBUF*2;
        uint32_t vh_u = S.vh + buf*KBUF*2, vl_u = S.vl + buf*KBUF*2;
        if (ch < NCH-1)
            qk_emit_chunk<false>(kh_u, kl_u, vh_u, vl_u, laneK, laneV, aqh, aql,
                                 ch*KT, fc, inv0, inv1, prow0, prow1, q0ok, q1ok, oacc);
        else
            qk_emit_chunk<true >(kh_u, kl_u, vh_u, vl_u, laneK, laneV, aqh, aql,
                                 ch*KT, fc, inv0, inv1, prow0, prow1, q0ok, q1ok, oacc);
        __syncthreads();
        if (ch + 2 < NCH) {
            stageK(S, buf, ch+2, Kh, Kl, base, tid);
            stageV(S, buf, ch+2, Vh, Vl, base, tid);
            cpa_commit();
        }
    }

    // ---- write O (hi/lo) ----
    #pragma unroll
    for (int dt = 0; dt < 4; dt++) {
        int d = dt*8 + fc;
        if (q0ok) {
            size_t g = base + (size_t)r0g*128 + d;
            __nv_bfloat16 hh, ll;
            fsplit(oacc[dt][0], hh, ll); Oh[g]   = hh; Ol[g]   = ll;
            fsplit(oacc[dt][1], hh, ll); Oh[g+1] = hh; Ol[g+1] = ll;
        }
        if (q1ok) {
            size_t g = base + (size_t)r1g*128 + d;
            __nv_bfloat16 hh, ll;
            fsplit(oacc[dt][2], hh, ll); Oh[g]   = hh; Ol[g]   = ll;
            fsplit(oacc[dt][3], hh, ll); Oh[g+1] = hh; Ol[g+1] = ll;
        }
    }
}

// ---------------------------------------------------------------------------
// Fused residual + LayerNorm : h = LN(h + add) ; writes fp32 + split bf16
// ---------------------------------------------------------------------------
__global__ __launch_bounds__(256) void ln_kernel(const float* __restrict__ add,
                                                 const float* __restrict__ gam,
                                                 const float* __restrict__ bet) {
    int warp = threadIdx.x >> 5, lane = threadIdx.x & 31;
    int token = blockIdx.x * 8 + warp;
    const float* hp = &g_h[(size_t)token*Dd];
    const float* ap = &add[(size_t)token*Dd];
    float x[8], s = 0.f;
    #pragma unroll
    for (int j = 0; j < 8; j++) { x[j] = hp[lane*8 + j] + ap[lane*8 + j]; s += x[j]; }
    #pragma unroll
    for (int o = 16; o; o >>= 1) s += __shfl_xor_sync(~0u, s, o);
    float mean = s * (1.f/256.f);
    float v = 0.f;
    #pragma unroll
    for (int j = 0; j < 8; j++) { float d = x[j] - mean; v += d*d; }
    #pragma unroll
    for (int o = 16; o; o >>= 1) v += __shfl_xor_sync(~0u, v, o);
    float rstd = rsqrtf(v * (1.f/256.f) + EPSLN);
    float* op = &g_h[(size_t)token*Dd];
    #pragma unroll
    for (int j = 0; j < 8; j++) {
        int cix = lane*8 + j;
        float y = (x[j] - mean)*rstd*gam[cix] + bet[cix];
        op[cix] = y;
        size_t ix = (size_t)token*Dd + cix;
        __nv_bfloat16 hh, ll;
        fsplit(y, hh, ll);
        g_hhi[ix] = hh;
        g_hlo[ix] = ll;
    }
}

// ---------------------------------------------------------------------------
// Final head tail: out = relu_h(g_tmp fp32) @ o2w + o2b   (warp per token)
// ---------------------------------------------------------------------------
__global__ __launch_bounds__(256) void head2_kernel(const float* __restrict__ o2w,
                                                    const float* __restrict__ o2b,
                                                    float* __restrict__ out) {
    int warp = threadIdx.x >> 5, lane = threadIdx.x & 31;
    int token = blockIdx.x * 8 + warp;
    const float* hp = &g_tmp[(size_t)token*Dd];
    float a0 = 0.f, a1 = 0.f;
    #pragma unroll
    for (int j = 0; j < 8; j++) {
        int k = lane + j*32;
        float hv = hp[k];
        a0 = fmaf(hv, o2w[k*2],   a0);
        a1 = fmaf(hv, o2w[k*2+1], a1);
    }
    #pragma unroll
    for (int o = 16; o; o >>= 1) {
        a0 += __shfl_xor_sync(~0u, a0, o);
        a1 += __shfl_xor_sync(~0u, a1, o);
    }
    if (lane == 0) {
        out[(size_t)token*2]     = a0 + o2b[0];
        out[(size_t)token*2 + 1] = a1 + o2b[1];
    }
}

// ---------------------------------------------------------------------------
// Host orchestration
// ---------------------------------------------------------------------------
static inline void* symaddr(const void* s) {
    void* p = nullptr;
    cudaGetSymbolAddress(&p, s);
    return p;
}

extern "C" void kernel_launch(void* const* d_in, const int* in_sizes, int n_in,
                              void* d_out, int out_size) {
    const float* x    = (const float*)d_in[0];
    const float* in_w = (const float*)d_in[1];
    const float* in_b = (const float*)d_in[2];
    const float* qw   = (const float*)d_in[3];
    const float* qb   = (const float*)d_in[4];
    const float* kw   = (const float*)d_in[5];
    const float* kb   = (const float*)d_in[6];
    const float* vw   = (const float*)d_in[7];
    const float* vb   = (const float*)d_in[8];
    const float* ow   = (const float*)d_in[9];
    const float* ob   = (const float*)d_in[10];
    const float* f1w  = (const float*)d_in[11];
    const float* f1b  = (const float*)d_in[12];
    const float* f2w  = (const float*)d_in[13];
    const float* f2b  = (const float*)d_in[14];
    const float* n1g  = (const float*)d_in[15];
    const float* n1b  = (const float*)d_in[16];
    const float* n2g  = (const float*)d_in[17];
    const float* n2b  = (const float*)d_in[18];
    const float* o1w  = (const float*)d_in[19];
    const float* o1b  = (const float*)d_in[20];
    const float* o2w  = (const float*)d_in[21];
    const float* o2b  = (const float*)d_in[22];

    float* outp     = (float*)d_out;
    float* attn_out = outp + (size_t)Bd*Ld*2;

    __nv_bfloat16* p_hh   = (__nv_bfloat16*)symaddr(g_hhi);
    __nv_bfloat16* p_hl   = (__nv_bfloat16*)symaddr(g_hlo);
    __nv_bfloat16* p_qkvh = (__nv_bfloat16*)symaddr(g_qkvh);
    __nv_bfloat16* p_qkvl = (__nv_bfloat16*)symaddr(g_qkvl);
    __nv_bfloat16* p_oh   = (__nv_bfloat16*)symaddr(g_ohi);
    __nv_bfloat16* p_ol   = (__nv_bfloat16*)symaddr(g_olo);
    __nv_bfloat16* p_fh   = (__nv_bfloat16*)symaddr(g_fhi);
    __nv_bfloat16* p_fl   = (__nv_bfloat16*)symaddr(g_flo);
    float*         p_tmp  = (float*)symaddr(g_tmp);
    __nv_bfloat16* p_owh  = (__nv_bfloat16*)symaddr(g_owh);
    __nv_bfloat16* p_owl  = (__nv_bfloat16*)symaddr(g_owl);
    __nv_bfloat16* p_f1h  = (__nv_bfloat16*)symaddr(g_f1wh);
    __nv_bfloat16* p_f1l  = (__nv_bfloat16*)symaddr(g_f1wl);
    __nv_bfloat16* p_f2h  = (__nv_bfloat16*)symaddr(g_f2wh);
    __nv_bfloat16* p_f2l  = (__nv_bfloat16*)symaddr(g_f2wl);
    __nv_bfloat16* p_o1h  = (__nv_bfloat16*)symaddr(g_o1wh);
    __nv_bfloat16* p_o1l  = (__nv_bfloat16*)symaddr(g_o1wl);

    const int SM_G256 = 384*(256+8)*2;
    const int SM_G128 = 384*(128+8)*2;
    const int SM_G64  = 384*(64+8)*2;

    cudaFuncSetAttribute(gemm_qkv, cudaFuncAttributeMaxDynamicSharedMemorySize, SM_G256);
    cudaFuncSetAttribute(gemm_bias<256,true ,false,true >, cudaFuncAttributeMaxDynamicSharedMemorySize, SM_G256);
    cudaFuncSetAttribute(gemm_bias<256,false,true ,true >, cudaFuncAttributeMaxDynamicSharedMemorySize, SM_G256);
    cudaFuncSetAttribute(gemm_bias<128,false,true ,false>, cudaFuncAttributeMaxDynamicSharedMemorySize, SM_G128);
    cudaFuncSetAttribute(gemm_bias<64 ,false,true ,false>, cudaFuncAttributeMaxDynamicSharedMemorySize, SM_G64);
    cudaFuncSetAttribute(attn_kernel, cudaFuncAttributeMaxDynamicSharedMemorySize, SM_ATTN_BYTES);

    convert_w<<<384, 256>>>(qw, kw, vw, ow, f1w, f2w, o1w, qb, kb, vb);
    embed_kernel<<<BLd, Dd>>>(x, in_w, in_b);

    const dim3 gQKV (BLd/128, 6);
    const dim3 gProj(BLd/128, 4);   // N=256
    const dim3 gF1  (BLd/128, 1);   // N=64
    const dim3 gAttn((Ld + QT - 1)/QT, Bd*Hd);

    for (int i = 0; i < NLd; i++) {
        gemm_qkv<<<gQKV, 512, SM_G256>>>(i);

        attn_kernel<<<gAttn, 256, SM_ATTN_BYTES>>>(
            p_qkvh, p_qkvl,
            attn_out + (size_t)i*Bd*Hd*Ld*Ld, p_oh, p_ol);

        gemm_bias<128,false,true,false><<<gProj, 512, SM_G128>>>(
            p_oh, p_ol, p_owh + (size_t)i*128*Dd, p_owl + (size_t)i*128*Dd,
            ob + i*Dd, p_tmp, nullptr, nullptr, Dd);
        ln_kernel<<<BLd/8, 256>>>(p_tmp, n1g + i*Dd, n1b + i*Dd);

        gemm_bias<256,true,false,true><<<gF1, 512, SM_G256>>>(
            p_hh, p_hl, p_f1h + (size_t)i*Dd*FCd, p_f1l + (size_t)i*Dd*FCd,
            f1b + i*FCd, nullptr, p_fh, p_fl, FCd);
        gemm_bias<64,false,true,false><<<gProj, 512, SM_G64>>>(
            p_fh, p_fl, p_f2h + (size_t)i*FCd*Dd, p_f2l + (size_t)i*FCd*Dd,
            f2b + i*Dd, p_tmp, nullptr, nullptr, Dd);
        ln_kernel<<<BLd/8, 256>>>(p_tmp, n2g + i*Dd, n2b + i*Dd);
    }

    gemm_bias<256,false,true,true><<<gProj, 512, SM_G256>>>(
        p_hh, p_hl, p_o1h, p_o1l, o1b, p_tmp, nullptr, nullptr, Dd);
    head2_kernel<<<BLd/8, 256>>>(o2w, o2b, outp);
}

// round 9
// speedup vs baseline: 4.5782x; 1.0121x over previous
#include <cuda_runtime.h>
#include <cuda_bf16.h>
#include <stdint.h>

#define Bd  8
#define Ld  2016
#define Hd  4
#define DKd 32
#define Dd  256
#define FCd 64
#define NLd 3
#define BLd (Bd*Ld)          // 16128 tokens

#define SC2f 0.09016844005556f   // (1/sqrt(256)) * log2(e)
#define EPSLN 1e-5f

// ---------------------------------------------------------------------------
// Device scratch (no allocation allowed). hi/lo split bf16 pairs everywhere.
// ---------------------------------------------------------------------------
__device__ __align__(128) float          g_h    [BLd*Dd];
__device__ __align__(128) __nv_bfloat16  g_hhi  [BLd*Dd];
__device__ __align__(128) __nv_bfloat16  g_hlo  [BLd*Dd];
__device__ __align__(128) __nv_bfloat16  g_qkvh [3*BLd*128];
__device__ __align__(128) __nv_bfloat16  g_qkvl [3*BLd*128];
__device__ __align__(128) __nv_bfloat16  g_ohi  [BLd*128];
__device__ __align__(128) __nv_bfloat16  g_olo  [BLd*128];
__device__ __align__(128) float          g_tmp  [BLd*Dd];
__device__ __align__(128) __nv_bfloat16  g_fhi  [BLd*FCd];
__device__ __align__(128) __nv_bfloat16  g_flo  [BLd*FCd];
// split weights
__device__ __align__(128) __nv_bfloat16  g_qkvwh[NLd*3*Dd*128];
__device__ __align__(128) __nv_bfloat16  g_qkvwl[NLd*3*Dd*128];
__device__ __align__(128) float          g_qkvb [NLd*3*128];
__device__ __align__(128) __nv_bfloat16  g_owh  [NLd*128*Dd];
__device__ __align__(128) __nv_bfloat16  g_owl  [NLd*128*Dd];
__device__ __align__(128) __nv_bfloat16  g_f1wh [NLd*Dd*FCd];
__device__ __align__(128) __nv_bfloat16  g_f1wl [NLd*Dd*FCd];
__device__ __align__(128) __nv_bfloat16  g_f2wh [NLd*FCd*Dd];
__device__ __align__(128) __nv_bfloat16  g_f2wl [NLd*FCd*Dd];
__device__ __align__(128) __nv_bfloat16  g_o1wh [Dd*Dd];
__device__ __align__(128) __nv_bfloat16  g_o1wl [Dd*Dd];

// ---------------------------------------------------------------------------
// helpers
// ---------------------------------------------------------------------------
__device__ __forceinline__ void mma16816(float* d, const uint32_t* a,
                                         uint32_t b0, uint32_t b1) {
    asm volatile(
        "mma.sync.aligned.m16n8k16.row.col.f32.bf16.bf16.f32 "
        "{%0,%1,%2,%3}, {%4,%5,%6,%7}, {%8,%9}, {%0,%1,%2,%3};"
        : "+f"(d[0]), "+f"(d[1]), "+f"(d[2]), "+f"(d[3])
        : "r"(a[0]), "r"(a[1]), "r"(a[2]), "r"(a[3]), "r"(b0), "r"(b1));
}

__device__ __forceinline__ void ldsm4(uint32_t& r0, uint32_t& r1,
                                      uint32_t& r2, uint32_t& r3, uint32_t a) {
    asm volatile("ldmatrix.sync.aligned.m8n8.x4.shared.b16 {%0,%1,%2,%3}, [%4];"
        : "=r"(r0), "=r"(r1), "=r"(r2), "=r"(r3) : "r"(a));
}

__device__ __forceinline__ void ldsm4t(uint32_t& r0, uint32_t& r1,
                                       uint32_t& r2, uint32_t& r3, uint32_t a) {
    asm volatile("ldmatrix.sync.aligned.m8n8.x4.trans.shared.b16 {%0,%1,%2,%3}, [%4];"
        : "=r"(r0), "=r"(r1), "=r"(r2), "=r"(r3) : "r"(a));
}

__device__ __forceinline__ void cpa16(uint32_t dst, const void* src, int srcsize) {
    asm volatile("cp.async.cg.shared.global [%0], [%1], 16, %2;"
        :: "r"(dst), "l"(src), "r"(srcsize));
}
__device__ __forceinline__ void cpa_commit() {
    asm volatile("cp.async.commit_group;" ::: "memory");
}
template<int N>
__device__ __forceinline__ void cpa_wait() {
    asm volatile("cp.async.wait_group %0;" :: "n"(N) : "memory");
}

__device__ __forceinline__ float ex2(float x) {
    float y;
    asm("ex2.approx.ftz.f32 %0, %1;" : "=f"(y) : "f"(x));
    return y;
}

__device__ __forceinline__ uint32_t pk2(float x, float y) {
    __nv_bfloat162 t = __floats2bfloat162_rn(x, y);
    return *reinterpret_cast<uint32_t*>(&t);
}

__device__ __forceinline__ void fsplit(float v, __nv_bfloat16& hi, __nv_bfloat16& lo) {
    hi = __float2bfloat16(v);
    lo = __float2bfloat16(v - __bfloat162float(hi));
}

__device__ __forceinline__ void pksplit(float x, float y, uint32_t& hi, uint32_t& lo) {
    __nv_bfloat16 xh = __float2bfloat16(x), yh = __float2bfloat16(y);
    __nv_bfloat162 th; th.x = xh; th.y = yh;
    hi = *reinterpret_cast<uint32_t*>(&th);
    lo = pk2(x - __bfloat162float(xh), y - __bfloat162float(yh));
}

__device__ __forceinline__ void stcs2(float* p, float a, float b) {
    asm volatile("st.global.cs.v2.f32 [%0], {%1,%2};" :: "l"(p), "f"(a), "f"(b));
}

// ---------------------------------------------------------------------------
// Weight conversion fp32 -> bf16 hi/lo (+ QKV packing)
// ---------------------------------------------------------------------------
__global__ void convert_w(const float* __restrict__ qw, const float* __restrict__ kw,
                          const float* __restrict__ vw, const float* __restrict__ ow,
                          const float* __restrict__ f1w, const float* __restrict__ f2w,
                          const float* __restrict__ o1w,
                          const float* __restrict__ qb, const float* __restrict__ kb,
                          const float* __restrict__ vb) {
    int i = blockIdx.x * 256 + threadIdx.x;
    const int n1 = NLd*Dd*128;
    const int n3 = NLd*Dd*FCd;
    const int n5 = Dd*Dd;
    if (i < n1) {
        int l = i / (Dd*128), rem = i % (Dd*128);
        size_t b = (size_t)(l*3)*Dd*128 + rem;
        fsplit(qw[i], g_qkvwh[b],            g_qkvwl[b]);
        fsplit(kw[i], g_qkvwh[b + Dd*128],   g_qkvwl[b + Dd*128]);
        fsplit(vw[i], g_qkvwh[b + 2*Dd*128], g_qkvwl[b + 2*Dd*128]);
        fsplit(ow[i], g_owh[i], g_owl[i]);
    }
    if (i < n3) {
        fsplit(f1w[i], g_f1wh[i], g_f1wl[i]);
        fsplit(f2w[i], g_f2wh[i], g_f2wl[i]);
    }
    if (i < n5) fsplit(o1w[i], g_o1wh[i], g_o1wl[i]);
    if (i < NLd*128) {
        int l = i >> 7, n = i & 127;
        g_qkvb[(l*3+0)*128 + n] = qb[i];
        g_qkvb[(l*3+1)*128 + n] = kb[i];
        g_qkvb[(l*3+2)*128 + n] = vb[i];
    }
}

// ---------------------------------------------------------------------------
// Embed: h = x @ in_w + in_b (fp32 + split)
// ---------------------------------------------------------------------------
__global__ void embed_kernel(const float* __restrict__ x,
                             const float* __restrict__ in_w,
                             const float* __restrict__ in_b) {
    int t = blockIdx.x, d = threadIdx.x;
    float x0 = x[t*2], x1 = x[t*2+1];
    float v = fmaf(x0, in_w[d], fmaf(x1, in_w[Dd + d], in_b[d]));
    size_t ix = (size_t)t*Dd + d;
    g_h[ix] = v;
    fsplit(v, g_hhi[ix], g_hlo[ix]);
}

// ---------------------------------------------------------------------------
// GEMM core: tile 128x64, 512 threads (16 warps: 8 M x 2 N). 3-term split MMA.
// ---------------------------------------------------------------------------
template<int K, bool OUT_B16, bool OUT_F32, bool RELU>
__device__ __forceinline__ void gemm_body(
        const __nv_bfloat16* __restrict__ Ahi,
        const __nv_bfloat16* __restrict__ Alo,
        const __nv_bfloat16* __restrict__ Whi,
        const __nv_bfloat16* __restrict__ Wlo,
        const float* __restrict__ bias,
        float* __restrict__ outF,
        __nv_bfloat16* __restrict__ outBh,
        __nv_bfloat16* __restrict__ outBl,
        int N, int row0, int col0) {
    extern __shared__ __nv_bfloat16 sm[];
    constexpr int SA = K + 8;
    __nv_bfloat16* sAh = sm;
    __nv_bfloat16* sAl = sm + 128 * SA;
    __nv_bfloat16* sWh = sm + 256 * SA;
    __nv_bfloat16* sWl = sWh + 64 * SA;

    const int tid = threadIdx.x, lane = tid & 31, warp = tid >> 5;

    constexpr int AV = K / 8;
    #pragma unroll 2
    for (int i = tid; i < 128 * AV; i += 512) {
        int r = i / AV, c = (i % AV) * 8;
        size_t g = (size_t)(row0 + r)*K + c;
        *reinterpret_cast<uint4*>(&sAh[r*SA + c]) = *reinterpret_cast<const uint4*>(&Ahi[g]);
        *reinterpret_cast<uint4*>(&sAl[r*SA + c]) = *reinterpret_cast<const uint4*>(&Alo[g]);
    }
    #pragma unroll 2
    for (int i = tid; i < 64 * K / 4; i += 512) {
        int k = i >> 4, n4 = (i & 15) * 4;
        size_t g = (size_t)k*N + col0 + n4;
        uint2 wh = *reinterpret_cast<const uint2*>(&Whi[g]);
        uint2 wl = *reinterpret_cast<const uint2*>(&Wlo[g]);
        __nv_bfloat16 th[4]; *reinterpret_cast<uint2*>(th) = wh;
        __nv_bfloat16 tl[4]; *reinterpret_cast<uint2*>(tl) = wl;
        #pragma unroll
        for (int j = 0; j < 4; j++) {
            sWh[(n4+j)*SA + k] = th[j];
            sWl[(n4+j)*SA + k] = tl[j];
        }
    }
    __syncthreads();

    float acc[4][4];
    #pragma unroll
    for (int i = 0; i < 4; i++)
        #pragma unroll
        for (int j = 0; j < 4; j++) acc[i][j] = 0.f;

    const int mwarp = warp >> 1, nwarp = warp & 1;
    const int ar = mwarp*16 + (lane >> 2);
    const int ac = (lane & 3) * 2;
    #pragma unroll
    for (int kk = 0; kk < K/16; kk++) {
        uint32_t ah[4], al[4];
        {
            const __nv_bfloat16* pa = &sAh[ar*SA + kk*16 + ac];
            ah[0] = *(const uint32_t*)pa;
            ah[1] = *(const uint32_t*)(pa + 8*SA);
            ah[2] = *(const uint32_t*)(pa + 8);
            ah[3] = *(const uint32_t*)(pa + 8*SA + 8);
            const __nv_bfloat16* pl = &sAl[ar*SA + kk*16 + ac];
            al[0] = *(const uint32_t*)pl;
            al[1] = *(const uint32_t*)(pl + 8*SA);
            al[2] = *(const uint32_t*)(pl + 8);
            al[3] = *(const uint32_t*)(pl + 8*SA + 8);
        }
        #pragma unroll
        for (int nt = 0; nt < 4; nt++) {
            int nrow = nwarp*32 + nt*8 + (lane>>2);
            const __nv_bfloat16* pbh = &sWh[nrow*SA + kk*16 + ac];
            uint32_t bh0 = *(const uint32_t*)pbh;
            uint32_t bh1 = *(const uint32_t*)(pbh + 8);
            const __nv_bfloat16* pbl = &sWl[nrow*SA + kk*16 + ac];
            uint32_t bl0 = *(const uint32_t*)pbl;
            uint32_t bl1 = *(const uint32_t*)(pbl + 8);
            mma16816(acc[nt], ah, bh0, bh1);
            mma16816(acc[nt], al, bh0, bh1);
            mma16816(acc[nt], ah, bl0, bl1);
        }
    }

    const int orow = row0 + mwarp*16 + (lane >> 2);
    #pragma unroll
    for (int nt = 0; nt < 4; nt++) {
        int c = col0 + nwarp*32 + nt*8 + (lane & 3)*2;
        float b0v = bias[c], b1v = bias[c+1];
        #pragma unroll
        for (int half = 0; half < 2; half++) {
            int r = orow + half*8;
            float v0 = acc[nt][half*2+0] + b0v;
            float v1 = acc[nt][half*2+1] + b1v;
            if (RELU) { v0 = fmaxf(v0, 0.f); v1 = fmaxf(v1, 0.f); }
            size_t o = (size_t)r*N + c;
            if (OUT_F32) { outF[o] = v0; outF[o+1] = v1; }
            if (OUT_B16) {
                __nv_bfloat16 h0, l0, h1, l1;
                fsplit(v0, h0, l0);
                fsplit(v1, h1, l1);
                outBh[o] = h0; outBh[o+1] = h1;
                outBl[o] = l0; outBl[o+1] = l1;
            }
        }
    }
}

template<int K, bool OUT_B16, bool OUT_F32, bool RELU>
__global__ __launch_bounds__(512) void gemm_bias(
        const __nv_bfloat16* __restrict__ Ahi, const __nv_bfloat16* __restrict__ Alo,
        const __nv_bfloat16* __restrict__ Whi, const __nv_bfloat16* __restrict__ Wlo,
        const float* __restrict__ bias,
        float* __restrict__ outF,
        __nv_bfloat16* __restrict__ outBh, __nv_bfloat16* __restrict__ outBl,
        int N) {
    gemm_body<K, OUT_B16, OUT_F32, RELU>(Ahi, Alo, Whi, Wlo, bias, outF, outBh, outBl,
                                         N, blockIdx.x*128, blockIdx.y*64);
}

// Fused QKV: grid (126, 6); blockIdx.y selects (q/k/v, col-half)
__global__ __launch_bounds__(512) void gemm_qkv(int layer) {
    int sel = blockIdx.y >> 1;
    int col0 = (blockIdx.y & 1) * 64;
    const __nv_bfloat16* Whi = g_qkvwh + ((size_t)(layer*3 + sel))*Dd*128;
    const __nv_bfloat16* Wlo = g_qkvwl + ((size_t)(layer*3 + sel))*Dd*128;
    const float* bias = g_qkvb + (layer*3 + sel)*128;
    __nv_bfloat16* oh = g_qkvh + (size_t)sel*BLd*128;
    __nv_bfloat16* ol = g_qkvl + (size_t)sel*BLd*128;
    gemm_body<256, true, false, false>(g_hhi, g_hlo, Whi, Wlo, bias, nullptr, oh, ol,
                                       128, blockIdx.x*128, col0);
}

// ---------------------------------------------------------------------------
// Attention v5: 128-query tile, 256 threads (8 warps x 16 rows), 128-key
// chunks, cp.async double-buffered staging, ldmatrix fragments, Q from gmem
// with SCALE*log2e pre-folded (exp = ex2(acc) directly).
// Pass A: 2-term QK (K_hi only), unroll-2 for ILP. Pass B: exact 3-term QK
// with 2-stage software pipeline (QK of g+1 overlaps exp/PV of g), P out (.cs),
// 3-term PV. Zfilled padding keys -> score 0 -> exp 1 -> subtract 32.
// ---------------------------------------------------------------------------
#define QT 128
#define KT 128
#define NCH 16
#define NPAD 32.0f

#define KBUF 5120             // elements per buffer: 128*40
#define SM_ATTN_BYTES (8*KBUF*2)   // 81920

struct AttnSmem {
    uint32_t kh, kl, vh, vl;
};

__device__ __forceinline__ void stageKhi(const AttnSmem& S, int buf, int ch,
        const __nv_bfloat16* Kh, size_t base, int tid) {
    const int k0 = ch * KT;
    #pragma unroll
    for (int it = 0; it < 2; it++) {
        int o = tid + it*256;
        int r = o >> 2;
        int c = (o & 3) * 8;
        int s = k0 + r;
        bool ok = s < Ld;
        const __nv_bfloat16* src = Kh + base + (size_t)(ok ? s : 0)*128 + c;
        uint32_t dst = S.kh + (buf*KBUF + r*40 + c)*2;
        cpa16(dst, src, ok ? 16 : 0);
    }
}

__device__ __forceinline__ void stageK(const AttnSmem& S, int buf, int ch,
        const __nv_bfloat16* Kh, const __nv_bfloat16* Kl, size_t base, int tid) {
    const int k0 = ch * KT;
    #pragma unroll
    for (int it = 0; it < 4; it++) {
        int o = tid + it*256;
        int half = o >> 9;
        int r = (o & 511) >> 2;
        int c = (o & 3) * 8;
        int s = k0 + r;
        bool ok = s < Ld;
        const __nv_bfloat16* src = (half ? Kl : Kh) + base + (size_t)(ok ? s : 0)*128 + c;
        uint32_t dst = (half ? S.kl : S.kh) + (buf*KBUF + r*40 + c)*2;
        cpa16(dst, src, ok ? 16 : 0);
    }
}

__device__ __forceinline__ void stageV(const AttnSmem& S, int buf, int ch,
        const __nv_bfloat16* Vh, const __nv_bfloat16* Vl, size_t base, int tid) {
    const int k0 = ch * KT;
    #pragma unroll
    for (int it = 0; it < 4; it++) {
        int o = tid + it*256;
        int half = o >> 9;
        int r = (o & 511) >> 2;
        int c = (o & 3) * 8;
        int s = k0 + r;
        bool ok = s < Ld;
        const __nv_bfloat16* src = (half ? Vl : Vh) + base + (size_t)(ok ? s : 0)*128 + c;
        uint32_t dst = (half ? S.vl : S.vh) + (buf*KBUF + r*40 + c)*2;
        cpa16(dst, src, ok ? 16 : 0);
    }
}

// Pass A stats: 2-term QK (Qh*Kh + Ql*Kh); scores pre-scaled -> ex2 direct.
__device__ __forceinline__ void qk_stats_chunk(
        uint32_t kh_u, int laneK,
        const uint32_t aqh[2][4], const uint32_t aql[2][4],
        float& s0, float& s1) {
    #pragma unroll 2
    for (int gq = 0; gq < 4; gq++) {
        float acc[4][4];
        #pragma unroll
        for (int i = 0; i < 4; i++)
            #pragma unroll
            for (int j = 0; j < 4; j++) acc[i][j] = 0.f;
        #pragma unroll
        for (int pair = 0; pair < 2; pair++) {
            int be = (gq*32 + pair*16)*40;
            #pragma unroll
            for (int kk = 0; kk < 2; kk++) {
                uint32_t bh0, bh1, bh2, bh3;
                uint32_t off = (be + kk*16 + laneK)*2;
                ldsm4(bh0, bh1, bh2, bh3, kh_u + off);
                mma16816(acc[pair*2  ], aqh[kk], bh0, bh1);
                mma16816(acc[pair*2  ], aql[kk], bh0, bh1);
                mma16816(acc[pair*2+1], aqh[kk], bh2, bh3);
                mma16816(acc[pair*2+1], aql[kk], bh2, bh3);
            }
        }
        #pragma unroll
        for (int nt = 0; nt < 4; nt++) {
            s0 += ex2(acc[nt][0]) + ex2(acc[nt][1]);
            s1 += ex2(acc[nt][2]) + ex2(acc[nt][3]);
        }
    }
}

// Pass B: compute 3-term QK accs for one 16-key group.
__device__ __forceinline__ void qk_group(
        uint32_t kh_u, uint32_t kl_u, int laneK, int kbe,
        const uint32_t aqh[2][4], const uint32_t aql[2][4],
        float acc1[2][4], float acc2[2][4]) {
    #pragma unroll
    for (int i = 0; i < 2; i++)
        #pragma unroll
        for (int j = 0; j < 4; j++) { acc1[i][j] = 0.f; acc2[i][j] = 0.f; }
    #pragma unroll
    for (int kk = 0; kk < 2; kk++) {
        uint32_t bh0, bh1, bh2, bh3, bl0, bl1, bl2, bl3;
        uint32_t off = (kbe + kk*16 + laneK)*2;
        ldsm4(bh0, bh1, bh2, bh3, kh_u + off);
        ldsm4(bl0, bl1, bl2, bl3, kl_u + off);
        mma16816(acc1[0], aqh[kk], bh0, bh1);
        mma16816(acc2[0], aql[kk], bh0, bh1);
        mma16816(acc2[0], aqh[kk], bl0, bl1);
        mma16816(acc1[1], aqh[kk], bh2, bh3);
        mma16816(acc2[1], aql[kk], bh2, bh3);
        mma16816(acc2[1], aqh[kk], bl2, bl3);
    }
}

// Pass B: exp, store P, PV for one group (accs already computed).
template<bool MASK>
__device__ __forceinline__ void emit_group(
        uint32_t vh_u, uint32_t vl_u, int laneV, int g, int k0, int fc,
        float inv0, float inv1,
        float* prow0, float* prow1, bool wr0, bool wr1,
        const float acc1[2][4], const float acc2[2][4], float oacc[4][4]) {
    int kbe = g*16*40;
    int colb = k0 + g*16 + fc;
    bool ok0 = !MASK || (colb < Ld);
    bool ok1 = !MASK || (colb + 8 < Ld);
    float p00 = ok0 ? ex2(acc1[0][0]+acc2[0][0])*inv0 : 0.f;
    float p01 = ok0 ? ex2(acc1[0][1]+acc2[0][1])*inv0 : 0.f;
    float p02 = ok0 ? ex2(acc1[0][2]+acc2[0][2])*inv1 : 0.f;
    float p03 = ok0 ? ex2(acc1[0][3]+acc2[0][3])*inv1 : 0.f;
    float p10 = ok1 ? ex2(acc1[1][0]+acc2[1][0])*inv0 : 0.f;
    float p11 = ok1 ? ex2(acc1[1][1]+acc2[1][1])*inv0 : 0.f;
    float p12 = ok1 ? ex2(acc1[1][2]+acc2[1][2])*inv1 : 0.f;
    float p13 = ok1 ? ex2(acc1[1][3]+acc2[1][3])*inv1 : 0.f;

    if (wr0) {
        if (ok0) stcs2(&prow0[colb],     p00, p01);
        if (ok1) stcs2(&prow0[colb + 8], p10, p11);
    }
    if (wr1) {
        if (ok0) stcs2(&prow1[colb],     p02, p03);
        if (ok1) stcs2(&prow1[colb + 8], p12, p13);
    }

    uint32_t ah[4], al[4];
    pksplit(p00, p01, ah[0], al[0]);
    pksplit(p02, p03, ah[1], al[1]);
    pksplit(p10, p11, ah[2], al[2]);
    pksplit(p12, p13, ah[3], al[3]);

    #pragma unroll
    for (int dp = 0; dp < 2; dp++) {
        uint32_t vb0, vb1, vb2, vb3, wl0, wl1, wl2, wl3;
        uint32_t off = (kbe + dp*16 + laneV)*2;
        ldsm4t(vb0, vb1, vb2, vb3, vh_u + off);
        ldsm4t(wl0, wl1, wl2, wl3, vl_u + off);
        mma16816(oacc[dp*2  ], ah, vb0, vb1);
        mma16816(oacc[dp*2  ], al, vb0, vb1);
        mma16816(oacc[dp*2  ], ah, wl0, wl1);
        mma16816(oacc[dp*2+1], ah, vb2, vb3);
        mma16816(oacc[dp*2+1], al, vb2, vb3);
        mma16816(oacc[dp*2+1], ah, wl2, wl3);
    }
}

// Pass B chunk: 2-stage software pipeline over 8 groups.
template<bool MASK>
__device__ __forceinline__ void qk_emit_chunk(
        uint32_t kh_u, uint32_t kl_u, uint32_t vh_u, uint32_t vl_u,
        int laneK, int laneV,
        const uint32_t aqh[2][4], const uint32_t aql[2][4],
        int k0, int fc, float inv0, float inv1,
        float* prow0, float* prow1, bool wr0, bool wr1,
        float oacc[4][4]) {
    float a1A[2][4], a2A[2][4], a1B[2][4], a2B[2][4];
    qk_group(kh_u, kl_u, laneK, 0, aqh, aql, a1A, a2A);
    #pragma unroll
    for (int g = 0; g < 8; g += 2) {
        qk_group(kh_u, kl_u, laneK, (g+1)*640, aqh, aql, a1B, a2B);
        emit_group<MASK>(vh_u, vl_u, laneV, g, k0, fc, inv0, inv1,
                         prow0, prow1, wr0, wr1, a1A, a2A, oacc);
        if (g + 2 < 8)
            qk_group(kh_u, kl_u, laneK, (g+2)*640, aqh, aql, a1A, a2A);
        emit_group<MASK>(vh_u, vl_u, laneV, g+1, k0, fc, inv0, inv1,
                         prow0, prow1, wr0, wr1, a1B, a2B, oacc);
    }
}

__global__ __launch_bounds__(256, 2) void attn_kernel(
        const __nv_bfloat16* __restrict__ qkvh,
        const __nv_bfloat16* __restrict__ qkvl,
        float* __restrict__ Pout,
        __nv_bfloat16* __restrict__ Oh, __nv_bfloat16* __restrict__ Ol) {
    extern __shared__ __nv_bfloat16 sm[];
    uint32_t sm_u = (uint32_t)__cvta_generic_to_shared(sm);
    AttnSmem S;
    S.kh = sm_u;
    S.kl = sm_u + 2*KBUF*2;
    S.vh = sm_u + 4*KBUF*2;
    S.vl = sm_u + 6*KBUF*2;

    const int tid = threadIdx.x, lane = tid & 31, warp = tid >> 5;
    const int bh = blockIdx.y;
    const int b  = bh >> 2, h = bh & 3;
    const int q0 = blockIdx.x * QT;
    const size_t base = ((size_t)b*Ld*Hd + h)*DKd;
    const __nv_bfloat16* Qh = qkvh;
    const __nv_bfloat16* Ql = qkvl;
    const __nv_bfloat16* Kh = qkvh + (size_t)BLd*128;
    const __nv_bfloat16* Kl = qkvl + (size_t)BLd*128;
    const __nv_bfloat16* Vh = qkvh + (size_t)2*BLd*128;
    const __nv_bfloat16* Vl = qkvl + (size_t)2*BLd*128;

    const int mrow = warp * 16;
    const int fr = lane >> 2, fc = (lane & 3) * 2;
    const int lr = lane & 7, sel = lane >> 3;
    const int laneK = ((sel>>1)*8 + lr)*40 + (sel&1)*8;
    const int laneV = ((sel&1)*8 + lr)*40 + (sel>>1)*8;

    // ---- Q fragments from gmem, with SCALE*log2e folded in (re-split) ----
    const int r0g = q0 + mrow + fr, r1g = r0g + 8;
    const bool q0ok = (r0g < Ld), q1ok = (r1g < Ld);
    uint32_t aqh[2][4], aql[2][4];
    #pragma unroll
    for (int kk = 0; kk < 2; kk++) {
        int c = kk*16 + fc;
        size_t g0 = base + (size_t)r0g*128 + c;
        size_t g1 = base + (size_t)r1g*128 + c;
        aqh[kk][0] = q0ok ? *(const uint32_t*)&Qh[g0]     : 0;
        aqh[kk][1] = q1ok ? *(const uint32_t*)&Qh[g1]     : 0;
        aqh[kk][2] = q0ok ? *(const uint32_t*)&Qh[g0 + 8] : 0;
        aqh[kk][3] = q1ok ? *(const uint32_t*)&Qh[g1 + 8] : 0;
        aql[kk][0] = q0ok ? *(const uint32_t*)&Ql[g0]     : 0;
        aql[kk][1] = q1ok ? *(const uint32_t*)&Ql[g1]     : 0;
        aql[kk][2] = q0ok ? *(const uint32_t*)&Ql[g0 + 8] : 0;
        aql[kk][3] = q1ok ? *(const uint32_t*)&Ql[g1 + 8] : 0;
    }
    #pragma unroll
    for (int kk = 0; kk < 2; kk++) {
        #pragma unroll
        for (int j = 0; j < 4; j++) {
            __nv_bfloat162 h2 = *reinterpret_cast<__nv_bfloat162*>(&aqh[kk][j]);
            __nv_bfloat162 l2 = *reinterpret_cast<__nv_bfloat162*>(&aql[kk][j]);
            float x0 = (__bfloat162float(h2.x) + __bfloat162float(l2.x)) * SC2f;
            float x1 = (__bfloat162float(h2.y) + __bfloat162float(l2.y)) * SC2f;
            pksplit(x0, x1, aqh[kk][j], aql[kk][j]);
        }
    }

    float s0 = 0.f, s1 = 0.f;

    // ======== PASS A: row sums (K_hi only, double-buffered) ========
    stageKhi(S, 0, 0, Kh, base, tid); cpa_commit();
    stageKhi(S, 1, 1, Kh, base, tid); cpa_commit();
    #pragma unroll 1
    for (int ch = 0; ch < NCH; ch++) {
        if (ch < NCH-1) cpa_wait<1>(); else cpa_wait<0>();
        __syncthreads();
        int buf = ch & 1;
        qk_stats_chunk(S.kh + buf*KBUF*2, laneK, aqh, aql, s0, s1);
        __syncthreads();
        if (ch + 2 < NCH) { stageKhi(S, buf, ch+2, Kh, base, tid); cpa_commit(); }
    }

    // prologue for pass B overlaps the reduction
    stageK(S, 0, 0, Kh, Kl, base, tid);
    stageV(S, 0, 0, Vh, Vl, base, tid); cpa_commit();
    stageK(S, 1, 1, Kh, Kl, base, tid);
    stageV(S, 1, 1, Vh, Vl, base, tid); cpa_commit();

    s0 += __shfl_xor_sync(~0u, s0, 1);
    s0 += __shfl_xor_sync(~0u, s0, 2);
    s1 += __shfl_xor_sync(~0u, s1, 1);
    s1 += __shfl_xor_sync(~0u, s1, 2);
    s0 -= NPAD;
    s1 -= NPAD;
    const float inv0 = 1.f / s0, inv1 = 1.f / s1;

    // ======== PASS B: P out + PV ========
    float oacc[4][4];
    #pragma unroll
    for (int i = 0; i < 4; i++)
        #pragma unroll
        for (int j = 0; j < 4; j++) oacc[i][j] = 0.f;

    float* prow0 = &Pout[((size_t)bh*Ld + r0g)*Ld];
    float* prow1 = prow0 + 8*(size_t)Ld;

    #pragma unroll 1
    for (int ch = 0; ch < NCH; ch++) {
        if (ch < NCH-1) cpa_wait<1>(); else cpa_wait<0>();
        __syncthreads();
        int buf = ch & 1;
        uint32_t kh_u = S.kh + buf*KBUF*2, kl_u = S.kl + buf*KBUF*2;
        uint32_t vh_u = S.vh + buf*KBUF*2, vl_u = S.vl + buf*KBUF*2;
        if (ch < NCH-1)
            qk_emit_chunk<false>(kh_u, kl_u, vh_u, vl_u, laneK, laneV, aqh, aql,
                                 ch*KT, fc, inv0, inv1, prow0, prow1, q0ok, q1ok, oacc);
        else
            qk_emit_chunk<true >(kh_u, kl_u, vh_u, vl_u, laneK, laneV, aqh, aql,
                                 ch*KT, fc, inv0, inv1, prow0, prow1, q0ok, q1ok, oacc);
        __syncthreads();
        if (ch + 2 < NCH) {
            stageK(S, buf, ch+2, Kh, Kl, base, tid);
            stageV(S, buf, ch+2, Vh, Vl, base, tid);
            cpa_commit();
        }
    }

    // ---- write O (hi/lo) ----
    #pragma unroll
    for (int dt = 0; dt < 4; dt++) {
        int d = dt*8 + fc;
        if (q0ok) {
            size_t g = base + (size_t)r0g*128 + d;
            __nv_bfloat16 hh, ll;
            fsplit(oacc[dt][0], hh, ll); Oh[g]   = hh; Ol[g]   = ll;
            fsplit(oacc[dt][1], hh, ll); Oh[g+1] = hh; Ol[g+1] = ll;
        }
        if (q1ok) {
            size_t g = base + (size_t)r1g*128 + d;
            __nv_bfloat16 hh, ll;
            fsplit(oacc[dt][2], hh, ll); Oh[g]   = hh; Ol[g]   = ll;
            fsplit(oacc[dt][3], hh, ll); Oh[g+1] = hh; Ol[g+1] = ll;
        }
    }
}

// ---------------------------------------------------------------------------
// Fused residual + LayerNorm : h = LN(h + add) ; writes fp32 + split bf16
// ---------------------------------------------------------------------------
__global__ __launch_bounds__(256) void ln_kernel(const float* __restrict__ add,
                                                 const float* __restrict__ gam,
                                                 const float* __restrict__ bet) {
    int warp = threadIdx.x >> 5, lane = threadIdx.x & 31;
    int token = blockIdx.x * 8 + warp;
    const float* hp = &g_h[(size_t)token*Dd];
    const float* ap = &add[(size_t)token*Dd];
    float x[8], s = 0.f;
    #pragma unroll
    for (int j = 0; j < 8; j++) { x[j] = hp[lane*8 + j] + ap[lane*8 + j]; s += x[j]; }
    #pragma unroll
    for (int o = 16; o; o >>= 1) s += __shfl_xor_sync(~0u, s, o);
    float mean = s * (1.f/256.f);
    float v = 0.f;
    #pragma unroll
    for (int j = 0; j < 8; j++) { float d = x[j] - mean; v += d*d; }
    #pragma unroll
    for (int o = 16; o; o >>= 1) v += __shfl_xor_sync(~0u, v, o);
    float rstd = rsqrtf(v * (1.f/256.f) + EPSLN);
    float* op = &g_h[(size_t)token*Dd];
    #pragma unroll
    for (int j = 0; j < 8; j++) {
        int cix = lane*8 + j;
        float y = (x[j] - mean)*rstd*gam[cix] + bet[cix];
        op[cix] = y;
        size_t ix = (size_t)token*Dd + cix;
        __nv_bfloat16 hh, ll;
        fsplit(y, hh, ll);
        g_hhi[ix] = hh;
        g_hlo[ix] = ll;
    }
}

// ---------------------------------------------------------------------------
// Final head tail: out = relu_h(g_tmp fp32) @ o2w + o2b   (warp per token)
// ---------------------------------------------------------------------------
__global__ __launch_bounds__(256) void head2_kernel(const float* __restrict__ o2w,
                                                    const float* __restrict__ o2b,
                                                    float* __restrict__ out) {
    int warp = threadIdx.x >> 5, lane = threadIdx.x & 31;
    int token = blockIdx.x * 8 + warp;
    const float* hp = &g_tmp[(size_t)token*Dd];
    float a0 = 0.f, a1 = 0.f;
    #pragma unroll
    for (int j = 0; j < 8; j++) {
        int k = lane + j*32;
        float hv = hp[k];
        a0 = fmaf(hv, o2w[k*2],   a0);
        a1 = fmaf(hv, o2w[k*2+1], a1);
    }
    #pragma unroll
    for (int o = 16; o; o >>= 1) {
        a0 += __shfl_xor_sync(~0u, a0, o);
        a1 += __shfl_xor_sync(~0u, a1, o);
    }
    if (lane == 0) {
        out[(size_t)token*2]     = a0 + o2b[0];
        out[(size_t)token*2 + 1] = a1 + o2b[1];
    }
}

// ---------------------------------------------------------------------------
// Host orchestration
// ---------------------------------------------------------------------------
static inline void* symaddr(const void* s) {
    void* p = nullptr;
    cudaGetSymbolAddress(&p, s);
    return p;
}

extern "C" void kernel_launch(void* const* d_in, const int* in_sizes, int n_in,
                              void* d_out, int out_size) {
    const float* x    = (const float*)d_in[0];
    const float* in_w = (const float*)d_in[1];
    const float* in_b = (const float*)d_in[2];
    const float* qw   = (const float*)d_in[3];
    const float* qb   = (const float*)d_in[4];
    const float* kw   = (const float*)d_in[5];
    const float* kb   = (const float*)d_in[6];
    const float* vw   = (const float*)d_in[7];
    const float* vb   = (const float*)d_in[8];
    const float* ow   = (const float*)d_in[9];
    const float* ob   = (const float*)d_in[10];
    const float* f1w  = (const float*)d_in[11];
    const float* f1b  = (const float*)d_in[12];
    const float* f2w  = (const float*)d_in[13];
    const float* f2b  = (const float*)d_in[14];
    const float* n1g  = (const float*)d_in[15];
    const float* n1b  = (const float*)d_in[16];
    const float* n2g  = (const float*)d_in[17];
    const float* n2b  = (const float*)d_in[18];
    const float* o1w  = (const float*)d_in[19];
    const float* o1b  = (const float*)d_in[20];
    const float* o2w  = (const float*)d_in[21];
    const float* o2b  = (const float*)d_in[22];

    float* outp     = (float*)d_out;
    float* attn_out = outp + (size_t)Bd*Ld*2;

    __nv_bfloat16* p_hh   = (__nv_bfloat16*)symaddr(g_hhi);
    __nv_bfloat16* p_hl   = (__nv_bfloat16*)symaddr(g_hlo);
    __nv_bfloat16* p_qkvh = (__nv_bfloat16*)symaddr(g_qkvh);
    __nv_bfloat16* p_qkvl = (__nv_bfloat16*)symaddr(g_qkvl);
    __nv_bfloat16* p_oh   = (__nv_bfloat16*)symaddr(g_ohi);
    __nv_bfloat16* p_ol   = (__nv_bfloat16*)symaddr(g_olo);
    __nv_bfloat16* p_fh   = (__nv_bfloat16*)symaddr(g_fhi);
    __nv_bfloat16* p_fl   = (__nv_bfloat16*)symaddr(g_flo);
    float*         p_tmp  = (float*)symaddr(g_tmp);
    __nv_bfloat16* p_owh  = (__nv_bfloat16*)symaddr(g_owh);
    __nv_bfloat16* p_owl  = (__nv_bfloat16*)symaddr(g_owl);
    __nv_bfloat16* p_f1h  = (__nv_bfloat16*)symaddr(g_f1wh);
    __nv_bfloat16* p_f1l  = (__nv_bfloat16*)symaddr(g_f1wl);
    __nv_bfloat16* p_f2h  = (__nv_bfloat16*)symaddr(g_f2wh);
    __nv_bfloat16* p_f2l  = (__nv_bfloat16*)symaddr(g_f2wl);
    __nv_bfloat16* p_o1h  = (__nv_bfloat16*)symaddr(g_o1wh);
    __nv_bfloat16* p_o1l  = (__nv_bfloat16*)symaddr(g_o1wl);

    const int SM_G256 = 384*(256+8)*2;
    const int SM_G128 = 384*(128+8)*2;
    const int SM_G64  = 384*(64+8)*2;

    cudaFuncSetAttribute(gemm_qkv, cudaFuncAttributeMaxDynamicSharedMemorySize, SM_G256);
    cudaFuncSetAttribute(gemm_bias<256,true ,false,true >, cudaFuncAttributeMaxDynamicSharedMemorySize, SM_G256);
    cudaFuncSetAttribute(gemm_bias<256,false,true ,true >, cudaFuncAttributeMaxDynamicSharedMemorySize, SM_G256);
    cudaFuncSetAttribute(gemm_bias<128,false,true ,false>, cudaFuncAttributeMaxDynamicSharedMemorySize, SM_G128);
    cudaFuncSetAttribute(gemm_bias<64 ,false,true ,false>, cudaFuncAttributeMaxDynamicSharedMemorySize, SM_G64);
    cudaFuncSetAttribute(attn_kernel, cudaFuncAttributeMaxDynamicSharedMemorySize, SM_ATTN_BYTES);

    convert_w<<<384, 256>>>(qw, kw, vw, ow, f1w, f2w, o1w, qb, kb, vb);
    embed_kernel<<<BLd, Dd>>>(x, in_w, in_b);

    const dim3 gQKV (BLd/128, 6);
    const dim3 gProj(BLd/128, 4);   // N=256
    const dim3 gF1  (BLd/128, 1);   // N=64
    const dim3 gAttn((Ld + QT - 1)/QT, Bd*Hd);

    for (int i = 0; i < NLd; i++) {
        gemm_qkv<<<gQKV, 512, SM_G256>>>(i);

        attn_kernel<<<gAttn, 256, SM_ATTN_BYTES>>>(
            p_qkvh, p_qkvl,
            attn_out + (size_t)i*Bd*Hd*Ld*Ld, p_oh, p_ol);

        gemm_bias<128,false,true,false><<<gProj, 512, SM_G128>>>(
            p_oh, p_ol, p_owh + (size_t)i*128*Dd, p_owl + (size_t)i*128*Dd,
            ob + i*Dd, p_tmp, nullptr, nullptr, Dd);
        ln_kernel<<<BLd/8, 256>>>(p_tmp, n1g + i*Dd, n1b + i*Dd);

        gemm_bias<256,true,false,true><<<gF1, 512, SM_G256>>>(
            p_hh, p_hl, p_f1h + (size_t)i*Dd*FCd, p_f1l + (size_t)i*Dd*FCd,
            f1b + i*FCd, nullptr, p_fh, p_fl, FCd);
        gemm_bias<64,false,true,false><<<gProj, 512, SM_G64>>>(
            p_fh, p_fl, p_f2h + (size_t)i*FCd*Dd, p_f2l + (size_t)i*FCd*Dd,
            f2b + i*Dd, p_tmp, nullptr, nullptr, Dd);
        ln_kernel<<<BLd/8, 256>>>(p_tmp, n2g + i*Dd, n2b + i*Dd);
    }

    gemm_bias<256,false,true,true><<<gProj, 512, SM_G256>>>(
        p_hh, p_hl, p_o1h, p_o1l, o1b, p_tmp, nullptr, nullptr, Dd);
    head2_kernel<<<BLd/8, 256>>>(o2w, o2b, outp);
}

// round 10
// speedup vs baseline: 4.8956x; 1.0693x over previous
#include <cuda_runtime.h>
#include <cuda_bf16.h>
#include <stdint.h>

#define Bd  8
#define Ld  2016
#define Hd  4
#define DKd 32
#define Dd  256
#define FCd 64
#define NLd 3
#define BLd (Bd*Ld)          // 16128 tokens

#define SC2f 0.09016844005556f   // (1/sqrt(256)) * log2(e)
#define EPSLN 1e-5f

// ---------------------------------------------------------------------------
// Device scratch (no allocation allowed). hi/lo split bf16 pairs everywhere.
// ---------------------------------------------------------------------------
__device__ __align__(128) float          g_h    [BLd*Dd];
__device__ __align__(128) __nv_bfloat16  g_hhi  [BLd*Dd];
__device__ __align__(128) __nv_bfloat16  g_hlo  [BLd*Dd];
__device__ __align__(128) __nv_bfloat16  g_qkvh [3*BLd*128];
__device__ __align__(128) __nv_bfloat16  g_qkvl [3*BLd*128];
__device__ __align__(128) __nv_bfloat16  g_ohi  [BLd*128];
__device__ __align__(128) __nv_bfloat16  g_olo  [BLd*128];
__device__ __align__(128) float          g_tmp  [BLd*Dd];
__device__ __align__(128) __nv_bfloat16  g_fhi  [BLd*FCd];
__device__ __align__(128) __nv_bfloat16  g_flo  [BLd*FCd];
// split weights
__device__ __align__(128) __nv_bfloat16  g_qkvwh[NLd*3*Dd*128];
__device__ __align__(128) __nv_bfloat16  g_qkvwl[NLd*3*Dd*128];
__device__ __align__(128) float          g_qkvb [NLd*3*128];
__device__ __align__(128) __nv_bfloat16  g_owh  [NLd*128*Dd];
__device__ __align__(128) __nv_bfloat16  g_owl  [NLd*128*Dd];
__device__ __align__(128) __nv_bfloat16  g_f1wh [NLd*Dd*FCd];
__device__ __align__(128) __nv_bfloat16  g_f1wl [NLd*Dd*FCd];
__device__ __align__(128) __nv_bfloat16  g_f2wh [NLd*FCd*Dd];
__device__ __align__(128) __nv_bfloat16  g_f2wl [NLd*FCd*Dd];
__device__ __align__(128) __nv_bfloat16  g_o1wh [Dd*Dd];
__device__ __align__(128) __nv_bfloat16  g_o1wl [Dd*Dd];

// ---------------------------------------------------------------------------
// helpers
// ---------------------------------------------------------------------------
__device__ __forceinline__ void mma16816(float* d, const uint32_t* a,
                                         uint32_t b0, uint32_t b1) {
    asm volatile(
        "mma.sync.aligned.m16n8k16.row.col.f32.bf16.bf16.f32 "
        "{%0,%1,%2,%3}, {%4,%5,%6,%7}, {%8,%9}, {%0,%1,%2,%3};"
        : "+f"(d[0]), "+f"(d[1]), "+f"(d[2]), "+f"(d[3])
        : "r"(a[0]), "r"(a[1]), "r"(a[2]), "r"(a[3]), "r"(b0), "r"(b1));
}

__device__ __forceinline__ void ldsm4(uint32_t& r0, uint32_t& r1,
                                      uint32_t& r2, uint32_t& r3, uint32_t a) {
    asm volatile("ldmatrix.sync.aligned.m8n8.x4.shared.b16 {%0,%1,%2,%3}, [%4];"
        : "=r"(r0), "=r"(r1), "=r"(r2), "=r"(r3) : "r"(a));
}

__device__ __forceinline__ void ldsm4t(uint32_t& r0, uint32_t& r1,
                                       uint32_t& r2, uint32_t& r3, uint32_t a) {
    asm volatile("ldmatrix.sync.aligned.m8n8.x4.trans.shared.b16 {%0,%1,%2,%3}, [%4];"
        : "=r"(r0), "=r"(r1), "=r"(r2), "=r"(r3) : "r"(a));
}

__device__ __forceinline__ void cpa16(uint32_t dst, const void* src, int srcsize) {
    asm volatile("cp.async.cg.shared.global [%0], [%1], 16, %2;"
        :: "r"(dst), "l"(src), "r"(srcsize));
}
__device__ __forceinline__ void cpa_commit() {
    asm volatile("cp.async.commit_group;" ::: "memory");
}
template<int N>
__device__ __forceinline__ void cpa_wait() {
    asm volatile("cp.async.wait_group %0;" :: "n"(N) : "memory");
}

__device__ __forceinline__ float ex2(float x) {
    float y;
    asm("ex2.approx.ftz.f32 %0, %1;" : "=f"(y) : "f"(x));
    return y;
}

__device__ __forceinline__ uint32_t pk2(float x, float y) {
    __nv_bfloat162 t = __floats2bfloat162_rn(x, y);
    return *reinterpret_cast<uint32_t*>(&t);
}

__device__ __forceinline__ void fsplit(float v, __nv_bfloat16& hi, __nv_bfloat16& lo) {
    hi = __float2bfloat16(v);
    lo = __float2bfloat16(v - __bfloat162float(hi));
}

__device__ __forceinline__ void pksplit(float x, float y, uint32_t& hi, uint32_t& lo) {
    __nv_bfloat16 xh = __float2bfloat16(x), yh = __float2bfloat16(y);
    __nv_bfloat162 th; th.x = xh; th.y = yh;
    hi = *reinterpret_cast<uint32_t*>(&th);
    lo = pk2(x - __bfloat162float(xh), y - __bfloat162float(yh));
}

__device__ __forceinline__ void stcs2(float* p, float a, float b) {
    asm volatile("st.global.cs.v2.f32 [%0], {%1,%2};" :: "l"(p), "f"(a), "f"(b));
}

// ---------------------------------------------------------------------------
// Weight conversion fp32 -> bf16 hi/lo (+ QKV packing)
// ---------------------------------------------------------------------------
__global__ void convert_w(const float* __restrict__ qw, const float* __restrict__ kw,
                          const float* __restrict__ vw, const float* __restrict__ ow,
                          const float* __restrict__ f1w, const float* __restrict__ f2w,
                          const float* __restrict__ o1w,
                          const float* __restrict__ qb, const float* __restrict__ kb,
                          const float* __restrict__ vb) {
    int i = blockIdx.x * 256 + threadIdx.x;
    const int n1 = NLd*Dd*128;
    const int n3 = NLd*Dd*FCd;
    const int n5 = Dd*Dd;
    if (i < n1) {
        int l = i / (Dd*128), rem = i % (Dd*128);
        size_t b = (size_t)(l*3)*Dd*128 + rem;
        fsplit(qw[i], g_qkvwh[b],            g_qkvwl[b]);
        fsplit(kw[i], g_qkvwh[b + Dd*128],   g_qkvwl[b + Dd*128]);
        fsplit(vw[i], g_qkvwh[b + 2*Dd*128], g_qkvwl[b + 2*Dd*128]);
        fsplit(ow[i], g_owh[i], g_owl[i]);
    }
    if (i < n3) {
        fsplit(f1w[i], g_f1wh[i], g_f1wl[i]);
        fsplit(f2w[i], g_f2wh[i], g_f2wl[i]);
    }
    if (i < n5) fsplit(o1w[i], g_o1wh[i], g_o1wl[i]);
    if (i < NLd*128) {
        int l = i >> 7, n = i & 127;
        g_qkvb[(l*3+0)*128 + n] = qb[i];
        g_qkvb[(l*3+1)*128 + n] = kb[i];
        g_qkvb[(l*3+2)*128 + n] = vb[i];
    }
}

// ---------------------------------------------------------------------------
// Embed: h = x @ in_w + in_b (fp32 + split)
// ---------------------------------------------------------------------------
__global__ void embed_kernel(const float* __restrict__ x,
                             const float* __restrict__ in_w,
                             const float* __restrict__ in_b) {
    int t = blockIdx.x, d = threadIdx.x;
    float x0 = x[t*2], x1 = x[t*2+1];
    float v = fmaf(x0, in_w[d], fmaf(x1, in_w[Dd + d], in_b[d]));
    size_t ix = (size_t)t*Dd + d;
    g_h[ix] = v;
    fsplit(v, g_hhi[ix], g_hlo[ix]);
}

// ---------------------------------------------------------------------------
// GEMM core: tile 128x64, 512 threads (16 warps: 8 M x 2 N). 3-term split MMA.
// ---------------------------------------------------------------------------
template<int K, bool OUT_B16, bool OUT_F32, bool RELU>
__device__ __forceinline__ void gemm_body(
        const __nv_bfloat16* __restrict__ Ahi,
        const __nv_bfloat16* __restrict__ Alo,
        const __nv_bfloat16* __restrict__ Whi,
        const __nv_bfloat16* __restrict__ Wlo,
        const float* __restrict__ bias,
        float* __restrict__ outF,
        __nv_bfloat16* __restrict__ outBh,
        __nv_bfloat16* __restrict__ outBl,
        int N, int row0, int col0) {
    extern __shared__ __nv_bfloat16 sm[];
    constexpr int SA = K + 8;
    __nv_bfloat16* sAh = sm;
    __nv_bfloat16* sAl = sm + 128 * SA;
    __nv_bfloat16* sWh = sm + 256 * SA;
    __nv_bfloat16* sWl = sWh + 64 * SA;

    const int tid = threadIdx.x, lane = tid & 31, warp = tid >> 5;

    constexpr int AV = K / 8;
    #pragma unroll 2
    for (int i = tid; i < 128 * AV; i += 512) {
        int r = i / AV, c = (i % AV) * 8;
        size_t g = (size_t)(row0 + r)*K + c;
        *reinterpret_cast<uint4*>(&sAh[r*SA + c]) = *reinterpret_cast<const uint4*>(&Ahi[g]);
        *reinterpret_cast<uint4*>(&sAl[r*SA + c]) = *reinterpret_cast<const uint4*>(&Alo[g]);
    }
    #pragma unroll 2
    for (int i = tid; i < 64 * K / 4; i += 512) {
        int k = i >> 4, n4 = (i & 15) * 4;
        size_t g = (size_t)k*N + col0 + n4;
        uint2 wh = *reinterpret_cast<const uint2*>(&Whi[g]);
        uint2 wl = *reinterpret_cast<const uint2*>(&Wlo[g]);
        __nv_bfloat16 th[4]; *reinterpret_cast<uint2*>(th) = wh;
        __nv_bfloat16 tl[4]; *reinterpret_cast<uint2*>(tl) = wl;
        #pragma unroll
        for (int j = 0; j < 4; j++) {
            sWh[(n4+j)*SA + k] = th[j];
            sWl[(n4+j)*SA + k] = tl[j];
        }
    }
    __syncthreads();

    float acc[4][4];
    #pragma unroll
    for (int i = 0; i < 4; i++)
        #pragma unroll
        for (int j = 0; j < 4; j++) acc[i][j] = 0.f;

    const int mwarp = warp >> 1, nwarp = warp & 1;
    const int ar = mwarp*16 + (lane >> 2);
    const int ac = (lane & 3) * 2;
    #pragma unroll
    for (int kk = 0; kk < K/16; kk++) {
        uint32_t ah[4], al[4];
        {
            const __nv_bfloat16* pa = &sAh[ar*SA + kk*16 + ac];
            ah[0] = *(const uint32_t*)pa;
            ah[1] = *(const uint32_t*)(pa + 8*SA);
            ah[2] = *(const uint32_t*)(pa + 8);
            ah[3] = *(const uint32_t*)(pa + 8*SA + 8);
            const __nv_bfloat16* pl = &sAl[ar*SA + kk*16 + ac];
            al[0] = *(const uint32_t*)pl;
            al[1] = *(const uint32_t*)(pl + 8*SA);
            al[2] = *(const uint32_t*)(pl + 8);
            al[3] = *(const uint32_t*)(pl + 8*SA + 8);
        }
        #pragma unroll
        for (int nt = 0; nt < 4; nt++) {
            int nrow = nwarp*32 + nt*8 + (lane>>2);
            const __nv_bfloat16* pbh = &sWh[nrow*SA + kk*16 + ac];
            uint32_t bh0 = *(const uint32_t*)pbh;
            uint32_t bh1 = *(const uint32_t*)(pbh + 8);
            const __nv_bfloat16* pbl = &sWl[nrow*SA + kk*16 + ac];
            uint32_t bl0 = *(const uint32_t*)pbl;
            uint32_t bl1 = *(const uint32_t*)(pbl + 8);
            mma16816(acc[nt], ah, bh0, bh1);
            mma16816(acc[nt], al, bh0, bh1);
            mma16816(acc[nt], ah, bl0, bl1);
        }
    }

    const int orow = row0 + mwarp*16 + (lane >> 2);
    #pragma unroll
    for (int nt = 0; nt < 4; nt++) {
        int c = col0 + nwarp*32 + nt*8 + (lane & 3)*2;
        float b0v = bias[c], b1v = bias[c+1];
        #pragma unroll
        for (int half = 0; half < 2; half++) {
            int r = orow + half*8;
            float v0 = acc[nt][half*2+0] + b0v;
            float v1 = acc[nt][half*2+1] + b1v;
            if (RELU) { v0 = fmaxf(v0, 0.f); v1 = fmaxf(v1, 0.f); }
            size_t o = (size_t)r*N + c;
            if (OUT_F32) { outF[o] = v0; outF[o+1] = v1; }
            if (OUT_B16) {
                __nv_bfloat16 h0, l0, h1, l1;
                fsplit(v0, h0, l0);
                fsplit(v1, h1, l1);
                outBh[o] = h0; outBh[o+1] = h1;
                outBl[o] = l0; outBl[o+1] = l1;
            }
        }
    }
}

template<int K, bool OUT_B16, bool OUT_F32, bool RELU>
__global__ __launch_bounds__(512) void gemm_bias(
        const __nv_bfloat16* __restrict__ Ahi, const __nv_bfloat16* __restrict__ Alo,
        const __nv_bfloat16* __restrict__ Whi, const __nv_bfloat16* __restrict__ Wlo,
        const float* __restrict__ bias,
        float* __restrict__ outF,
        __nv_bfloat16* __restrict__ outBh, __nv_bfloat16* __restrict__ outBl,
        int N) {
    gemm_body<K, OUT_B16, OUT_F32, RELU>(Ahi, Alo, Whi, Wlo, bias, outF, outBh, outBl,
                                         N, blockIdx.x*128, blockIdx.y*64);
}

// Fused QKV: grid (126, 6); blockIdx.y selects (q/k/v, col-half)
__global__ __launch_bounds__(512) void gemm_qkv(int layer) {
    int sel = blockIdx.y >> 1;
    int col0 = (blockIdx.y & 1) * 64;
    const __nv_bfloat16* Whi = g_qkvwh + ((size_t)(layer*3 + sel))*Dd*128;
    const __nv_bfloat16* Wlo = g_qkvwl + ((size_t)(layer*3 + sel))*Dd*128;
    const float* bias = g_qkvb + (layer*3 + sel)*128;
    __nv_bfloat16* oh = g_qkvh + (size_t)sel*BLd*128;
    __nv_bfloat16* ol = g_qkvl + (size_t)sel*BLd*128;
    gemm_body<256, true, false, false>(g_hhi, g_hlo, Whi, Wlo, bias, nullptr, oh, ol,
                                       128, blockIdx.x*128, col0);
}

// ---------------------------------------------------------------------------
// GEMM (tile 128 x 256, full rows) + fused residual + LayerNorm.
// 512 threads: 16 warps = 8 M-slices x 2 N-slices (each warp 16 rows x 128 cols).
// After MMA: v = acc + bias staged to smem, then in-CTA row LayerNorm:
// h = LN(g_h + v), written to g_h (fp32) + g_hhi/g_hlo (split bf16).
// ---------------------------------------------------------------------------
#define LNSS 260    // fp32 stride for the staging slab

template<int K>
__global__ __launch_bounds__(512) void gemm_ln(
        const __nv_bfloat16* __restrict__ Ahi,
        const __nv_bfloat16* __restrict__ Alo,
        const __nv_bfloat16* __restrict__ Whi,
        const __nv_bfloat16* __restrict__ Wlo,
        const float* __restrict__ bias,
        const float* __restrict__ gam,
        const float* __restrict__ bet) {
    extern __shared__ __nv_bfloat16 sm[];
    constexpr int SA = K + 8;
    __nv_bfloat16* sAh = sm;
    __nv_bfloat16* sAl = sm + 128 * SA;
    __nv_bfloat16* sWh = sm + 256 * SA;
    __nv_bfloat16* sWl = sWh + 256 * SA;
    float* sv = (float*)sm;   // reused after MMA: [128][LNSS]

    const int tid = threadIdx.x, lane = tid & 31, warp = tid >> 5;
    const int row0 = blockIdx.x * 128;

    constexpr int AV = K / 8;
    #pragma unroll 2
    for (int i = tid; i < 128 * AV; i += 512) {
        int r = i / AV, c = (i % AV) * 8;
        size_t g = (size_t)(row0 + r)*K + c;
        *reinterpret_cast<uint4*>(&sAh[r*SA + c]) = *reinterpret_cast<const uint4*>(&Ahi[g]);
        *reinterpret_cast<uint4*>(&sAl[r*SA + c]) = *reinterpret_cast<const uint4*>(&Alo[g]);
    }
    #pragma unroll 2
    for (int i = tid; i < 256 * K / 4; i += 512) {
        int k = i / 64, n4 = (i % 64) * 4;
        size_t g = (size_t)k*Dd + n4;
        uint2 wh = *reinterpret_cast<const uint2*>(&Whi[g]);
        uint2 wl = *reinterpret_cast<const uint2*>(&Wlo[g]);
        __nv_bfloat16 th[4]; *reinterpret_cast<uint2*>(th) = wh;
        __nv_bfloat16 tl[4]; *reinterpret_cast<uint2*>(tl) = wl;
        #pragma unroll
        for (int j = 0; j < 4; j++) {
            sWh[(n4+j)*SA + k] = th[j];
            sWl[(n4+j)*SA + k] = tl[j];
        }
    }
    __syncthreads();

    float acc[16][4];
    #pragma unroll
    for (int i = 0; i < 16; i++)
        #pragma unroll
        for (int j = 0; j < 4; j++) acc[i][j] = 0.f;

    const int mwarp = warp >> 1, nwarp = warp & 1;
    const int ar = mwarp*16 + (lane >> 2);
    const int ac = (lane & 3) * 2;
    #pragma unroll
    for (int kk = 0; kk < K/16; kk++) {
        uint32_t ah[4], al[4];
        {
            const __nv_bfloat16* pa = &sAh[ar*SA + kk*16 + ac];
            ah[0] = *(const uint32_t*)pa;
            ah[1] = *(const uint32_t*)(pa + 8*SA);
            ah[2] = *(const uint32_t*)(pa + 8);
            ah[3] = *(const uint32_t*)(pa + 8*SA + 8);
            const __nv_bfloat16* pl = &sAl[ar*SA + kk*16 + ac];
            al[0] = *(const uint32_t*)pl;
            al[1] = *(const uint32_t*)(pl + 8*SA);
            al[2] = *(const uint32_t*)(pl + 8);
            al[3] = *(const uint32_t*)(pl + 8*SA + 8);
        }
        #pragma unroll
        for (int nt = 0; nt < 16; nt++) {
            int nrow = nwarp*128 + nt*8 + (lane>>2);
            const __nv_bfloat16* pbh = &sWh[nrow*SA + kk*16 + ac];
            uint32_t bh0 = *(const uint32_t*)pbh;
            uint32_t bh1 = *(const uint32_t*)(pbh + 8);
            const __nv_bfloat16* pbl = &sWl[nrow*SA + kk*16 + ac];
            uint32_t bl0 = *(const uint32_t*)pbl;
            uint32_t bl1 = *(const uint32_t*)(pbl + 8);
            mma16816(acc[nt], ah, bh0, bh1);
            mma16816(acc[nt], al, bh0, bh1);
            mma16816(acc[nt], ah, bl0, bl1);
        }
    }
    __syncthreads();   // operands no longer needed; reuse smem as staging

    // stage v = acc + bias
    {
        const int r0 = mwarp*16 + (lane >> 2);
        #pragma unroll
        for (int nt = 0; nt < 16; nt++) {
            int c = nwarp*128 + nt*8 + (lane & 3)*2;
            float b0v = bias[c], b1v = bias[c+1];
            sv[ r0     *LNSS + c]     = acc[nt][0] + b0v;
            sv[ r0     *LNSS + c + 1] = acc[nt][1] + b1v;
            sv[(r0 + 8)*LNSS + c]     = acc[nt][2] + b0v;
            sv[(r0 + 8)*LNSS + c + 1] = acc[nt][3] + b1v;
        }
    }
    __syncthreads();

    // row LayerNorm: warp w handles rows w*8 .. w*8+7
    #pragma unroll 1
    for (int rr = 0; rr < 8; rr++) {
        int row = warp*8 + rr;
        int token = row0 + row;
        const float* hp = &g_h[(size_t)token*Dd];
        float x[8], s = 0.f;
        #pragma unroll
        for (int j = 0; j < 8; j++) {
            x[j] = hp[lane*8 + j] + sv[row*LNSS + lane*8 + j];
            s += x[j];
        }
        #pragma unroll
        for (int o = 16; o; o >>= 1) s += __shfl_xor_sync(~0u, s, o);
        float mean = s * (1.f/256.f);
        float v = 0.f;
        #pragma unroll
        for (int j = 0; j < 8; j++) { float d = x[j] - mean; v += d*d; }
        #pragma unroll
        for (int o = 16; o; o >>= 1) v += __shfl_xor_sync(~0u, v, o);
        float rstd = rsqrtf(v * (1.f/256.f) + EPSLN);
        float* op = &g_h[(size_t)token*Dd];
        #pragma unroll
        for (int j = 0; j < 8; j++) {
            int cix = lane*8 + j;
            float y = (x[j] - mean)*rstd*gam[cix] + bet[cix];
            op[cix] = y;
            size_t ix = (size_t)token*Dd + cix;
            __nv_bfloat16 hh, ll;
            fsplit(y, hh, ll);
            g_hhi[ix] = hh;
            g_hlo[ix] = ll;
        }
    }
}

// ---------------------------------------------------------------------------
// Attention v6: 128-query tile, 256 threads (8 warps x 16 rows).
// Pass A: 1-term QK (Qh*Kh only; K_hi staged), 4-buffer ring, 2 chunks per
// barrier. Pass B: exact 3-term QK w/ 2-stage SW pipeline, P out (.cs),
// 3-term PV. Q fragments pre-scaled by SCALE*log2e. m=0 softmax; zfilled
// padding keys contribute exactly 1.0 each -> subtract 32 from row sums.
// ---------------------------------------------------------------------------
#define QT 128
#define KT 128
#define NCH 16
#define NPAD 32.0f

#define KBUF 5120             // elements per buffer: 128*40
#define SM_ATTN_BYTES (8*KBUF*2)   // 81920

struct AttnSmem {
    uint32_t kh, kl, vh, vl;
};

// Pass A: stage K_hi chunk into 128x40 buffer b (4-buffer ring at sm base)
__device__ __forceinline__ void stageKhiA(uint32_t sm_u, int b, int ch,
        const __nv_bfloat16* Kh, size_t base, int tid) {
    const int k0 = ch * KT;
    #pragma unroll
    for (int it = 0; it < 2; it++) {
        int o = tid + it*256;
        int r = o >> 2;
        int c = (o & 3) * 8;
        int s = k0 + r;
        bool ok = s < Ld;
        const __nv_bfloat16* src = Kh + base + (size_t)(ok ? s : 0)*128 + c;
        uint32_t dst = sm_u + b*10240 + (r*40 + c)*2;
        cpa16(dst, src, ok ? 16 : 0);
    }
}

__device__ __forceinline__ void stageK(const AttnSmem& S, int buf, int ch,
        const __nv_bfloat16* Kh, const __nv_bfloat16* Kl, size_t base, int tid) {
    const int k0 = ch * KT;
    #pragma unroll
    for (int it = 0; it < 4; it++) {
        int o = tid + it*256;
        int half = o >> 9;
        int r = (o & 511) >> 2;
        int c = (o & 3) * 8;
        int s = k0 + r;
        bool ok = s < Ld;
        const __nv_bfloat16* src = (half ? Kl : Kh) + base + (size_t)(ok ? s : 0)*128 + c;
        uint32_t dst = (half ? S.kl : S.kh) + (buf*KBUF + r*40 + c)*2;
        cpa16(dst, src, ok ? 16 : 0);
    }
}

__device__ __forceinline__ void stageV(const AttnSmem& S, int buf, int ch,
        const __nv_bfloat16* Vh, const __nv_bfloat16* Vl, size_t base, int tid) {
    const int k0 = ch * KT;
    #pragma unroll
    for (int it = 0; it < 4; it++) {
        int o = tid + it*256;
        int half = o >> 9;
        int r = (o & 511) >> 2;
        int c = (o & 3) * 8;
        int s = k0 + r;
        bool ok = s < Ld;
        const __nv_bfloat16* src = (half ? Vl : Vh) + base + (size_t)(ok ? s : 0)*128 + c;
        uint32_t dst = (half ? S.vl : S.vh) + (buf*KBUF + r*40 + c)*2;
        cpa16(dst, src, ok ? 16 : 0);
    }
}

// Pass A stats: 1-term QK (Qh*Kh); scores pre-scaled -> ex2 direct.
__device__ __forceinline__ void qk_stats_chunk(
        uint32_t kh_u, int laneK,
        const uint32_t aqh[2][4],
        float& s0, float& s1) {
    #pragma unroll 2
    for (int gq = 0; gq < 4; gq++) {
        float acc[4][4];
        #pragma unroll
        for (int i = 0; i < 4; i++)
            #pragma unroll
            for (int j = 0; j < 4; j++) acc[i][j] = 0.f;
        #pragma unroll
        for (int pair = 0; pair < 2; pair++) {
            int be = (gq*32 + pair*16)*40;
            #pragma unroll
            for (int kk = 0; kk < 2; kk++) {
                uint32_t bh0, bh1, bh2, bh3;
                uint32_t off = (be + kk*16 + laneK)*2;
                ldsm4(bh0, bh1, bh2, bh3, kh_u + off);
                mma16816(acc[pair*2  ], aqh[kk], bh0, bh1);
                mma16816(acc[pair*2+1], aqh[kk], bh2, bh3);
            }
        }
        #pragma unroll
        for (int nt = 0; nt < 4; nt++) {
            s0 += ex2(acc[nt][0]) + ex2(acc[nt][1]);
            s1 += ex2(acc[nt][2]) + ex2(acc[nt][3]);
        }
    }
}

// Pass B: compute 3-term QK accs for one 16-key group.
__device__ __forceinline__ void qk_group(
        uint32_t kh_u, uint32_t kl_u, int laneK, int kbe,
        const uint32_t aqh[2][4], const uint32_t aql[2][4],
        float acc1[2][4], float acc2[2][4]) {
    #pragma unroll
    for (int i = 0; i < 2; i++)
        #pragma unroll
        for (int j = 0; j < 4; j++) { acc1[i][j] = 0.f; acc2[i][j] = 0.f; }
    #pragma unroll
    for (int kk = 0; kk < 2; kk++) {
        uint32_t bh0, bh1, bh2, bh3, bl0, bl1, bl2, bl3;
        uint32_t off = (kbe + kk*16 + laneK)*2;
        ldsm4(bh0, bh1, bh2, bh3, kh_u + off);
        ldsm4(bl0, bl1, bl2, bl3, kl_u + off);
        mma16816(acc1[0], aqh[kk], bh0, bh1);
        mma16816(acc2[0], aql[kk], bh0, bh1);
        mma16816(acc2[0], aqh[kk], bl0, bl1);
        mma16816(acc1[1], aqh[kk], bh2, bh3);
        mma16816(acc2[1], aql[kk], bh2, bh3);
        mma16816(acc2[1], aqh[kk], bl2, bl3);
    }
}

// Pass B: exp, store P, PV for one group (accs already computed).
template<bool MASK>
__device__ __forceinline__ void emit_group(
        uint32_t vh_u, uint32_t vl_u, int laneV, int g, int k0, int fc,
        float inv0, float inv1,
        float* prow0, float* prow1, bool wr0, bool wr1,
        const float acc1[2][4], const float acc2[2][4], float oacc[4][4]) {
    int kbe = g*16*40;
    int colb = k0 + g*16 + fc;
    bool ok0 = !MASK || (colb < Ld);
    bool ok1 = !MASK || (colb + 8 < Ld);
    float p00 = ok0 ? ex2(acc1[0][0]+acc2[0][0])*inv0 : 0.f;
    float p01 = ok0 ? ex2(acc1[0][1]+acc2[0][1])*inv0 : 0.f;
    float p02 = ok0 ? ex2(acc1[0][2]+acc2[0][2])*inv1 : 0.f;
    float p03 = ok0 ? ex2(acc1[0][3]+acc2[0][3])*inv1 : 0.f;
    float p10 = ok1 ? ex2(acc1[1][0]+acc2[1][0])*inv0 : 0.f;
    float p11 = ok1 ? ex2(acc1[1][1]+acc2[1][1])*inv0 : 0.f;
    float p12 = ok1 ? ex2(acc1[1][2]+acc2[1][2])*inv1 : 0.f;
    float p13 = ok1 ? ex2(acc1[1][3]+acc2[1][3])*inv1 : 0.f;

    if (wr0) {
        if (ok0) stcs2(&prow0[colb],     p00, p01);
        if (ok1) stcs2(&prow0[colb + 8], p10, p11);
    }
    if (wr1) {
        if (ok0) stcs2(&prow1[colb],     p02, p03);
        if (ok1) stcs2(&prow1[colb + 8], p12, p13);
    }

    uint32_t ah[4], al[4];
    pksplit(p00, p01, ah[0], al[0]);
    pksplit(p02, p03, ah[1], al[1]);
    pksplit(p10, p11, ah[2], al[2]);
    pksplit(p12, p13, ah[3], al[3]);

    #pragma unroll
    for (int dp = 0; dp < 2; dp++) {
        uint32_t vb0, vb1, vb2, vb3, wl0, wl1, wl2, wl3;
        uint32_t off = (kbe + dp*16 + laneV)*2;
        ldsm4t(vb0, vb1, vb2, vb3, vh_u + off);
        ldsm4t(wl0, wl1, wl2, wl3, vl_u + off);
        mma16816(oacc[dp*2  ], ah, vb0, vb1);
        mma16816(oacc[dp*2  ], al, vb0, vb1);
        mma16816(oacc[dp*2  ], ah, wl0, wl1);
        mma16816(oacc[dp*2+1], ah, vb2, vb3);
        mma16816(oacc[dp*2+1], al, vb2, vb3);
        mma16816(oacc[dp*2+1], ah, wl2, wl3);
    }
}

// Pass B chunk: 2-stage software pipeline over 8 groups.
template<bool MASK>
__device__ __forceinline__ void qk_emit_chunk(
        uint32_t kh_u, uint32_t kl_u, uint32_t vh_u, uint32_t vl_u,
        int laneK, int laneV,
        const uint32_t aqh[2][4], const uint32_t aql[2][4],
        int k0, int fc, float inv0, float inv1,
        float* prow0, float* prow1, bool wr0, bool wr1,
        float oacc[4][4]) {
    float a1A[2][4], a2A[2][4], a1B[2][4], a2B[2][4];
    qk_group(kh_u, kl_u, laneK, 0, aqh, aql, a1A, a2A);
    #pragma unroll
    for (int g = 0; g < 8; g += 2) {
        qk_group(kh_u, kl_u, laneK, (g+1)*640, aqh, aql, a1B, a2B);
        emit_group<MASK>(vh_u, vl_u, laneV, g, k0, fc, inv0, inv1,
                         prow0, prow1, wr0, wr1, a1A, a2A, oacc);
        if (g + 2 < 8)
            qk_group(kh_u, kl_u, laneK, (g+2)*640, aqh, aql, a1A, a2A);
        emit_group<MASK>(vh_u, vl_u, laneV, g+1, k0, fc, inv0, inv1,
                         prow0, prow1, wr0, wr1, a1B, a2B, oacc);
    }
}

__global__ __launch_bounds__(256, 2) void attn_kernel(
        const __nv_bfloat16* __restrict__ qkvh,
        const __nv_bfloat16* __restrict__ qkvl,
        float* __restrict__ Pout,
        __nv_bfloat16* __restrict__ Oh, __nv_bfloat16* __restrict__ Ol) {
    extern __shared__ __nv_bfloat16 sm[];
    uint32_t sm_u = (uint32_t)__cvta_generic_to_shared(sm);
    AttnSmem S;
    S.kh = sm_u;
    S.kl = sm_u + 2*KBUF*2;
    S.vh = sm_u + 4*KBUF*2;
    S.vl = sm_u + 6*KBUF*2;

    const int tid = threadIdx.x, lane = tid & 31, warp = tid >> 5;
    const int bh = blockIdx.y;
    const int b  = bh >> 2, h = bh & 3;
    const int q0 = blockIdx.x * QT;
    const size_t base = ((size_t)b*Ld*Hd + h)*DKd;
    const __nv_bfloat16* Qh = qkvh;
    const __nv_bfloat16* Ql = qkvl;
    const __nv_bfloat16* Kh = qkvh + (size_t)BLd*128;
    const __nv_bfloat16* Kl = qkvl + (size_t)BLd*128;
    const __nv_bfloat16* Vh = qkvh + (size_t)2*BLd*128;
    const __nv_bfloat16* Vl = qkvl + (size_t)2*BLd*128;

    const int mrow = warp * 16;
    const int fr = lane >> 2, fc = (lane & 3) * 2;
    const int lr = lane & 7, sel = lane >> 3;
    const int laneK = ((sel>>1)*8 + lr)*40 + (sel&1)*8;
    const int laneV = ((sel&1)*8 + lr)*40 + (sel>>1)*8;

    // ---- Q fragments from gmem, SCALE*log2e folded (re-split) ----
    const int r0g = q0 + mrow + fr, r1g = r0g + 8;
    const bool q0ok = (r0g < Ld), q1ok = (r1g < Ld);
    uint32_t aqh[2][4], aql[2][4];
    #pragma unroll
    for (int kk = 0; kk < 2; kk++) {
        int c = kk*16 + fc;
        size_t g0 = base + (size_t)r0g*128 + c;
        size_t g1 = base + (size_t)r1g*128 + c;
        aqh[kk][0] = q0ok ? *(const uint32_t*)&Qh[g0]     : 0;
        aqh[kk][1] = q1ok ? *(const uint32_t*)&Qh[g1]     : 0;
        aqh[kk][2] = q0ok ? *(const uint32_t*)&Qh[g0 + 8] : 0;
        aqh[kk][3] = q1ok ? *(const uint32_t*)&Qh[g1 + 8] : 0;
        aql[kk][0] = q0ok ? *(const uint32_t*)&Ql[g0]     : 0;
        aql[kk][1] = q1ok ? *(const uint32_t*)&Ql[g1]     : 0;
        aql[kk][2] = q0ok ? *(const uint32_t*)&Ql[g0 + 8] : 0;
        aql[kk][3] = q1ok ? *(const uint32_t*)&Ql[g1 + 8] : 0;
    }
    #pragma unroll
    for (int kk = 0; kk < 2; kk++) {
        #pragma unroll
        for (int j = 0; j < 4; j++) {
            __nv_bfloat162 h2 = *reinterpret_cast<__nv_bfloat162*>(&aqh[kk][j]);
            __nv_bfloat162 l2 = *reinterpret_cast<__nv_bfloat162*>(&aql[kk][j]);
            float x0 = (__bfloat162float(h2.x) + __bfloat162float(l2.x)) * SC2f;
            float x1 = (__bfloat162float(h2.y) + __bfloat162float(l2.y)) * SC2f;
            pksplit(x0, x1, aqh[kk][j], aql[kk][j]);
        }
    }

    float s0 = 0.f, s1 = 0.f;

    // ======== PASS A: row sums (K_hi only, 4-buffer ring, 2 chunks/sync) ====
    stageKhiA(sm_u, 0, 0, Kh, base, tid);
    stageKhiA(sm_u, 1, 1, Kh, base, tid); cpa_commit();
    stageKhiA(sm_u, 2, 2, Kh, base, tid);
    stageKhiA(sm_u, 3, 3, Kh, base, tid); cpa_commit();
    #pragma unroll 1
    for (int it = 0; it < 8; it++) {
        if (it < 7) cpa_wait<1>(); else cpa_wait<0>();
        __syncthreads();
        int b0 = (it & 1) ? 2 : 0;
        qk_stats_chunk(sm_u + b0*10240,       laneK, aqh, s0, s1);
        qk_stats_chunk(sm_u + (b0+1)*10240,   laneK, aqh, s0, s1);
        __syncthreads();
        if (it < 6) {
            stageKhiA(sm_u, b0,   2*it+4, Kh, base, tid);
            stageKhiA(sm_u, b0+1, 2*it+5, Kh, base, tid);
            cpa_commit();
        }
    }

    // prologue for pass B overlaps the reduction
    stageK(S, 0, 0, Kh, Kl, base, tid);
    stageV(S, 0, 0, Vh, Vl, base, tid); cpa_commit();
    stageK(S, 1, 1, Kh, Kl, base, tid);
    stageV(S, 1, 1, Vh, Vl, base, tid); cpa_commit();

    s0 += __shfl_xor_sync(~0u, s0, 1);
    s0 += __shfl_xor_sync(~0u, s0, 2);
    s1 += __shfl_xor_sync(~0u, s1, 1);
    s1 += __shfl_xor_sync(~0u, s1, 2);
    s0 -= NPAD;
    s1 -= NPAD;
    const float inv0 = 1.f / s0, inv1 = 1.f / s1;

    // ======== PASS B: P out + PV ========
    float oacc[4][4];
    #pragma unroll
    for (int i = 0; i < 4; i++)
        #pragma unroll
        for (int j = 0; j < 4; j++) oacc[i][j] = 0.f;

    float* prow0 = &Pout[((size_t)bh*Ld + r0g)*Ld];
    float* prow1 = prow0 + 8*(size_t)Ld;

    #pragma unroll 1
    for (int ch = 0; ch < NCH; ch++) {
        if (ch < NCH-1) cpa_wait<1>(); else cpa_wait<0>();
        __syncthreads();
        int buf = ch & 1;
        uint32_t kh_u = S.kh + buf*KBUF*2, kl_u = S.kl + buf*KBUF*2;
        uint32_t vh_u = S.vh + buf*KBUF*2, vl_u = S.vl + buf*KBUF*2;
        if (ch < NCH-1)
            qk_emit_chunk<false>(kh_u, kl_u, vh_u, vl_u, laneK, laneV, aqh, aql,
                                 ch*KT, fc, inv0, inv1, prow0, prow1, q0ok, q1ok, oacc);
        else
            qk_emit_chunk<true >(kh_u, kl_u, vh_u, vl_u, laneK, laneV, aqh, aql,
                                 ch*KT, fc, inv0, inv1, prow0, prow1, q0ok, q1ok, oacc);
        __syncthreads();
        if (ch + 2 < NCH) {
            stageK(S, buf, ch+2, Kh, Kl, base, tid);
            stageV(S, buf, ch+2, Vh, Vl, base, tid);
            cpa_commit();
        }
    }

    // ---- write O (hi/lo) ----
    #pragma unroll
    for (int dt = 0; dt < 4; dt++) {
        int d = dt*8 + fc;
        if (q0ok) {
            size_t g = base + (size_t)r0g*128 + d;
            __nv_bfloat16 hh, ll;
            fsplit(oacc[dt][0], hh, ll); Oh[g]   = hh; Ol[g]   = ll;
            fsplit(oacc[dt][1], hh, ll); Oh[g+1] = hh; Ol[g+1] = ll;
        }
        if (q1ok) {
            size_t g = base + (size_t)r1g*128 + d;
            __nv_bfloat16 hh, ll;
            fsplit(oacc[dt][2], hh, ll); Oh[g]   = hh; Ol[g]   = ll;
            fsplit(oacc[dt][3], hh, ll); Oh[g+1] = hh; Ol[g+1] = ll;
        }
    }
}

// ---------------------------------------------------------------------------
// Final head tail: out = relu_h(g_tmp fp32) @ o2w + o2b   (warp per token)
// ---------------------------------------------------------------------------
__global__ __launch_bounds__(256) void head2_kernel(const float* __restrict__ o2w,
                                                    const float* __restrict__ o2b,
                                                    float* __restrict__ out) {
    int warp = threadIdx.x >> 5, lane = threadIdx.x & 31;
    int token = blockIdx.x * 8 + warp;
    const float* hp = &g_tmp[(size_t)token*Dd];
    float a0 = 0.f, a1 = 0.f;
    #pragma unroll
    for (int j = 0; j < 8; j++) {
        int k = lane + j*32;
        float hv = hp[k];
        a0 = fmaf(hv, o2w[k*2],   a0);
        a1 = fmaf(hv, o2w[k*2+1], a1);
    }
    #pragma unroll
    for (int o = 16; o; o >>= 1) {
        a0 += __shfl_xor_sync(~0u, a0, o);
        a1 += __shfl_xor_sync(~0u, a1, o);
    }
    if (lane == 0) {
        out[(size_t)token*2]     = a0 + o2b[0];
        out[(size_t)token*2 + 1] = a1 + o2b[1];
    }
}

// ---------------------------------------------------------------------------
// Host orchestration
// ---------------------------------------------------------------------------
static inline void* symaddr(const void* s) {
    void* p = nullptr;
    cudaGetSymbolAddress(&p, s);
    return p;
}

extern "C" void kernel_launch(void* const* d_in, const int* in_sizes, int n_in,
                              void* d_out, int out_size) {
    const float* x    = (const float*)d_in[0];
    const float* in_w = (const float*)d_in[1];
    const float* in_b = (const float*)d_in[2];
    const float* qw   = (const float*)d_in[3];
    const float* qb   = (const float*)d_in[4];
    const float* kw   = (const float*)d_in[5];
    const float* kb   = (const float*)d_in[6];
    const float* vw   = (const float*)d_in[7];
    const float* vb   = (const float*)d_in[8];
    const float* ow   = (const float*)d_in[9];
    const float* ob   = (const float*)d_in[10];
    const float* f1w  = (const float*)d_in[11];
    const float* f1b  = (const float*)d_in[12];
    const float* f2w  = (const float*)d_in[13];
    const float* f2b  = (const float*)d_in[14];
    const float* n1g  = (const float*)d_in[15];
    const float* n1b  = (const float*)d_in[16];
    const float* n2g  = (const float*)d_in[17];
    const float* n2b  = (const float*)d_in[18];
    const float* o1w  = (const float*)d_in[19];
    const float* o1b  = (const float*)d_in[20];
    const float* o2w  = (const float*)d_in[21];
    const float* o2b  = (const float*)d_in[22];

    float* outp     = (float*)d_out;
    float* attn_out = outp + (size_t)Bd*Ld*2;

    __nv_bfloat16* p_hh   = (__nv_bfloat16*)symaddr(g_hhi);
    __nv_bfloat16* p_hl   = (__nv_bfloat16*)symaddr(g_hlo);
    __nv_bfloat16* p_qkvh = (__nv_bfloat16*)symaddr(g_qkvh);
    __nv_bfloat16* p_qkvl = (__nv_bfloat16*)symaddr(g_qkvl);
    __nv_bfloat16* p_oh   = (__nv_bfloat16*)symaddr(g_ohi);
    __nv_bfloat16* p_ol   = (__nv_bfloat16*)symaddr(g_olo);
    __nv_bfloat16* p_fh   = (__nv_bfloat16*)symaddr(g_fhi);
    __nv_bfloat16* p_fl   = (__nv_bfloat16*)symaddr(g_flo);
    float*         p_tmp  = (float*)symaddr(g_tmp);
    __nv_bfloat16* p_owh  = (__nv_bfloat16*)symaddr(g_owh);
    __nv_bfloat16* p_owl  = (__nv_bfloat16*)symaddr(g_owl);
    __nv_bfloat16* p_f1h  = (__nv_bfloat16*)symaddr(g_f1wh);
    __nv_bfloat16* p_f1l  = (__nv_bfloat16*)symaddr(g_f1wl);
    __nv_bfloat16* p_f2h  = (__nv_bfloat16*)symaddr(g_f2wh);
    __nv_bfloat16* p_f2l  = (__nv_bfloat16*)symaddr(g_f2wl);
    __nv_bfloat16* p_o1h  = (__nv_bfloat16*)symaddr(g_o1wh);
    __nv_bfloat16* p_o1l  = (__nv_bfloat16*)symaddr(g_o1wl);

    const int SM_G256  = 384*(256+8)*2;                       // 202752
    const int SM_G64   = 384*(64+8)*2;                        // 55296
    const int SM_LN128 = (2*128*(128+8) + 2*256*(128+8))*2;   // 208896
    const int SM_LN64_OP = (2*128*(64+8) + 2*256*(64+8))*2;   // 110592
    const int SM_LNSLAB  = 128*LNSS*4;                        // 133120
    const int SM_LN64  = SM_LN64_OP > SM_LNSLAB ? SM_LN64_OP : SM_LNSLAB;

    cudaFuncSetAttribute(gemm_qkv, cudaFuncAttributeMaxDynamicSharedMemorySize, SM_G256);
    cudaFuncSetAttribute(gemm_bias<256,true ,false,true >, cudaFuncAttributeMaxDynamicSharedMemorySize, SM_G256);
    cudaFuncSetAttribute(gemm_bias<256,false,true ,true >, cudaFuncAttributeMaxDynamicSharedMemorySize, SM_G256);
    cudaFuncSetAttribute(gemm_ln<128>, cudaFuncAttributeMaxDynamicSharedMemorySize, SM_LN128);
    cudaFuncSetAttribute(gemm_ln<64 >, cudaFuncAttributeMaxDynamicSharedMemorySize, SM_LN64);
    cudaFuncSetAttribute(attn_kernel, cudaFuncAttributeMaxDynamicSharedMemorySize, SM_ATTN_BYTES);

    convert_w<<<384, 256>>>(qw, kw, vw, ow, f1w, f2w, o1w, qb, kb, vb);
    embed_kernel<<<BLd, Dd>>>(x, in_w, in_b);

    const dim3 gQKV (BLd/128, 6);
    const dim3 gProj(BLd/128, 4);   // N=256 (head only)
    const dim3 gF1  (BLd/128, 1);   // N=64
    const dim3 gLN  (BLd/128);
    const dim3 gAttn((Ld + QT - 1)/QT, Bd*Hd);

    for (int i = 0; i < NLd; i++) {
        gemm_qkv<<<gQKV, 512, SM_G256>>>(i);

        attn_kernel<<<gAttn, 256, SM_ATTN_BYTES>>>(
            p_qkvh, p_qkvl,
            attn_out + (size_t)i*Bd*Hd*Ld*Ld, p_oh, p_ol);

        // o-projection + residual + LN1 (fused)
        gemm_ln<128><<<gLN, 512, SM_LN128>>>(
            p_oh, p_ol, p_owh + (size_t)i*128*Dd, p_owl + (size_t)i*128*Dd,
            ob + i*Dd, n1g + i*Dd, n1b + i*Dd);

        // FFN1 (relu, split bf16 out)
        gemm_bias<256,true,false,true><<<gF1, 512, SM_G256>>>(
            p_hh, p_hl, p_f1h + (size_t)i*Dd*FCd, p_f1l + (size_t)i*Dd*FCd,
            f1b + i*FCd, nullptr, p_fh, p_fl, FCd);

        // FFN2 + residual + LN2 (fused)
        gemm_ln<64><<<gLN, 512, SM_LN64>>>(
            p_fh, p_fl, p_f2h + (size_t)i*FCd*Dd, p_f2l + (size_t)i*FCd*Dd,
            f2b + i*Dd, n2g + i*Dd, n2b + i*Dd);
    }

    gemm_bias<256,false,true,true><<<gProj, 512, SM_G256>>>(
        p_hh, p_hl, p_o1h, p_o1l, o1b, p_tmp, nullptr, nullptr, Dd);
    head2_kernel<<<BLd/8, 256>>>(o2w, o2b, outp);
}

// round 11
// speedup vs baseline: 5.9546x; 1.2163x over previous
#include <cuda_runtime.h>
#include <cuda_bf16.h>
#include <cuda_fp16.h>
#include <stdint.h>

#define Bd  8
#define Ld  2016
#define Hd  4
#define DKd 32
#define Dd  256
#define FCd 64
#define NLd 3
#define BLd (Bd*Ld)          // 16128 tokens

#define SC2f 0.09016844005556f   // (1/sqrt(256)) * log2(e)
#define EPSLN 1e-5f

// ---------------------------------------------------------------------------
// Device scratch. Residual stream: fp32 + split bf16. Attention: fp16.
// ---------------------------------------------------------------------------
__device__ __align__(128) float          g_h    [BLd*Dd];
__device__ __align__(128) __nv_bfloat16  g_hhi  [BLd*Dd];
__device__ __align__(128) __nv_bfloat16  g_hlo  [BLd*Dd];
__device__ __align__(128) __half         g_qkv  [3*BLd*128];   // fp16 (Q pre-scaled)
__device__ __align__(128) __nv_bfloat16  g_ohi  [BLd*128];
__device__ __align__(128) __nv_bfloat16  g_olo  [BLd*128];
__device__ __align__(128) float          g_tmp  [BLd*Dd];
__device__ __align__(128) __nv_bfloat16  g_fhi  [BLd*FCd];
__device__ __align__(128) __nv_bfloat16  g_flo  [BLd*FCd];
// split weights
__device__ __align__(128) __nv_bfloat16  g_qkvwh[NLd*3*Dd*128];
__device__ __align__(128) __nv_bfloat16  g_qkvwl[NLd*3*Dd*128];
__device__ __align__(128) float          g_qkvb [NLd*3*128];
__device__ __align__(128) __nv_bfloat16  g_owh  [NLd*128*Dd];
__device__ __align__(128) __nv_bfloat16  g_owl  [NLd*128*Dd];
__device__ __align__(128) __nv_bfloat16  g_f1wh [NLd*Dd*FCd];
__device__ __align__(128) __nv_bfloat16  g_f1wl [NLd*Dd*FCd];
__device__ __align__(128) __nv_bfloat16  g_f2wh [NLd*FCd*Dd];
__device__ __align__(128) __nv_bfloat16  g_f2wl [NLd*FCd*Dd];
__device__ __align__(128) __nv_bfloat16  g_o1wh [Dd*Dd];
__device__ __align__(128) __nv_bfloat16  g_o1wl [Dd*Dd];

// ---------------------------------------------------------------------------
// helpers
// ---------------------------------------------------------------------------
__device__ __forceinline__ void mma16816(float* d, const uint32_t* a,
                                         uint32_t b0, uint32_t b1) {
    asm volatile(
        "mma.sync.aligned.m16n8k16.row.col.f32.bf16.bf16.f32 "
        "{%0,%1,%2,%3}, {%4,%5,%6,%7}, {%8,%9}, {%0,%1,%2,%3};"
        : "+f"(d[0]), "+f"(d[1]), "+f"(d[2]), "+f"(d[3])
        : "r"(a[0]), "r"(a[1]), "r"(a[2]), "r"(a[3]), "r"(b0), "r"(b1));
}

__device__ __forceinline__ void mma16816h(float* d, const uint32_t* a,
                                          uint32_t b0, uint32_t b1) {
    asm volatile(
        "mma.sync.aligned.m16n8k16.row.col.f32.f16.f16.f32 "
        "{%0,%1,%2,%3}, {%4,%5,%6,%7}, {%8,%9}, {%0,%1,%2,%3};"
        : "+f"(d[0]), "+f"(d[1]), "+f"(d[2]), "+f"(d[3])
        : "r"(a[0]), "r"(a[1]), "r"(a[2]), "r"(a[3]), "r"(b0), "r"(b1));
}

__device__ __forceinline__ void ldsm4(uint32_t& r0, uint32_t& r1,
                                      uint32_t& r2, uint32_t& r3, uint32_t a) {
    asm volatile("ldmatrix.sync.aligned.m8n8.x4.shared.b16 {%0,%1,%2,%3}, [%4];"
        : "=r"(r0), "=r"(r1), "=r"(r2), "=r"(r3) : "r"(a));
}

__device__ __forceinline__ void ldsm4t(uint32_t& r0, uint32_t& r1,
                                       uint32_t& r2, uint32_t& r3, uint32_t a) {
    asm volatile("ldmatrix.sync.aligned.m8n8.x4.trans.shared.b16 {%0,%1,%2,%3}, [%4];"
        : "=r"(r0), "=r"(r1), "=r"(r2), "=r"(r3) : "r"(a));
}

__device__ __forceinline__ void cpa16(uint32_t dst, const void* src, int srcsize) {
    asm volatile("cp.async.cg.shared.global [%0], [%1], 16, %2;"
        :: "r"(dst), "l"(src), "r"(srcsize));
}
__device__ __forceinline__ void cpa_commit() {
    asm volatile("cp.async.commit_group;" ::: "memory");
}
template<int N>
__device__ __forceinline__ void cpa_wait() {
    asm volatile("cp.async.wait_group %0;" :: "n"(N) : "memory");
}

__device__ __forceinline__ float ex2(float x) {
    float y;
    asm("ex2.approx.ftz.f32 %0, %1;" : "=f"(y) : "f"(x));
    return y;
}

__device__ __forceinline__ uint32_t pk2h(float x, float y) {
    __half2 t = __floats2half2_rn(x, y);
    return *reinterpret_cast<uint32_t*>(&t);
}

__device__ __forceinline__ void fsplit(float v, __nv_bfloat16& hi, __nv_bfloat16& lo) {
    hi = __float2bfloat16(v);
    lo = __float2bfloat16(v - __bfloat162float(hi));
}

__device__ __forceinline__ void stcs2(float* p, float a, float b) {
    asm volatile("st.global.cs.v2.f32 [%0], {%1,%2};" :: "l"(p), "f"(a), "f"(b));
}

// ---------------------------------------------------------------------------
// Weight conversion fp32 -> bf16 hi/lo (+ QKV packing)
// ---------------------------------------------------------------------------
__global__ void convert_w(const float* __restrict__ qw, const float* __restrict__ kw,
                          const float* __restrict__ vw, const float* __restrict__ ow,
                          const float* __restrict__ f1w, const float* __restrict__ f2w,
                          const float* __restrict__ o1w,
                          const float* __restrict__ qb, const float* __restrict__ kb,
                          const float* __restrict__ vb) {
    int i = blockIdx.x * 256 + threadIdx.x;
    const int n1 = NLd*Dd*128;
    const int n3 = NLd*Dd*FCd;
    const int n5 = Dd*Dd;
    if (i < n1) {
        int l = i / (Dd*128), rem = i % (Dd*128);
        size_t b = (size_t)(l*3)*Dd*128 + rem;
        fsplit(qw[i], g_qkvwh[b],            g_qkvwl[b]);
        fsplit(kw[i], g_qkvwh[b + Dd*128],   g_qkvwl[b + Dd*128]);
        fsplit(vw[i], g_qkvwh[b + 2*Dd*128], g_qkvwl[b + 2*Dd*128]);
        fsplit(ow[i], g_owh[i], g_owl[i]);
    }
    if (i < n3) {
        fsplit(f1w[i], g_f1wh[i], g_f1wl[i]);
        fsplit(f2w[i], g_f2wh[i], g_f2wl[i]);
    }
    if (i < n5) fsplit(o1w[i], g_o1wh[i], g_o1wl[i]);
    if (i < NLd*128) {
        int l = i >> 7, n = i & 127;
        g_qkvb[(l*3+0)*128 + n] = qb[i];
        g_qkvb[(l*3+1)*128 + n] = kb[i];
        g_qkvb[(l*3+2)*128 + n] = vb[i];
    }
}

// ---------------------------------------------------------------------------
// Embed: h = x @ in_w + in_b (fp32 + split)
// ---------------------------------------------------------------------------
__global__ void embed_kernel(const float* __restrict__ x,
                             const float* __restrict__ in_w,
                             const float* __restrict__ in_b) {
    int t = blockIdx.x, d = threadIdx.x;
    float x0 = x[t*2], x1 = x[t*2+1];
    float v = fmaf(x0, in_w[d], fmaf(x1, in_w[Dd + d], in_b[d]));
    size_t ix = (size_t)t*Dd + d;
    g_h[ix] = v;
    fsplit(v, g_hhi[ix], g_hlo[ix]);
}

// ---------------------------------------------------------------------------
// GEMM core: tile 128x64, 512 threads. 3-term split MMA.
// OUT modes: F32, split-bf16, fp16*oscale.
// ---------------------------------------------------------------------------
template<int K, bool OUT_B16, bool OUT_F32, bool OUT_F16, bool RELU>
__device__ __forceinline__ void gemm_body(
        const __nv_bfloat16* __restrict__ Ahi,
        const __nv_bfloat16* __restrict__ Alo,
        const __nv_bfloat16* __restrict__ Whi,
        const __nv_bfloat16* __restrict__ Wlo,
        const float* __restrict__ bias,
        float* __restrict__ outF,
        __nv_bfloat16* __restrict__ outBh,
        __nv_bfloat16* __restrict__ outBl,
        __half* __restrict__ outH, float oscale,
        int N, int row0, int col0) {
    extern __shared__ __nv_bfloat16 sm[];
    constexpr int SA = K + 8;
    __nv_bfloat16* sAh = sm;
    __nv_bfloat16* sAl = sm + 128 * SA;
    __nv_bfloat16* sWh = sm + 256 * SA;
    __nv_bfloat16* sWl = sWh + 64 * SA;

    const int tid = threadIdx.x, lane = tid & 31, warp = tid >> 5;

    constexpr int AV = K / 8;
    #pragma unroll 2
    for (int i = tid; i < 128 * AV; i += 512) {
        int r = i / AV, c = (i % AV) * 8;
        size_t g = (size_t)(row0 + r)*K + c;
        *reinterpret_cast<uint4*>(&sAh[r*SA + c]) = *reinterpret_cast<const uint4*>(&Ahi[g]);
        *reinterpret_cast<uint4*>(&sAl[r*SA + c]) = *reinterpret_cast<const uint4*>(&Alo[g]);
    }
    #pragma unroll 2
    for (int i = tid; i < 64 * K / 4; i += 512) {
        int k = i >> 4, n4 = (i & 15) * 4;
        size_t g = (size_t)k*N + col0 + n4;
        uint2 wh = *reinterpret_cast<const uint2*>(&Whi[g]);
        uint2 wl = *reinterpret_cast<const uint2*>(&Wlo[g]);
        __nv_bfloat16 th[4]; *reinterpret_cast<uint2*>(th) = wh;
        __nv_bfloat16 tl[4]; *reinterpret_cast<uint2*>(tl) = wl;
        #pragma unroll
        for (int j = 0; j < 4; j++) {
            sWh[(n4+j)*SA + k] = th[j];
            sWl[(n4+j)*SA + k] = tl[j];
        }
    }
    __syncthreads();

    float acc[4][4];
    #pragma unroll
    for (int i = 0; i < 4; i++)
        #pragma unroll
        for (int j = 0; j < 4; j++) acc[i][j] = 0.f;

    const int mwarp = warp >> 1, nwarp = warp & 1;
    const int ar = mwarp*16 + (lane >> 2);
    const int ac = (lane & 3) * 2;
    #pragma unroll
    for (int kk = 0; kk < K/16; kk++) {
        uint32_t ah[4], al[4];
        {
            const __nv_bfloat16* pa = &sAh[ar*SA + kk*16 + ac];
            ah[0] = *(const uint32_t*)pa;
            ah[1] = *(const uint32_t*)(pa + 8*SA);
            ah[2] = *(const uint32_t*)(pa + 8);
            ah[3] = *(const uint32_t*)(pa + 8*SA + 8);
            const __nv_bfloat16* pl = &sAl[ar*SA + kk*16 + ac];
            al[0] = *(const uint32_t*)pl;
            al[1] = *(const uint32_t*)(pl + 8*SA);
            al[2] = *(const uint32_t*)(pl + 8);
            al[3] = *(const uint32_t*)(pl + 8*SA + 8);
        }
        #pragma unroll
        for (int nt = 0; nt < 4; nt++) {
            int nrow = nwarp*32 + nt*8 + (lane>>2);
            const __nv_bfloat16* pbh = &sWh[nrow*SA + kk*16 + ac];
            uint32_t bh0 = *(const uint32_t*)pbh;
            uint32_t bh1 = *(const uint32_t*)(pbh + 8);
            const __nv_bfloat16* pbl = &sWl[nrow*SA + kk*16 + ac];
            uint32_t bl0 = *(const uint32_t*)pbl;
            uint32_t bl1 = *(const uint32_t*)(pbl + 8);
            mma16816(acc[nt], ah, bh0, bh1);
            mma16816(acc[nt], al, bh0, bh1);
            mma16816(acc[nt], ah, bl0, bl1);
        }
    }

    const int orow = row0 + mwarp*16 + (lane >> 2);
    #pragma unroll
    for (int nt = 0; nt < 4; nt++) {
        int c = col0 + nwarp*32 + nt*8 + (lane & 3)*2;
        float b0v = bias[c], b1v = bias[c+1];
        #pragma unroll
        for (int half = 0; half < 2; half++) {
            int r = orow + half*8;
            float v0 = acc[nt][half*2+0] + b0v;
            float v1 = acc[nt][half*2+1] + b1v;
            if (RELU) { v0 = fmaxf(v0, 0.f); v1 = fmaxf(v1, 0.f); }
            size_t o = (size_t)r*N + c;
            if (OUT_F32) { outF[o] = v0; outF[o+1] = v1; }
            if (OUT_B16) {
                __nv_bfloat16 h0, l0, h1, l1;
                fsplit(v0, h0, l0);
                fsplit(v1, h1, l1);
                outBh[o] = h0; outBh[o+1] = h1;
                outBl[o] = l0; outBl[o+1] = l1;
            }
            if (OUT_F16) {
                __half2 t = __floats2half2_rn(v0*oscale, v1*oscale);
                *reinterpret_cast<__half2*>(&outH[o]) = t;
            }
        }
    }
}

template<int K, bool OUT_B16, bool OUT_F32, bool RELU>
__global__ __launch_bounds__(512) void gemm_bias(
        const __nv_bfloat16* __restrict__ Ahi, const __nv_bfloat16* __restrict__ Alo,
        const __nv_bfloat16* __restrict__ Whi, const __nv_bfloat16* __restrict__ Wlo,
        const float* __restrict__ bias,
        float* __restrict__ outF,
        __nv_bfloat16* __restrict__ outBh, __nv_bfloat16* __restrict__ outBl,
        int N) {
    gemm_body<K, OUT_B16, OUT_F32, false, RELU>(Ahi, Alo, Whi, Wlo, bias,
        outF, outBh, outBl, nullptr, 1.f, N, blockIdx.x*128, blockIdx.y*64);
}

// Fused QKV: grid (126, 6); writes fp16 (Q pre-scaled by SCALE*log2e)
__global__ __launch_bounds__(512) void gemm_qkv(int layer) {
    int sel = blockIdx.y >> 1;
    int col0 = (blockIdx.y & 1) * 64;
    const __nv_bfloat16* Whi = g_qkvwh + ((size_t)(layer*3 + sel))*Dd*128;
    const __nv_bfloat16* Wlo = g_qkvwl + ((size_t)(layer*3 + sel))*Dd*128;
    const float* bias = g_qkvb + (layer*3 + sel)*128;
    __half* oh = g_qkv + (size_t)sel*BLd*128;
    float oscale = (sel == 0) ? SC2f : 1.f;
    gemm_body<256, false, false, true, false>(g_hhi, g_hlo, Whi, Wlo, bias,
        nullptr, nullptr, nullptr, oh, oscale, 128, blockIdx.x*128, col0);
}

// ---------------------------------------------------------------------------
// GEMM (tile 128 x 256, full rows) + fused residual + LayerNorm.
// ---------------------------------------------------------------------------
#define LNSS 260

template<int K>
__global__ __launch_bounds__(512) void gemm_ln(
        const __nv_bfloat16* __restrict__ Ahi,
        const __nv_bfloat16* __restrict__ Alo,
        const __nv_bfloat16* __restrict__ Whi,
        const __nv_bfloat16* __restrict__ Wlo,
        const float* __restrict__ bias,
        const float* __restrict__ gam,
        const float* __restrict__ bet) {
    extern __shared__ __nv_bfloat16 sm[];
    constexpr int SA = K + 8;
    __nv_bfloat16* sAh = sm;
    __nv_bfloat16* sAl = sm + 128 * SA;
    __nv_bfloat16* sWh = sm + 256 * SA;
    __nv_bfloat16* sWl = sWh + 256 * SA;
    float* sv = (float*)sm;

    const int tid = threadIdx.x, lane = tid & 31, warp = tid >> 5;
    const int row0 = blockIdx.x * 128;

    constexpr int AV = K / 8;
    #pragma unroll 2
    for (int i = tid; i < 128 * AV; i += 512) {
        int r = i / AV, c = (i % AV) * 8;
        size_t g = (size_t)(row0 + r)*K + c;
        *reinterpret_cast<uint4*>(&sAh[r*SA + c]) = *reinterpret_cast<const uint4*>(&Ahi[g]);
        *reinterpret_cast<uint4*>(&sAl[r*SA + c]) = *reinterpret_cast<const uint4*>(&Alo[g]);
    }
    #pragma unroll 2
    for (int i = tid; i < 256 * K / 4; i += 512) {
        int k = i / 64, n4 = (i % 64) * 4;
        size_t g = (size_t)k*Dd + n4;
        uint2 wh = *reinterpret_cast<const uint2*>(&Whi[g]);
        uint2 wl = *reinterpret_cast<const uint2*>(&Wlo[g]);
        __nv_bfloat16 th[4]; *reinterpret_cast<uint2*>(th) = wh;
        __nv_bfloat16 tl[4]; *reinterpret_cast<uint2*>(tl) = wl;
        #pragma unroll
        for (int j = 0; j < 4; j++) {
            sWh[(n4+j)*SA + k] = th[j];
            sWl[(n4+j)*SA + k] = tl[j];
        }
    }
    __syncthreads();

    float acc[16][4];
    #pragma unroll
    for (int i = 0; i < 16; i++)
        #pragma unroll
        for (int j = 0; j < 4; j++) acc[i][j] = 0.f;

    const int mwarp = warp >> 1, nwarp = warp & 1;
    const int ar = mwarp*16 + (lane >> 2);
    const int ac = (lane & 3) * 2;
    #pragma unroll
    for (int kk = 0; kk < K/16; kk++) {
        uint32_t ah[4], al[4];
        {
            const __nv_bfloat16* pa = &sAh[ar*SA + kk*16 + ac];
            ah[0] = *(const uint32_t*)pa;
            ah[1] = *(const uint32_t*)(pa + 8*SA);
            ah[2] = *(const uint32_t*)(pa + 8);
            ah[3] = *(const uint32_t*)(pa + 8*SA + 8);
            const __nv_bfloat16* pl = &sAl[ar*SA + kk*16 + ac];
            al[0] = *(const uint32_t*)pl;
            al[1] = *(const uint32_t*)(pl + 8*SA);
            al[2] = *(const uint32_t*)(pl + 8);
            al[3] = *(const uint32_t*)(pl + 8*SA + 8);
        }
        #pragma unroll
        for (int nt = 0; nt < 16; nt++) {
            int nrow = nwarp*128 + nt*8 + (lane>>2);
            const __nv_bfloat16* pbh = &sWh[nrow*SA + kk*16 + ac];
            uint32_t bh0 = *(const uint32_t*)pbh;
            uint32_t bh1 = *(const uint32_t*)(pbh + 8);
            const __nv_bfloat16* pbl = &sWl[nrow*SA + kk*16 + ac];
            uint32_t bl0 = *(const uint32_t*)pbl;
            uint32_t bl1 = *(const uint32_t*)(pbl + 8);
            mma16816(acc[nt], ah, bh0, bh1);
            mma16816(acc[nt], al, bh0, bh1);
            mma16816(acc[nt], ah, bl0, bl1);
        }
    }
    __syncthreads();

    {
        const int r0 = mwarp*16 + (lane >> 2);
        #pragma unroll
        for (int nt = 0; nt < 16; nt++) {
            int c = nwarp*128 + nt*8 + (lane & 3)*2;
            float b0v = bias[c], b1v = bias[c+1];
            sv[ r0     *LNSS + c]     = acc[nt][0] + b0v;
            sv[ r0     *LNSS + c + 1] = acc[nt][1] + b1v;
            sv[(r0 + 8)*LNSS + c]     = acc[nt][2] + b0v;
            sv[(r0 + 8)*LNSS + c + 1] = acc[nt][3] + b1v;
        }
    }
    __syncthreads();

    #pragma unroll 1
    for (int rr = 0; rr < 8; rr++) {
        int row = warp*8 + rr;
        int token = row0 + row;
        const float* hp = &g_h[(size_t)token*Dd];
        float x[8], s = 0.f;
        #pragma unroll
        for (int j = 0; j < 8; j++) {
            x[j] = hp[lane*8 + j] + sv[row*LNSS + lane*8 + j];
            s += x[j];
        }
        #pragma unroll
        for (int o = 16; o; o >>= 1) s += __shfl_xor_sync(~0u, s, o);
        float mean = s * (1.f/256.f);
        float v = 0.f;
        #pragma unroll
        for (int j = 0; j < 8; j++) { float d = x[j] - mean; v += d*d; }
        #pragma unroll
        for (int o = 16; o; o >>= 1) v += __shfl_xor_sync(~0u, v, o);
        float rstd = rsqrtf(v * (1.f/256.f) + EPSLN);
        float* op = &g_h[(size_t)token*Dd];
        #pragma unroll
        for (int j = 0; j < 8; j++) {
            int cix = lane*8 + j;
            float y = (x[j] - mean)*rstd*gam[cix] + bet[cix];
            op[cix] = y;
            size_t ix = (size_t)token*Dd + cix;
            __nv_bfloat16 hh, ll;
            fsplit(y, hh, ll);
            g_hhi[ix] = hh;
            g_hlo[ix] = ll;
        }
    }
}

// ---------------------------------------------------------------------------
// Attention v7 (fp16): 128-query tile, 256 threads (8 warps x 16 rows).
// Single-term fp16 MMA everywhere (Q pre-scaled by SCALE*log2e in QKV GEMM).
// Pass A: row sums (4-buffer K ring, 2 chunks/barrier). Pass B: QK (SW
// pipelined), P out (.cs), PV. smem 40KB -> 3 CTAs/SM.
// Zfilled padding keys -> score exactly 0 -> exp exactly 1 -> subtract 32.
// ---------------------------------------------------------------------------
#define QT 128
#define KT 128
#define NCH 16
#define NPAD 32.0f

#define BUFB 10240                 // bytes per 128x40-half buffer
#define SM_ATTN_BYTES (4*BUFB)     // 40960

// stage one 128-key fp16 chunk (zero-fill past Ld) into buffer at byte off
__device__ __forceinline__ void stage1(uint32_t sm_u, int bufoff, int ch,
        const __half* P, size_t base, int tid) {
    const int k0 = ch * KT;
    #pragma unroll
    for (int it = 0; it < 2; it++) {
        int o = tid + it*256;          // 512 transfers of 16B
        int r = o >> 2;
        int c = (o & 3) * 8;
        int s = k0 + r;
        bool ok = s < Ld;
        const __half* src = P + base + (size_t)(ok ? s : 0)*128 + c;
        uint32_t dst = sm_u + bufoff + (r*40 + c)*2;
        cpa16(dst, src, ok ? 16 : 0);
    }
}

// Pass A stats: 1-term fp16 QK; scores pre-scaled -> ex2 direct.
__device__ __forceinline__ void qk_stats_chunk(
        uint32_t kh_u, int laneK,
        const uint32_t aq[2][4],
        float& s0, float& s1) {
    #pragma unroll 2
    for (int gq = 0; gq < 4; gq++) {
        float acc[4][4];
        #pragma unroll
        for (int i = 0; i < 4; i++)
            #pragma unroll
            for (int j = 0; j < 4; j++) acc[i][j] = 0.f;
        #pragma unroll
        for (int pair = 0; pair < 2; pair++) {
            int be = (gq*32 + pair*16)*40;
            #pragma unroll
            for (int kk = 0; kk < 2; kk++) {
                uint32_t b0, b1, b2, b3;
                uint32_t off = (be + kk*16 + laneK)*2;
                ldsm4(b0, b1, b2, b3, kh_u + off);
                mma16816h(acc[pair*2  ], aq[kk], b0, b1);
                mma16816h(acc[pair*2+1], aq[kk], b2, b3);
            }
        }
        #pragma unroll
        for (int nt = 0; nt < 4; nt++) {
            s0 += ex2(acc[nt][0]) + ex2(acc[nt][1]);
            s1 += ex2(acc[nt][2]) + ex2(acc[nt][3]);
        }
    }
}

// Pass B: 1-term QK accs for one 16-key group.
__device__ __forceinline__ void qk_group(
        uint32_t kh_u, int laneK, int kbe,
        const uint32_t aq[2][4], float acc[2][4]) {
    #pragma unroll
    for (int i = 0; i < 2; i++)
        #pragma unroll
        for (int j = 0; j < 4; j++) acc[i][j] = 0.f;
    #pragma unroll
    for (int kk = 0; kk < 2; kk++) {
        uint32_t b0, b1, b2, b3;
        uint32_t off = (kbe + kk*16 + laneK)*2;
        ldsm4(b0, b1, b2, b3, kh_u + off);
        mma16816h(acc[0], aq[kk], b0, b1);
        mma16816h(acc[1], aq[kk], b2, b3);
    }
}

// Pass B: exp, store P, PV for one group.
template<bool MASK>
__device__ __forceinline__ void emit_group(
        uint32_t vh_u, int laneV, int g, int k0, int fc,
        float inv0, float inv1,
        float* prow0, float* prow1, bool wr0, bool wr1,
        const float acc[2][4], float oacc[4][4]) {
    int kbe = g*16*40;
    int colb = k0 + g*16 + fc;
    bool ok0 = !MASK || (colb < Ld);
    bool ok1 = !MASK || (colb + 8 < Ld);
    float p00 = ok0 ? ex2(acc[0][0])*inv0 : 0.f;
    float p01 = ok0 ? ex2(acc[0][1])*inv0 : 0.f;
    float p02 = ok0 ? ex2(acc[0][2])*inv1 : 0.f;
    float p03 = ok0 ? ex2(acc[0][3])*inv1 : 0.f;
    float p10 = ok1 ? ex2(acc[1][0])*inv0 : 0.f;
    float p11 = ok1 ? ex2(acc[1][1])*inv0 : 0.f;
    float p12 = ok1 ? ex2(acc[1][2])*inv1 : 0.f;
    float p13 = ok1 ? ex2(acc[1][3])*inv1 : 0.f;

    if (wr0) {
        if (ok0) stcs2(&prow0[colb],     p00, p01);
        if (ok1) stcs2(&prow0[colb + 8], p10, p11);
    }
    if (wr1) {
        if (ok0) stcs2(&prow1[colb],     p02, p03);
        if (ok1) stcs2(&prow1[colb + 8], p12, p13);
    }

    uint32_t ah[4];
    ah[0] = pk2h(p00, p01);
    ah[1] = pk2h(p02, p03);
    ah[2] = pk2h(p10, p11);
    ah[3] = pk2h(p12, p13);

    #pragma unroll
    for (int dp = 0; dp < 2; dp++) {
        uint32_t v0, v1, v2, v3;
        uint32_t off = (kbe + dp*16 + laneV)*2;
        ldsm4t(v0, v1, v2, v3, vh_u + off);
        mma16816h(oacc[dp*2  ], ah, v0, v1);
        mma16816h(oacc[dp*2+1], ah, v2, v3);
    }
}

// Pass B chunk: 2-stage software pipeline over 8 groups.
template<bool MASK>
__device__ __forceinline__ void qk_emit_chunk(
        uint32_t kh_u, uint32_t vh_u, int laneK, int laneV,
        const uint32_t aq[2][4],
        int k0, int fc, float inv0, float inv1,
        float* prow0, float* prow1, bool wr0, bool wr1,
        float oacc[4][4]) {
    float aA[2][4], aB[2][4];
    qk_group(kh_u, laneK, 0, aq, aA);
    #pragma unroll
    for (int g = 0; g < 8; g += 2) {
        qk_group(kh_u, laneK, (g+1)*640, aq, aB);
        emit_group<MASK>(vh_u, laneV, g, k0, fc, inv0, inv1,
                         prow0, prow1, wr0, wr1, aA, oacc);
        if (g + 2 < 8)
            qk_group(kh_u, laneK, (g+2)*640, aq, aA);
        emit_group<MASK>(vh_u, laneV, g+1, k0, fc, inv0, inv1,
                         prow0, prow1, wr0, wr1, aB, oacc);
    }
}

__global__ __launch_bounds__(256, 3) void attn_kernel(
        const __half* __restrict__ qkv,
        float* __restrict__ Pout,
        __nv_bfloat16* __restrict__ Oh, __nv_bfloat16* __restrict__ Ol) {
    extern __shared__ __half smh[];
    uint32_t sm_u = (uint32_t)__cvta_generic_to_shared(smh);

    const int tid = threadIdx.x, lane = tid & 31, warp = tid >> 5;
    const int bh = blockIdx.y;
    const int b  = bh >> 2, h = bh & 3;
    const int q0 = blockIdx.x * QT;
    const size_t base = ((size_t)b*Ld*Hd + h)*DKd;
    const __half* Q = qkv;
    const __half* K = qkv + (size_t)BLd*128;
    const __half* V = qkv + (size_t)2*BLd*128;

    const int mrow = warp * 16;
    const int fr = lane >> 2, fc = (lane & 3) * 2;
    const int lr = lane & 7, sel = lane >> 3;
    const int laneK = ((sel>>1)*8 + lr)*40 + (sel&1)*8;
    const int laneV = ((sel&1)*8 + lr)*40 + (sel>>1)*8;

    // ---- Q fragments straight from gmem (already scaled by SC2f) ----
    const int r0g = q0 + mrow + fr, r1g = r0g + 8;
    const bool q0ok = (r0g < Ld), q1ok = (r1g < Ld);
    uint32_t aq[2][4];
    #pragma unroll
    for (int kk = 0; kk < 2; kk++) {
        int c = kk*16 + fc;
        size_t g0 = base + (size_t)r0g*128 + c;
        size_t g1 = base + (size_t)r1g*128 + c;
        aq[kk][0] = q0ok ? *(const uint32_t*)&Q[g0]     : 0;
        aq[kk][1] = q1ok ? *(const uint32_t*)&Q[g1]     : 0;
        aq[kk][2] = q0ok ? *(const uint32_t*)&Q[g0 + 8] : 0;
        aq[kk][3] = q1ok ? *(const uint32_t*)&Q[g1 + 8] : 0;
    }

    float s0 = 0.f, s1 = 0.f;

    // ======== PASS A: row sums (K only, 4-buffer ring, 2 chunks/sync) ====
    stage1(sm_u, 0*BUFB, 0, K, base, tid);
    stage1(sm_u, 1*BUFB, 1, K, base, tid); cpa_commit();
    stage1(sm_u, 2*BUFB, 2, K, base, tid);
    stage1(sm_u, 3*BUFB, 3, K, base, tid); cpa_commit();
    #pragma unroll 1
    for (int it = 0; it < 8; it++) {
        if (it < 7) cpa_wait<1>(); else cpa_wait<0>();
        __syncthreads();
        int b0 = (it & 1) ? 2 : 0;
        qk_stats_chunk(sm_u + b0*BUFB,     laneK, aq, s0, s1);
        qk_stats_chunk(sm_u + (b0+1)*BUFB, laneK, aq, s0, s1);
        __syncthreads();
        if (it < 6) {
            stage1(sm_u, b0*BUFB,     2*it+4, K, base, tid);
            stage1(sm_u, (b0+1)*BUFB, 2*it+5, K, base, tid);
            cpa_commit();
        }
    }

    // prologue for pass B overlaps the reduction: K in bufs 0/1, V in 2/3
    stage1(sm_u, 0*BUFB, 0, K, base, tid);
    stage1(sm_u, 2*BUFB, 0, V, base, tid); cpa_commit();
    stage1(sm_u, 1*BUFB, 1, K, base, tid);
    stage1(sm_u, 3*BUFB, 1, V, base, tid); cpa_commit();

    s0 += __shfl_xor_sync(~0u, s0, 1);
    s0 += __shfl_xor_sync(~0u, s0, 2);
    s1 += __shfl_xor_sync(~0u, s1, 1);
    s1 += __shfl_xor_sync(~0u, s1, 2);
    s0 -= NPAD;
    s1 -= NPAD;
    const float inv0 = 1.f / s0, inv1 = 1.f / s1;

    // ======== PASS B: P out + PV ========
    float oacc[4][4];
    #pragma unroll
    for (int i = 0; i < 4; i++)
        #pragma unroll
        for (int j = 0; j < 4; j++) oacc[i][j] = 0.f;

    float* prow0 = &Pout[((size_t)bh*Ld + r0g)*Ld];
    float* prow1 = prow0 + 8*(size_t)Ld;

    #pragma unroll 1
    for (int ch = 0; ch < NCH; ch++) {
        if (ch < NCH-1) cpa_wait<1>(); else cpa_wait<0>();
        __syncthreads();
        int buf = ch & 1;
        uint32_t kh_u = sm_u + buf*BUFB;
        uint32_t vh_u = sm_u + (2 + buf)*BUFB;
        if (ch < NCH-1)
            qk_emit_chunk<false>(kh_u, vh_u, laneK, laneV, aq,
                                 ch*KT, fc, inv0, inv1, prow0, prow1, q0ok, q1ok, oacc);
        else
            qk_emit_chunk<true >(kh_u, vh_u, laneK, laneV, aq,
                                 ch*KT, fc, inv0, inv1, prow0, prow1, q0ok, q1ok, oacc);
        __syncthreads();
        if (ch + 2 < NCH) {
            stage1(sm_u, buf*BUFB,       ch+2, K, base, tid);
            stage1(sm_u, (2 + buf)*BUFB, ch+2, V, base, tid);
            cpa_commit();
        }
    }

    // ---- write O (split bf16) ----
    #pragma unroll
    for (int dt = 0; dt < 4; dt++) {
        int d = dt*8 + fc;
        if (q0ok) {
            size_t g = base + (size_t)r0g*128 + d;
            __nv_bfloat16 hh, ll;
            fsplit(oacc[dt][0], hh, ll); Oh[g]   = hh; Ol[g]   = ll;
            fsplit(oacc[dt][1], hh, ll); Oh[g+1] = hh; Ol[g+1] = ll;
        }
        if (q1ok) {
            size_t g = base + (size_t)r1g*128 + d;
            __nv_bfloat16 hh, ll;
            fsplit(oacc[dt][2], hh, ll); Oh[g]   = hh; Ol[g]   = ll;
            fsplit(oacc[dt][3], hh, ll); Oh[g+1] = hh; Ol[g+1] = ll;
        }
    }
}

// ---------------------------------------------------------------------------
// Final head tail: out = relu_h(g_tmp fp32) @ o2w + o2b   (warp per token)
// ---------------------------------------------------------------------------
__global__ __launch_bounds__(256) void head2_kernel(const float* __restrict__ o2w,
                                                    const float* __restrict__ o2b,
                                                    float* __restrict__ out) {
    int warp = threadIdx.x >> 5, lane = threadIdx.x & 31;
    int token = blockIdx.x * 8 + warp;
    const float* hp = &g_tmp[(size_t)token*Dd];
    float a0 = 0.f, a1 = 0.f;
    #pragma unroll
    for (int j = 0; j < 8; j++) {
        int k = lane + j*32;
        float hv = hp[k];
        a0 = fmaf(hv, o2w[k*2],   a0);
        a1 = fmaf(hv, o2w[k*2+1], a1);
    }
    #pragma unroll
    for (int o = 16; o; o >>= 1) {
        a0 += __shfl_xor_sync(~0u, a0, o);
        a1 += __shfl_xor_sync(~0u, a1, o);
    }
    if (lane == 0) {
        out[(size_t)token*2]     = a0 + o2b[0];
        out[(size_t)token*2 + 1] = a1 + o2b[1];
    }
}

// ---------------------------------------------------------------------------
// Host orchestration
// ---------------------------------------------------------------------------
static inline void* symaddr(const void* s) {
    void* p = nullptr;
    cudaGetSymbolAddress(&p, s);
    return p;
}

extern "C" void kernel_launch(void* const* d_in, const int* in_sizes, int n_in,
                              void* d_out, int out_size) {
    const float* x    = (const float*)d_in[0];
    const float* in_w = (const float*)d_in[1];
    const float* in_b = (const float*)d_in[2];
    const float* qw   = (const float*)d_in[3];
    const float* qb   = (const float*)d_in[4];
    const float* kw   = (const float*)d_in[5];
    const float* kb   = (const float*)d_in[6];
    const float* vw   = (const float*)d_in[7];
    const float* vb   = (const float*)d_in[8];
    const float* ow   = (const float*)d_in[9];
    const float* ob   = (const float*)d_in[10];
    const float* f1w  = (const float*)d_in[11];
    const float* f1b  = (const float*)d_in[12];
    const float* f2w  = (const float*)d_in[13];
    const float* f2b  = (const float*)d_in[14];
    const float* n1g  = (const float*)d_in[15];
    const float* n1b  = (const float*)d_in[16];
    const float* n2g  = (const float*)d_in[17];
    const float* n2b  = (const float*)d_in[18];
    const float* o1w  = (const float*)d_in[19];
    const float* o1b  = (const float*)d_in[20];
    const float* o2w  = (const float*)d_in[21];
    const float* o2b  = (const float*)d_in[22];

    float* outp     = (float*)d_out;
    float* attn_out = outp + (size_t)Bd*Ld*2;

    __nv_bfloat16* p_hh   = (__nv_bfloat16*)symaddr(g_hhi);
    __nv_bfloat16* p_hl   = (__nv_bfloat16*)symaddr(g_hlo);
    __half*        p_qkv  = (__half*)symaddr(g_qkv);
    __nv_bfloat16* p_oh   = (__nv_bfloat16*)symaddr(g_ohi);
    __nv_bfloat16* p_ol   = (__nv_bfloat16*)symaddr(g_olo);
    __nv_bfloat16* p_fh   = (__nv_bfloat16*)symaddr(g_fhi);
    __nv_bfloat16* p_fl   = (__nv_bfloat16*)symaddr(g_flo);
    float*         p_tmp  = (float*)symaddr(g_tmp);
    __nv_bfloat16* p_owh  = (__nv_bfloat16*)symaddr(g_owh);
    __nv_bfloat16* p_owl  = (__nv_bfloat16*)symaddr(g_owl);
    __nv_bfloat16* p_f1h  = (__nv_bfloat16*)symaddr(g_f1wh);
    __nv_bfloat16* p_f1l  = (__nv_bfloat16*)symaddr(g_f1wl);
    __nv_bfloat16* p_f2h  = (__nv_bfloat16*)symaddr(g_f2wh);
    __nv_bfloat16* p_f2l  = (__nv_bfloat16*)symaddr(g_f2wl);
    __nv_bfloat16* p_o1h  = (__nv_bfloat16*)symaddr(g_o1wh);
    __nv_bfloat16* p_o1l  = (__nv_bfloat16*)symaddr(g_o1wl);

    const int SM_G256  = 384*(256+8)*2;                       // 202752
    const int SM_LN128 = (2*128*(128+8) + 2*256*(128+8))*2;   // 208896
    const int SM_LN64_OP = (2*128*(64+8) + 2*256*(64+8))*2;   // 110592
    const int SM_LNSLAB  = 128*LNSS*4;                        // 133120
    const int SM_LN64  = SM_LN64_OP > SM_LNSLAB ? SM_LN64_OP : SM_LNSLAB;

    cudaFuncSetAttribute(gemm_qkv, cudaFuncAttributeMaxDynamicSharedMemorySize, SM_G256);
    cudaFuncSetAttribute(gemm_bias<256,true ,false,true >, cudaFuncAttributeMaxDynamicSharedMemorySize, SM_G256);
    cudaFuncSetAttribute(gemm_bias<256,false,true ,true >, cudaFuncAttributeMaxDynamicSharedMemorySize, SM_G256);
    cudaFuncSetAttribute(gemm_ln<128>, cudaFuncAttributeMaxDynamicSharedMemorySize, SM_LN128);
    cudaFuncSetAttribute(gemm_ln<64 >, cudaFuncAttributeMaxDynamicSharedMemorySize, SM_LN64);
    cudaFuncSetAttribute(attn_kernel, cudaFuncAttributeMaxDynamicSharedMemorySize, SM_ATTN_BYTES);

    convert_w<<<384, 256>>>(qw, kw, vw, ow, f1w, f2w, o1w, qb, kb, vb);
    embed_kernel<<<BLd, Dd>>>(x, in_w, in_b);

    const dim3 gQKV (BLd/128, 6);
    const dim3 gProj(BLd/128, 4);   // N=256 (head only)
    const dim3 gF1  (BLd/128, 1);   // N=64
    const dim3 gLN  (BLd/128);
    const dim3 gAttn((Ld + QT - 1)/QT, Bd*Hd);

    for (int i = 0; i < NLd; i++) {
        gemm_qkv<<<gQKV, 512, SM_G256>>>(i);

        attn_kernel<<<gAttn, 256, SM_ATTN_BYTES>>>(
            p_qkv, attn_out + (size_t)i*Bd*Hd*Ld*Ld, p_oh, p_ol);

        // o-projection + residual + LN1 (fused)
        gemm_ln<128><<<gLN, 512, SM_LN128>>>(
            p_oh, p_ol, p_owh + (size_t)i*128*Dd, p_owl + (size_t)i*128*Dd,
            ob + i*Dd, n1g + i*Dd, n1b + i*Dd);

        // FFN1 (relu, split bf16 out)
        gemm_bias<256,true,false,true><<<gF1, 512, SM_G256>>>(
            p_hh, p_hl, p_f1h + (size_t)i*Dd*FCd, p_f1l + (size_t)i*Dd*FCd,
            f1b + i*FCd, nullptr, p_fh, p_fl, FCd);

        // FFN2 + residual + LN2 (fused)
        gemm_ln<64><<<gLN, 512, SM_LN64>>>(
            p_fh, p_fl, p_f2h + (size_t)i*FCd*Dd, p_f2l + (size_t)i*FCd*Dd,
            f2b + i*Dd, n2g + i*Dd, n2b + i*Dd);
    }

    gemm_bias<256,false,true,true><<<gProj, 512, SM_G256>>>(
        p_hh, p_hl, p_o1h, p_o1l, o1b, p_tmp, nullptr, nullptr, Dd);
    head2_kernel<<<BLd/8, 256>>>(o2w, o2b, outp);
}

// round 12
// speedup vs baseline: 6.9536x; 1.1678x over previous
#include <cuda_runtime.h>
#include <cuda_bf16.h>
#include <cuda_fp16.h>
#include <stdint.h>

#define Bd  8
#define Ld  2016
#define Hd  4
#define DKd 32
#define Dd  256
#define FCd 64
#define NLd 3
#define BLd (Bd*Ld)          // 16128 tokens

#define SC2f 0.09016844005556f   // (1/sqrt(256)) * log2(e)
#define EPSLN 1e-5f

// ---------------------------------------------------------------------------
// Device scratch. Residual stream: fp32 + split fp16. Weights: fp16.
// ---------------------------------------------------------------------------
__device__ __align__(128) float   g_h    [BLd*Dd];
__device__ __align__(128) __half  g_hh   [BLd*Dd];
__device__ __align__(128) __half  g_hl   [BLd*Dd];
__device__ __align__(128) __half  g_qkv  [3*BLd*128];   // fp16 (Q pre-scaled)
__device__ __align__(128) __half  g_oh   [BLd*128];
__device__ __align__(128) __half  g_ol   [BLd*128];
__device__ __align__(128) float   g_tmp  [BLd*Dd];
__device__ __align__(128) __half  g_fh   [BLd*FCd];
__device__ __align__(128) __half  g_fl   [BLd*FCd];
// fp16 weights
__device__ __align__(128) __half  g_qkvw [NLd*3*Dd*128];
__device__ __align__(128) float   g_qkvb [NLd*3*128];
__device__ __align__(128) __half  g_ow   [NLd*128*Dd];
__device__ __align__(128) __half  g_f1w  [NLd*Dd*FCd];
__device__ __align__(128) __half  g_f2w  [NLd*FCd*Dd];
__device__ __align__(128) __half  g_o1w  [Dd*Dd];

// ---------------------------------------------------------------------------
// helpers
// ---------------------------------------------------------------------------
__device__ __forceinline__ void mma16816h(float* d, const uint32_t* a,
                                          uint32_t b0, uint32_t b1) {
    asm volatile(
        "mma.sync.aligned.m16n8k16.row.col.f32.f16.f16.f32 "
        "{%0,%1,%2,%3}, {%4,%5,%6,%7}, {%8,%9}, {%0,%1,%2,%3};"
        : "+f"(d[0]), "+f"(d[1]), "+f"(d[2]), "+f"(d[3])
        : "r"(a[0]), "r"(a[1]), "r"(a[2]), "r"(a[3]), "r"(b0), "r"(b1));
}

__device__ __forceinline__ void ldsm4(uint32_t& r0, uint32_t& r1,
                                      uint32_t& r2, uint32_t& r3, uint32_t a) {
    asm volatile("ldmatrix.sync.aligned.m8n8.x4.shared.b16 {%0,%1,%2,%3}, [%4];"
        : "=r"(r0), "=r"(r1), "=r"(r2), "=r"(r3) : "r"(a));
}

__device__ __forceinline__ void ldsm4t(uint32_t& r0, uint32_t& r1,
                                       uint32_t& r2, uint32_t& r3, uint32_t a) {
    asm volatile("ldmatrix.sync.aligned.m8n8.x4.trans.shared.b16 {%0,%1,%2,%3}, [%4];"
        : "=r"(r0), "=r"(r1), "=r"(r2), "=r"(r3) : "r"(a));
}

__device__ __forceinline__ void cpa16(uint32_t dst, const void* src, int srcsize) {
    asm volatile("cp.async.cg.shared.global [%0], [%1], 16, %2;"
        :: "r"(dst), "l"(src), "r"(srcsize));
}
__device__ __forceinline__ void cpa_commit() {
    asm volatile("cp.async.commit_group;" ::: "memory");
}
template<int N>
__device__ __forceinline__ void cpa_wait() {
    asm volatile("cp.async.wait_group %0;" :: "n"(N) : "memory");
}

__device__ __forceinline__ float ex2(float x) {
    float y;
    asm("ex2.approx.ftz.f32 %0, %1;" : "=f"(y) : "f"(x));
    return y;
}

__device__ __forceinline__ uint32_t pk2h(float x, float y) {
    __half2 t = __floats2half2_rn(x, y);
    return *reinterpret_cast<uint32_t*>(&t);
}

__device__ __forceinline__ void fsplit_h(float v, __half& hi, __half& lo) {
    hi = __float2half_rn(v);
    lo = __float2half_rn(v - __half2float(hi));
}

__device__ __forceinline__ void stcs2(float* p, float a, float b) {
    asm volatile("st.global.cs.v2.f32 [%0], {%1,%2};" :: "l"(p), "f"(a), "f"(b));
}

// ---------------------------------------------------------------------------
// Weight conversion fp32 -> fp16 (+ QKV packing)
// ---------------------------------------------------------------------------
__global__ void convert_w(const float* __restrict__ qw, const float* __restrict__ kw,
                          const float* __restrict__ vw, const float* __restrict__ ow,
                          const float* __restrict__ f1w, const float* __restrict__ f2w,
                          const float* __restrict__ o1w,
                          const float* __restrict__ qb, const float* __restrict__ kb,
                          const float* __restrict__ vb) {
    int i = blockIdx.x * 256 + threadIdx.x;
    const int n1 = NLd*Dd*128;
    const int n3 = NLd*Dd*FCd;
    const int n5 = Dd*Dd;
    if (i < n1) {
        int l = i / (Dd*128), rem = i % (Dd*128);
        size_t b = (size_t)(l*3)*Dd*128 + rem;
        g_qkvw[b]            = __float2half_rn(qw[i]);
        g_qkvw[b + Dd*128]   = __float2half_rn(kw[i]);
        g_qkvw[b + 2*Dd*128] = __float2half_rn(vw[i]);
        g_ow[i]              = __float2half_rn(ow[i]);
    }
    if (i < n3) {
        g_f1w[i] = __float2half_rn(f1w[i]);
        g_f2w[i] = __float2half_rn(f2w[i]);
    }
    if (i < n5) g_o1w[i] = __float2half_rn(o1w[i]);
    if (i < NLd*128) {
        int l = i >> 7, n = i & 127;
        g_qkvb[(l*3+0)*128 + n] = qb[i];
        g_qkvb[(l*3+1)*128 + n] = kb[i];
        g_qkvb[(l*3+2)*128 + n] = vb[i];
    }
}

// ---------------------------------------------------------------------------
// Embed: h = x @ in_w + in_b (fp32 + split fp16)
// ---------------------------------------------------------------------------
__global__ void embed_kernel(const float* __restrict__ x,
                             const float* __restrict__ in_w,
                             const float* __restrict__ in_b) {
    int t = blockIdx.x, d = threadIdx.x;
    float x0 = x[t*2], x1 = x[t*2+1];
    float v = fmaf(x0, in_w[d], fmaf(x1, in_w[Dd + d], in_b[d]));
    size_t ix = (size_t)t*Dd + d;
    g_h[ix] = v;
    fsplit_h(v, g_hh[ix], g_hl[ix]);
}

// ---------------------------------------------------------------------------
// GEMM core: tile 128x64, 512 threads. 2-term split fp16 MMA
// (A = hi+lo fp16, W = single fp16). OM: 0=fp32, 1=split fp16, 2=fp16*scale.
// ---------------------------------------------------------------------------
template<int K, int OM, bool RELU>
__device__ __forceinline__ void gemm_body(
        const __half* __restrict__ Ahi,
        const __half* __restrict__ Alo,
        const __half* __restrict__ W,
        const float* __restrict__ bias,
        float* __restrict__ outF,
        __half* __restrict__ outH1,
        __half* __restrict__ outH2, float oscale,
        int N, int row0, int col0) {
    extern __shared__ __half smh[];
    constexpr int SA = K + 8;
    __half* sAh = smh;
    __half* sAl = smh + 128 * SA;
    __half* sW  = smh + 256 * SA;

    const int tid = threadIdx.x, lane = tid & 31, warp = tid >> 5;

    constexpr int AV = K / 8;
    #pragma unroll 2
    for (int i = tid; i < 128 * AV; i += 512) {
        int r = i / AV, c = (i % AV) * 8;
        size_t g = (size_t)(row0 + r)*K + c;
        *reinterpret_cast<uint4*>(&sAh[r*SA + c]) = *reinterpret_cast<const uint4*>(&Ahi[g]);
        *reinterpret_cast<uint4*>(&sAl[r*SA + c]) = *reinterpret_cast<const uint4*>(&Alo[g]);
    }
    #pragma unroll 2
    for (int i = tid; i < 64 * K / 4; i += 512) {
        int k = i >> 4, n4 = (i & 15) * 4;
        size_t g = (size_t)k*N + col0 + n4;
        uint2 w2 = *reinterpret_cast<const uint2*>(&W[g]);
        __half tw[4]; *reinterpret_cast<uint2*>(tw) = w2;
        #pragma unroll
        for (int j = 0; j < 4; j++) sW[(n4+j)*SA + k] = tw[j];
    }
    __syncthreads();

    float acc[4][4];
    #pragma unroll
    for (int i = 0; i < 4; i++)
        #pragma unroll
        for (int j = 0; j < 4; j++) acc[i][j] = 0.f;

    const int mwarp = warp >> 1, nwarp = warp & 1;
    const int ar = mwarp*16 + (lane >> 2);
    const int ac = (lane & 3) * 2;
    #pragma unroll
    for (int kk = 0; kk < K/16; kk++) {
        uint32_t ah[4], al[4];
        {
            const __half* pa = &sAh[ar*SA + kk*16 + ac];
            ah[0] = *(const uint32_t*)pa;
            ah[1] = *(const uint32_t*)(pa + 8*SA);
            ah[2] = *(const uint32_t*)(pa + 8);
            ah[3] = *(const uint32_t*)(pa + 8*SA + 8);
            const __half* pl = &sAl[ar*SA + kk*16 + ac];
            al[0] = *(const uint32_t*)pl;
            al[1] = *(const uint32_t*)(pl + 8*SA);
            al[2] = *(const uint32_t*)(pl + 8);
            al[3] = *(const uint32_t*)(pl + 8*SA + 8);
        }
        #pragma unroll
        for (int nt = 0; nt < 4; nt++) {
            int nrow = nwarp*32 + nt*8 + (lane>>2);
            const __half* pb = &sW[nrow*SA + kk*16 + ac];
            uint32_t b0 = *(const uint32_t*)pb;
            uint32_t b1 = *(const uint32_t*)(pb + 8);
            mma16816h(acc[nt], ah, b0, b1);
            mma16816h(acc[nt], al, b0, b1);
        }
    }

    const int orow = row0 + mwarp*16 + (lane >> 2);
    #pragma unroll
    for (int nt = 0; nt < 4; nt++) {
        int c = col0 + nwarp*32 + nt*8 + (lane & 3)*2;
        float b0v = bias[c], b1v = bias[c+1];
        #pragma unroll
        for (int half = 0; half < 2; half++) {
            int r = orow + half*8;
            float v0 = acc[nt][half*2+0] + b0v;
            float v1 = acc[nt][half*2+1] + b1v;
            if (RELU) { v0 = fmaxf(v0, 0.f); v1 = fmaxf(v1, 0.f); }
            size_t o = (size_t)r*N + c;
            if (OM == 0) { outF[o] = v0; outF[o+1] = v1; }
            if (OM == 1) {
                __half h0, l0, h1, l1;
                fsplit_h(v0, h0, l0);
                fsplit_h(v1, h1, l1);
                outH1[o] = h0; outH1[o+1] = h1;
                outH2[o] = l0; outH2[o+1] = l1;
            }
            if (OM == 2) {
                __half2 t = __floats2half2_rn(v0*oscale, v1*oscale);
                *reinterpret_cast<__half2*>(&outH1[o]) = t;
            }
        }
    }
}

template<int K, int OM, bool RELU>
__global__ __launch_bounds__(512) void gemm_bias(
        const __half* __restrict__ Ahi, const __half* __restrict__ Alo,
        const __half* __restrict__ W,
        const float* __restrict__ bias,
        float* __restrict__ outF,
        __half* __restrict__ outH1, __half* __restrict__ outH2,
        int N) {
    gemm_body<K, OM, RELU>(Ahi, Alo, W, bias, outF, outH1, outH2, 1.f,
                           N, blockIdx.x*128, blockIdx.y*64);
}

// Fused QKV: grid (126, 6); writes fp16 (Q pre-scaled by SCALE*log2e)
__global__ __launch_bounds__(512) void gemm_qkv(int layer) {
    int sel = blockIdx.y >> 1;
    int col0 = (blockIdx.y & 1) * 64;
    const __half* W = g_qkvw + ((size_t)(layer*3 + sel))*Dd*128;
    const float* bias = g_qkvb + (layer*3 + sel)*128;
    __half* oh = g_qkv + (size_t)sel*BLd*128;
    float oscale = (sel == 0) ? SC2f : 1.f;
    gemm_body<256, 2, false>(g_hh, g_hl, W, bias, nullptr, oh, nullptr, oscale,
                             128, blockIdx.x*128, col0);
}

// ---------------------------------------------------------------------------
// GEMM (tile 128 x 256, full rows) + fused residual + LayerNorm.
// A = split fp16, W = single fp16, 2-term MMA.
// ---------------------------------------------------------------------------
#define LNSS 260

template<int K>
__global__ __launch_bounds__(512) void gemm_ln(
        const __half* __restrict__ Ahi,
        const __half* __restrict__ Alo,
        const __half* __restrict__ W,
        const float* __restrict__ bias,
        const float* __restrict__ gam,
        const float* __restrict__ bet) {
    extern __shared__ __half smh[];
    constexpr int SA = K + 8;
    __half* sAh = smh;
    __half* sAl = smh + 128 * SA;
    __half* sW  = smh + 256 * SA;
    float* sv = (float*)smh;

    const int tid = threadIdx.x, lane = tid & 31, warp = tid >> 5;
    const int row0 = blockIdx.x * 128;

    constexpr int AV = K / 8;
    #pragma unroll 2
    for (int i = tid; i < 128 * AV; i += 512) {
        int r = i / AV, c = (i % AV) * 8;
        size_t g = (size_t)(row0 + r)*K + c;
        *reinterpret_cast<uint4*>(&sAh[r*SA + c]) = *reinterpret_cast<const uint4*>(&Ahi[g]);
        *reinterpret_cast<uint4*>(&sAl[r*SA + c]) = *reinterpret_cast<const uint4*>(&Alo[g]);
    }
    #pragma unroll 2
    for (int i = tid; i < 256 * K / 4; i += 512) {
        int k = i / 64, n4 = (i % 64) * 4;
        size_t g = (size_t)k*Dd + n4;
        uint2 w2 = *reinterpret_cast<const uint2*>(&W[g]);
        __half tw[4]; *reinterpret_cast<uint2*>(tw) = w2;
        #pragma unroll
        for (int j = 0; j < 4; j++) sW[(n4+j)*SA + k] = tw[j];
    }
    __syncthreads();

    float acc[16][4];
    #pragma unroll
    for (int i = 0; i < 16; i++)
        #pragma unroll
        for (int j = 0; j < 4; j++) acc[i][j] = 0.f;

    const int mwarp = warp >> 1, nwarp = warp & 1;
    const int ar = mwarp*16 + (lane >> 2);
    const int ac = (lane & 3) * 2;
    #pragma unroll
    for (int kk = 0; kk < K/16; kk++) {
        uint32_t ah[4], al[4];
        {
            const __half* pa = &sAh[ar*SA + kk*16 + ac];
            ah[0] = *(const uint32_t*)pa;
            ah[1] = *(const uint32_t*)(pa + 8*SA);
            ah[2] = *(const uint32_t*)(pa + 8);
            ah[3] = *(const uint32_t*)(pa + 8*SA + 8);
            const __half* pl = &sAl[ar*SA + kk*16 + ac];
            al[0] = *(const uint32_t*)pl;
            al[1] = *(const uint32_t*)(pl + 8*SA);
            al[2] = *(const uint32_t*)(pl + 8);
            al[3] = *(const uint32_t*)(pl + 8*SA + 8);
        }
        #pragma unroll
        for (int nt = 0; nt < 16; nt++) {
            int nrow = nwarp*128 + nt*8 + (lane>>2);
            const __half* pb = &sW[nrow*SA + kk*16 + ac];
            uint32_t b0 = *(const uint32_t*)pb;
            uint32_t b1 = *(const uint32_t*)(pb + 8);
            mma16816h(acc[nt], ah, b0, b1);
            mma16816h(acc[nt], al, b0, b1);
        }
    }
    __syncthreads();

    {
        const int r0 = mwarp*16 + (lane >> 2);
        #pragma unroll
        for (int nt = 0; nt < 16; nt++) {
            int c = nwarp*128 + nt*8 + (lane & 3)*2;
            float b0v = bias[c], b1v = bias[c+1];
            sv[ r0     *LNSS + c]     = acc[nt][0] + b0v;
            sv[ r0     *LNSS + c + 1] = acc[nt][1] + b1v;
            sv[(r0 + 8)*LNSS + c]     = acc[nt][2] + b0v;
            sv[(r0 + 8)*LNSS + c + 1] = acc[nt][3] + b1v;
        }
    }
    __syncthreads();

    #pragma unroll 1
    for (int rr = 0; rr < 8; rr++) {
        int row = warp*8 + rr;
        int token = row0 + row;
        const float* hp = &g_h[(size_t)token*Dd];
        float x[8], s = 0.f;
        #pragma unroll
        for (int j = 0; j < 8; j++) {
            x[j] = hp[lane*8 + j] + sv[row*LNSS + lane*8 + j];
            s += x[j];
        }
        #pragma unroll
        for (int o = 16; o; o >>= 1) s += __shfl_xor_sync(~0u, s, o);
        float mean = s * (1.f/256.f);
        float v = 0.f;
        #pragma unroll
        for (int j = 0; j < 8; j++) { float d = x[j] - mean; v += d*d; }
        #pragma unroll
        for (int o = 16; o; o >>= 1) v += __shfl_xor_sync(~0u, v, o);
        float rstd = rsqrtf(v * (1.f/256.f) + EPSLN);
        float* op = &g_h[(size_t)token*Dd];
        #pragma unroll
        for (int j = 0; j < 8; j++) {
            int cix = lane*8 + j;
            float y = (x[j] - mean)*rstd*gam[cix] + bet[cix];
            op[cix] = y;
            size_t ix = (size_t)token*Dd + cix;
            fsplit_h(y, g_hh[ix], g_hl[ix]);
        }
    }
}

// ---------------------------------------------------------------------------
// Attention (fp16): 128-query tile, 256 threads (8 warps x 16 rows).
// Single-term fp16 MMA (Q pre-scaled by SCALE*log2e in QKV GEMM).
// Pass A: row sums (4-buffer K ring, 2 chunks/barrier). Pass B: QK (SW
// pipelined), P out (.cs), PV. smem 40KB -> 3 CTAs/SM.
// Zfilled padding keys -> score exactly 0 -> exp exactly 1 -> subtract 32.
// ---------------------------------------------------------------------------
#define QT 128
#define KT 128
#define NCH 16
#define NPAD 32.0f

#define BUFB 10240                 // bytes per 128x40-half buffer
#define SM_ATTN_BYTES (4*BUFB)     // 40960

__device__ __forceinline__ void stage1(uint32_t sm_u, int bufoff, int ch,
        const __half* P, size_t base, int tid) {
    const int k0 = ch * KT;
    #pragma unroll
    for (int it = 0; it < 2; it++) {
        int o = tid + it*256;
        int r = o >> 2;
        int c = (o & 3) * 8;
        int s = k0 + r;
        bool ok = s < Ld;
        const __half* src = P + base + (size_t)(ok ? s : 0)*128 + c;
        uint32_t dst = sm_u + bufoff + (r*40 + c)*2;
        cpa16(dst, src, ok ? 16 : 0);
    }
}

__device__ __forceinline__ void qk_stats_chunk(
        uint32_t kh_u, int laneK,
        const uint32_t aq[2][4],
        float& s0, float& s1) {
    #pragma unroll 2
    for (int gq = 0; gq < 4; gq++) {
        float acc[4][4];
        #pragma unroll
        for (int i = 0; i < 4; i++)
            #pragma unroll
            for (int j = 0; j < 4; j++) acc[i][j] = 0.f;
        #pragma unroll
        for (int pair = 0; pair < 2; pair++) {
            int be = (gq*32 + pair*16)*40;
            #pragma unroll
            for (int kk = 0; kk < 2; kk++) {
                uint32_t b0, b1, b2, b3;
                uint32_t off = (be + kk*16 + laneK)*2;
                ldsm4(b0, b1, b2, b3, kh_u + off);
                mma16816h(acc[pair*2  ], aq[kk], b0, b1);
                mma16816h(acc[pair*2+1], aq[kk], b2, b3);
            }
        }
        #pragma unroll
        for (int nt = 0; nt < 4; nt++) {
            s0 += ex2(acc[nt][0]) + ex2(acc[nt][1]);
            s1 += ex2(acc[nt][2]) + ex2(acc[nt][3]);
        }
    }
}

__device__ __forceinline__ void qk_group(
        uint32_t kh_u, int laneK, int kbe,
        const uint32_t aq[2][4], float acc[2][4]) {
    #pragma unroll
    for (int i = 0; i < 2; i++)
        #pragma unroll
        for (int j = 0; j < 4; j++) acc[i][j] = 0.f;
    #pragma unroll
    for (int kk = 0; kk < 2; kk++) {
        uint32_t b0, b1, b2, b3;
        uint32_t off = (kbe + kk*16 + laneK)*2;
        ldsm4(b0, b1, b2, b3, kh_u + off);
        mma16816h(acc[0], aq[kk], b0, b1);
        mma16816h(acc[1], aq[kk], b2, b3);
    }
}

template<bool MASK>
__device__ __forceinline__ void emit_group(
        uint32_t vh_u, int laneV, int g, int k0, int fc,
        float inv0, float inv1,
        float* prow0, float* prow1, bool wr0, bool wr1,
        const float acc[2][4], float oacc[4][4]) {
    int kbe = g*16*40;
    int colb = k0 + g*16 + fc;
    bool ok0 = !MASK || (colb < Ld);
    bool ok1 = !MASK || (colb + 8 < Ld);
    float p00 = ok0 ? ex2(acc[0][0])*inv0 : 0.f;
    float p01 = ok0 ? ex2(acc[0][1])*inv0 : 0.f;
    float p02 = ok0 ? ex2(acc[0][2])*inv1 : 0.f;
    float p03 = ok0 ? ex2(acc[0][3])*inv1 : 0.f;
    float p10 = ok1 ? ex2(acc[1][0])*inv0 : 0.f;
    float p11 = ok1 ? ex2(acc[1][1])*inv0 : 0.f;
    float p12 = ok1 ? ex2(acc[1][2])*inv1 : 0.f;
    float p13 = ok1 ? ex2(acc[1][3])*inv1 : 0.f;

    if (wr0) {
        if (ok0) stcs2(&prow0[colb],     p00, p01);
        if (ok1) stcs2(&prow0[colb + 8], p10, p11);
    }
    if (wr1) {
        if (ok0) stcs2(&prow1[colb],     p02, p03);
        if (ok1) stcs2(&prow1[colb + 8], p12, p13);
    }

    uint32_t ah[4];
    ah[0] = pk2h(p00, p01);
    ah[1] = pk2h(p02, p03);
    ah[2] = pk2h(p10, p11);
    ah[3] = pk2h(p12, p13);

    #pragma unroll
    for (int dp = 0; dp < 2; dp++) {
        uint32_t v0, v1, v2, v3;
        uint32_t off = (kbe + dp*16 + laneV)*2;
        ldsm4t(v0, v1, v2, v3, vh_u + off);
        mma16816h(oacc[dp*2  ], ah, v0, v1);
        mma16816h(oacc[dp*2+1], ah, v2, v3);
    }
}

template<bool MASK>
__device__ __forceinline__ void qk_emit_chunk(
        uint32_t kh_u, uint32_t vh_u, int laneK, int laneV,
        const uint32_t aq[2][4],
        int k0, int fc, float inv0, float inv1,
        float* prow0, float* prow1, bool wr0, bool wr1,
        float oacc[4][4]) {
    float aA[2][4], aB[2][4];
    qk_group(kh_u, laneK, 0, aq, aA);
    #pragma unroll
    for (int g = 0; g < 8; g += 2) {
        qk_group(kh_u, laneK, (g+1)*640, aq, aB);
        emit_group<MASK>(vh_u, laneV, g, k0, fc, inv0, inv1,
                         prow0, prow1, wr0, wr1, aA, oacc);
        if (g + 2 < 8)
            qk_group(kh_u, laneK, (g+2)*640, aq, aA);
        emit_group<MASK>(vh_u, laneV, g+1, k0, fc, inv0, inv1,
                         prow0, prow1, wr0, wr1, aB, oacc);
    }
}

__global__ __launch_bounds__(256, 3) void attn_kernel(
        const __half* __restrict__ qkv,
        float* __restrict__ Pout,
        __half* __restrict__ Oh, __half* __restrict__ Ol) {
    extern __shared__ __half smh[];
    uint32_t sm_u = (uint32_t)__cvta_generic_to_shared(smh);

    const int tid = threadIdx.x, lane = tid & 31, warp = tid >> 5;
    const int bh = blockIdx.y;
    const int b  = bh >> 2, h = bh & 3;
    const int q0 = blockIdx.x * QT;
    const size_t base = ((size_t)b*Ld*Hd + h)*DKd;
    const __half* Q = qkv;
    const __half* K = qkv + (size_t)BLd*128;
    const __half* V = qkv + (size_t)2*BLd*128;

    const int mrow = warp * 16;
    const int fr = lane >> 2, fc = (lane & 3) * 2;
    const int lr = lane & 7, sel = lane >> 3;
    const int laneK = ((sel>>1)*8 + lr)*40 + (sel&1)*8;
    const int laneV = ((sel&1)*8 + lr)*40 + (sel>>1)*8;

    const int r0g = q0 + mrow + fr, r1g = r0g + 8;
    const bool q0ok = (r0g < Ld), q1ok = (r1g < Ld);
    uint32_t aq[2][4];
    #pragma unroll
    for (int kk = 0; kk < 2; kk++) {
        int c = kk*16 + fc;
        size_t g0 = base + (size_t)r0g*128 + c;
        size_t g1 = base + (size_t)r1g*128 + c;
        aq[kk][0] = q0ok ? *(const uint32_t*)&Q[g0]     : 0;
        aq[kk][1] = q1ok ? *(const uint32_t*)&Q[g1]     : 0;
        aq[kk][2] = q0ok ? *(const uint32_t*)&Q[g0 + 8] : 0;
        aq[kk][3] = q1ok ? *(const uint32_t*)&Q[g1 + 8] : 0;
    }

    float s0 = 0.f, s1 = 0.f;

    // ======== PASS A: row sums (K only, 4-buffer ring, 2 chunks/sync) ====
    stage1(sm_u, 0*BUFB, 0, K, base, tid);
    stage1(sm_u, 1*BUFB, 1, K, base, tid); cpa_commit();
    stage1(sm_u, 2*BUFB, 2, K, base, tid);
    stage1(sm_u, 3*BUFB, 3, K, base, tid); cpa_commit();
    #pragma unroll 1
    for (int it = 0; it < 8; it++) {
        if (it < 7) cpa_wait<1>(); else cpa_wait<0>();
        __syncthreads();
        int b0 = (it & 1) ? 2 : 0;
        qk_stats_chunk(sm_u + b0*BUFB,     laneK, aq, s0, s1);
        qk_stats_chunk(sm_u + (b0+1)*BUFB, laneK, aq, s0, s1);
        __syncthreads();
        if (it < 6) {
            stage1(sm_u, b0*BUFB,     2*it+4, K, base, tid);
            stage1(sm_u, (b0+1)*BUFB, 2*it+5, K, base, tid);
            cpa_commit();
        }
    }

    // prologue for pass B overlaps the reduction: K in bufs 0/1, V in 2/3
    stage1(sm_u, 0*BUFB, 0, K, base, tid);
    stage1(sm_u, 2*BUFB, 0, V, base, tid); cpa_commit();
    stage1(sm_u, 1*BUFB, 1, K, base, tid);
    stage1(sm_u, 3*BUFB, 1, V, base, tid); cpa_commit();

    s0 += __shfl_xor_sync(~0u, s0, 1);
    s0 += __shfl_xor_sync(~0u, s0, 2);
    s1 += __shfl_xor_sync(~0u, s1, 1);
    s1 += __shfl_xor_sync(~0u, s1, 2);
    s0 -= NPAD;
    s1 -= NPAD;
    const float inv0 = 1.f / s0, inv1 = 1.f / s1;

    // ======== PASS B: P out + PV ========
    float oacc[4][4];
    #pragma unroll
    for (int i = 0; i < 4; i++)
        #pragma unroll
        for (int j = 0; j < 4; j++) oacc[i][j] = 0.f;

    float* prow0 = &Pout[((size_t)bh*Ld + r0g)*Ld];
    float* prow1 = prow0 + 8*(size_t)Ld;

    #pragma unroll 1
    for (int ch = 0; ch < NCH; ch++) {
        if (ch < NCH-1) cpa_wait<1>(); else cpa_wait<0>();
        __syncthreads();
        int buf = ch & 1;
        uint32_t kh_u = sm_u + buf*BUFB;
        uint32_t vh_u = sm_u + (2 + buf)*BUFB;
        if (ch < NCH-1)
            qk_emit_chunk<false>(kh_u, vh_u, laneK, laneV, aq,
                                 ch*KT, fc, inv0, inv1, prow0, prow1, q0ok, q1ok, oacc);
        else
            qk_emit_chunk<true >(kh_u, vh_u, laneK, laneV, aq,
                                 ch*KT, fc, inv0, inv1, prow0, prow1, q0ok, q1ok, oacc);
        __syncthreads();
        if (ch + 2 < NCH) {
            stage1(sm_u, buf*BUFB,       ch+2, K, base, tid);
            stage1(sm_u, (2 + buf)*BUFB, ch+2, V, base, tid);
            cpa_commit();
        }
    }

    // ---- write O (split fp16) ----
    #pragma unroll
    for (int dt = 0; dt < 4; dt++) {
        int d = dt*8 + fc;
        if (q0ok) {
            size_t g = base + (size_t)r0g*128 + d;
            __half hh, ll;
            fsplit_h(oacc[dt][0], hh, ll); Oh[g]   = hh; Ol[g]   = ll;
            fsplit_h(oacc[dt][1], hh, ll); Oh[g+1] = hh; Ol[g+1] = ll;
        }
        if (q1ok) {
            size_t g = base + (size_t)r1g*128 + d;
            __half hh, ll;
            fsplit_h(oacc[dt][2], hh, ll); Oh[g]   = hh; Ol[g]   = ll;
            fsplit_h(oacc[dt][3], hh, ll); Oh[g+1] = hh; Ol[g+1] = ll;
        }
    }
}

// ---------------------------------------------------------------------------
// Final head tail: out = relu_h(g_tmp fp32) @ o2w + o2b   (warp per token)
// ---------------------------------------------------------------------------
__global__ __launch_bounds__(256) void head2_kernel(const float* __restrict__ o2w,
                                                    const float* __restrict__ o2b,
                                                    float* __restrict__ out) {
    int warp = threadIdx.x >> 5, lane = threadIdx.x & 31;
    int token = blockIdx.x * 8 + warp;
    const float* hp = &g_tmp[(size_t)token*Dd];
    float a0 = 0.f, a1 = 0.f;
    #pragma unroll
    for (int j = 0; j < 8; j++) {
        int k = lane + j*32;
        float hv = hp[k];
        a0 = fmaf(hv, o2w[k*2],   a0);
        a1 = fmaf(hv, o2w[k*2+1], a1);
    }
    #pragma unroll
    for (int o = 16; o; o >>= 1) {
        a0 += __shfl_xor_sync(~0u, a0, o);
        a1 += __shfl_xor_sync(~0u, a1, o);
    }
    if (lane == 0) {
        out[(size_t)token*2]     = a0 + o2b[0];
        out[(size_t)token*2 + 1] = a1 + o2b[1];
    }
}

// ---------------------------------------------------------------------------
// Host orchestration
// ---------------------------------------------------------------------------
static inline void* symaddr(const void* s) {
    void* p = nullptr;
    cudaGetSymbolAddress(&p, s);
    return p;
}

extern "C" void kernel_launch(void* const* d_in, const int* in_sizes, int n_in,
                              void* d_out, int out_size) {
    const float* x    = (const float*)d_in[0];
    const float* in_w = (const float*)d_in[1];
    const float* in_b = (const float*)d_in[2];
    const float* qw   = (const float*)d_in[3];
    const float* qb   = (const float*)d_in[4];
    const float* kw   = (const float*)d_in[5];
    const float* kb   = (const float*)d_in[6];
    const float* vw   = (const float*)d_in[7];
    const float* vb   = (const float*)d_in[8];
    const float* ow   = (const float*)d_in[9];
    const float* ob   = (const float*)d_in[10];
    const float* f1w  = (const float*)d_in[11];
    const float* f1b  = (const float*)d_in[12];
    const float* f2w  = (const float*)d_in[13];
    const float* f2b  = (const float*)d_in[14];
    const float* n1g  = (const float*)d_in[15];
    const float* n1b  = (const float*)d_in[16];
    const float* n2g  = (const float*)d_in[17];
    const float* n2b  = (const float*)d_in[18];
    const float* o1w  = (const float*)d_in[19];
    const float* o1b  = (const float*)d_in[20];
    const float* o2w  = (const float*)d_in[21];
    const float* o2b  = (const float*)d_in[22];

    float* outp     = (float*)d_out;
    float* attn_out = outp + (size_t)Bd*Ld*2;

    __half* p_hh   = (__half*)symaddr(g_hh);
    __half* p_hl   = (__half*)symaddr(g_hl);
    __half* p_qkv  = (__half*)symaddr(g_qkv);
    __half* p_oh   = (__half*)symaddr(g_oh);
    __half* p_ol   = (__half*)symaddr(g_ol);
    __half* p_fh   = (__half*)symaddr(g_fh);
    __half* p_fl   = (__half*)symaddr(g_fl);
    float*  p_tmp  = (float*)symaddr(g_tmp);
    __half* p_ow   = (__half*)symaddr(g_ow);
    __half* p_f1w  = (__half*)symaddr(g_f1w);
    __half* p_f2w  = (__half*)symaddr(g_f2w);
    __half* p_o1w  = (__half*)symaddr(g_o1w);

    const int SM_G256  = (2*128*(256+8) + 64*(256+8))*2;      // 168960
    const int SM_LN128 = (2*128*(128+8) + 256*(128+8))*2;     // 139264
    const int SM_LN64_OP = (2*128*(64+8) + 256*(64+8))*2;     // 73728
    const int SM_LNSLAB  = 128*LNSS*4;                        // 133120
    const int SM_LN64  = SM_LN64_OP > SM_LNSLAB ? SM_LN64_OP : SM_LNSLAB;
    const int SM_LN128F = SM_LN128 > SM_LNSLAB ? SM_LN128 : SM_LNSLAB;

    cudaFuncSetAttribute(gemm_qkv, cudaFuncAttributeMaxDynamicSharedMemorySize, SM_G256);
    cudaFuncSetAttribute(gemm_bias<256,1,true >, cudaFuncAttributeMaxDynamicSharedMemorySize, SM_G256);
    cudaFuncSetAttribute(gemm_bias<256,0,true >, cudaFuncAttributeMaxDynamicSharedMemorySize, SM_G256);
    cudaFuncSetAttribute(gemm_ln<128>, cudaFuncAttributeMaxDynamicSharedMemorySize, SM_LN128F);
    cudaFuncSetAttribute(gemm_ln<64 >, cudaFuncAttributeMaxDynamicSharedMemorySize, SM_LN64);
    cudaFuncSetAttribute(attn_kernel, cudaFuncAttributeMaxDynamicSharedMemorySize, SM_ATTN_BYTES);

    convert_w<<<384, 256>>>(qw, kw, vw, ow, f1w, f2w, o1w, qb, kb, vb);
    embed_kernel<<<BLd, Dd>>>(x, in_w, in_b);

    const dim3 gQKV (BLd/128, 6);
    const dim3 gProj(BLd/128, 4);   // N=256 (head only)
    const dim3 gF1  (BLd/128, 1);   // N=64
    const dim3 gLN  (BLd/128);
    const dim3 gAttn((Ld + QT - 1)/QT, Bd*Hd);

    for (int i = 0; i < NLd; i++) {
        gemm_qkv<<<gQKV, 512, SM_G256>>>(i);

        attn_kernel<<<gAttn, 256, SM_ATTN_BYTES>>>(
            p_qkv, attn_out + (size_t)i*Bd*Hd*Ld*Ld, p_oh, p_ol);

        // o-projection + residual + LN1 (fused)
        gemm_ln<128><<<gLN, 512, SM_LN128F>>>(
            p_oh, p_ol, p_ow + (size_t)i*128*Dd,
            ob + i*Dd, n1g + i*Dd, n1b + i*Dd);

        // FFN1 (relu, split fp16 out)
        gemm_bias<256,1,true><<<gF1, 512, SM_G256>>>(
            p_hh, p_hl, p_f1w + (size_t)i*Dd*FCd,
            f1b + i*FCd, nullptr, p_fh, p_fl, FCd);

        // FFN2 + residual + LN2 (fused)
        gemm_ln<64><<<gLN, 512, SM_LN64>>>(
            p_fh, p_fl, p_f2w + (size_t)i*FCd*Dd,
            f2b + i*Dd, n2g + i*Dd, n2b + i*Dd);
    }

    gemm_bias<256,0,true><<<gProj, 512, SM_G256>>>(
        p_hh, p_hl, p_o1w, o1b, p_tmp, nullptr, nullptr, Dd);
    head2_kernel<<<BLd/8, 256>>>(o2w, o2b, outp);
}